// round 5
// baseline (speedup 1.0000x reference)
#include <cuda_runtime.h>
#include <cuda_bf16.h>
#include <math.h>
#include <stdint.h>

// Problem constants
#define BSZ   32
#define TD    64
#define TEC   128
#define EDIM  256
#define HDIM  512
#define G4    2048
#define VOC   32000
#define M_BT  2048
#define KEXT  1536          // 3x512 split-bf16 extended K

// HMMA fc-GEMM tiling
#define BM    256
#define BN    128
#define BK    64
#define KI    (KEXT / BK)   // 24
#define ROWB  144
#define SA_BYTES (BM * ROWB)
#define SB_BYTES (BN * ROWB)
#define STAGE    (SA_BYTES + SB_BYTES)
#define NSTAGE   3
#define SM_TOTAL (NSTAGE * STAGE)

// Persistent LSTM kernel
#define LCTA  128
#define HSTR  516           // padded h row stride (words) — debanks smem reads
#define LSTM_SMEM ((16 * 512 + 32 * HSTR + 16 * 33) * 4)

// Scratch
__device__ float g_bias[G4];
__device__ float g_emb [M_BT * EDIM];
__device__ float g_xih [TD * BSZ * G4];
__device__ float g_hs  [TD * BSZ * HDIM];
__device__ float g_c   [BSZ * HDIM];
__device__ float g_cat [M_BT * 2 * HDIM];
__device__ float g_aout[M_BT * HDIM];
__device__ unsigned g_bar;
__device__ __align__(16) __nv_bfloat16 g_Aext[(size_t)M_BT * KEXT]; // [hi|hi|lo]
__device__ __align__(16) __nv_bfloat16 g_Bext[(size_t)VOC * KEXT];  // [hi|lo|hi]

__device__ __forceinline__ float sigf(float x) { return 1.0f / (1.0f + expf(-x)); }

__device__ __forceinline__ uint32_t smem_u32(const void* p) {
    uint32_t a;
    asm("{ .reg .u64 t; cvta.to.shared.u64 t, %1; cvt.u32.u64 %0, t; }" : "=r"(a) : "l"(p));
    return a;
}

// ---------------------------------------------------------------------------
__global__ void k_bias(const float* __restrict__ bih, const float* __restrict__ bhh) {
    int i = blockIdx.x * 256 + threadIdx.x;
    if (i < G4) g_bias[i] = bih[i] + bhh[i];
    if (i == 0) g_bar = 0u;             // reset persistent-kernel barrier each launch
}

__global__ void k_embed(const int* __restrict__ decX, const float* __restrict__ embW) {
    int m = blockIdx.x;
    int e = threadIdx.x;
    int b = m & (BSZ - 1);
    int t = m >> 5;
    int tok = decX[b * TD + t];
    g_emb[m * EDIM + e] = embW[tok * EDIM + e];
}

// Generic fp32 GEMM (xih / attn): C = act(A[M,K]*B[N,K]^T + bias)
__global__ __launch_bounds__(256, 2)
void k_sgemm(const float* __restrict__ A, const float* __restrict__ Bm,
             const float* __restrict__ bias, float* __restrict__ C,
             int M, int N, int K, int act) {
    __shared__ float As[8][132];
    __shared__ float Bs[8][132];
    int tid = threadIdx.x;
    int m0 = blockIdx.y * 128, n0 = blockIdx.x * 128;
    int lr = tid >> 1;
    int lc = (tid & 1) * 4;
    const float* Ap = A + (size_t)(m0 + lr) * K + lc;
    const float* Bp = Bm + (size_t)(n0 + lr) * K + lc;
    int tx = tid & 15, ty = tid >> 4;
    float acc[8][8] = {};
    for (int kt = 0; kt < K; kt += 8) {
        float4 av = *(const float4*)(Ap + kt);
        float4 bv = *(const float4*)(Bp + kt);
        As[lc + 0][lr] = av.x; As[lc + 1][lr] = av.y;
        As[lc + 2][lr] = av.z; As[lc + 3][lr] = av.w;
        Bs[lc + 0][lr] = bv.x; Bs[lc + 1][lr] = bv.y;
        Bs[lc + 2][lr] = bv.z; Bs[lc + 3][lr] = bv.w;
        __syncthreads();
#pragma unroll
        for (int k = 0; k < 8; k++) {
            float a[8], bb[8];
#pragma unroll
            for (int i = 0; i < 8; i++) a[i] = As[k][ty * 8 + i];
#pragma unroll
            for (int j = 0; j < 8; j++) bb[j] = Bs[k][tx * 8 + j];
#pragma unroll
            for (int i = 0; i < 8; i++)
#pragma unroll
                for (int j = 0; j < 8; j++) acc[i][j] += a[i] * bb[j];
        }
        __syncthreads();
    }
#pragma unroll
    for (int i = 0; i < 8; i++) {
        int m = m0 + ty * 8 + i;
#pragma unroll
        for (int j = 0; j < 8; j++) {
            int n = n0 + tx * 8 + j;
            float v = acc[i][j] + bias[n];
            if (act) v = tanhf(v);
            C[(size_t)m * N + n] = v;
        }
    }
}

// ---------------------------------------------------------------------------
// Persistent fused LSTM: one kernel for all 64 timesteps.
// 128 CTAs (all co-resident). CTA i owns hidden units [i*4, i*4+4) — all 4
// gates, all 32 batches. Its 16 W_hh rows stay in SMEM for the whole run;
// cell state stays in registers. One software global barrier per step.
__global__ __launch_bounds__(256, 1)
void k_lstm(const float* __restrict__ h0, const float* __restrict__ c0,
            const float* __restrict__ Whh) {
    extern __shared__ float sm[];
    float* wS = sm;                       // 16 x 512
    float* hS = sm + 16 * 512;            // 32 x HSTR
    float* gS = hS + 32 * HSTR;           // 16 x 33
    int tid = threadIdx.x, cta = blockIdx.x;
    int hu0 = cta * 4;

    // Load this CTA's 16 W_hh rows once: local row (gate*4+q) <- global row gate*512+hu0+q
#pragma unroll
    for (int r = 0; r < 16; r++) {
        int gt = r >> 2, q = r & 3;
        const float* src = Whh + (size_t)(gt * HDIM + hu0 + q) * HDIM;
        for (int k = tid; k < HDIM; k += 256) wS[r * HDIM + k] = src[k];
    }

    // Cell state in registers (threads 0..127: b = tid>>2, q = tid&3)
    float creg = 0.0f;
    if (tid < 128) creg = c0[(tid >> 2) * HDIM + hu0 + (tid & 3)];

    int j  = tid >> 4;                    // local gate-row 0..15
    int bp = tid & 15;
    int gate = j >> 2, q = j & 3;
    int jg = gate * HDIM + hu0 + q;       // global gate index for x_ih

    for (int t = 0; t < TD; t++) {
        const float* hp = (t == 0) ? h0 : (g_hs + (size_t)(t - 1) * BSZ * HDIM);
        __syncthreads();
        // Stage h_prev into smem (padded rows)
        for (int i4 = tid; i4 < 4096; i4 += 256) {
            int b = i4 >> 7, kk = (i4 & 127) << 2;
            float4 v = *(const float4*)(hp + b * HDIM + kk);
            *(float4*)(hS + b * HSTR + kk) = v;
        }
        __syncthreads();

        // Two dot products per thread: (j, bp) and (j, bp+16)
        float a0 = 0.0f, a1 = 0.0f;
        const float* wrow = wS + j * HDIM;
#pragma unroll 8
        for (int k = 0; k < HDIM; k += 4) {
            float4 wv = *(const float4*)(wrow + k);
            float4 hA = *(const float4*)(hS + bp * HSTR + k);
            float4 hB = *(const float4*)(hS + (bp + 16) * HSTR + k);
            a0 += wv.x * hA.x + wv.y * hA.y + wv.z * hA.z + wv.w * hA.w;
            a1 += wv.x * hB.x + wv.y * hB.y + wv.z * hB.z + wv.w * hB.w;
        }
        a0 += g_xih[((size_t)t * BSZ + bp) * G4 + jg];
        a1 += g_xih[((size_t)t * BSZ + bp + 16) * G4 + jg];
        gS[j * 33 + bp]      = a0;
        gS[j * 33 + bp + 16] = a1;
        __syncthreads();

        // Pointwise update (threads 0..127)
        if (tid < 128) {
            int b = tid >> 2, qq = tid & 3;
            float gi = gS[(0  + qq) * 33 + b];
            float gf = gS[(4  + qq) * 33 + b];
            float gg = gS[(8  + qq) * 33 + b];
            float go = gS[(12 + qq) * 33 + b];
            float c = sigf(gf) * creg + sigf(gi) * tanhf(gg);
            creg = c;
            float hh = sigf(go) * tanhf(c);
            g_hs[((size_t)t * BSZ + b) * HDIM + hu0 + qq] = hh;
        }

        // Global barrier (monotonic counter; g_bar reset by k_bias)
        __threadfence();
        __syncthreads();
        if (tid == 0) {
            atomicAdd(&g_bar, 1u);
            unsigned target = (unsigned)(t + 1) * LCTA;
            volatile unsigned* vb = &g_bar;
            while (*vb < target) { __nanosleep(64); }
        }
        __syncthreads();
    }
    if (tid < 128) g_c[(tid >> 2) * HDIM + hu0 + (tid & 3)] = creg;
}

// ---------------------------------------------------------------------------
__global__ void k_attn(const float* __restrict__ enc) {
    __shared__ float hS[8][HDIM];
    __shared__ float sS[8][TEC];
    int bi = blockIdx.x;
    int b = bi >> 3;
    int t0 = (bi & 7) * 8;
    int tid = threadIdx.x;
    int w = tid >> 5, lane = tid & 31;
#pragma unroll
    for (int r = 0; r < 16; r++) {
        int li = r * 256 + tid;
        int tt = li >> 9, k = li & 511;
        hS[tt][k] = g_hs[(size_t)((t0 + tt) * BSZ + b) * HDIM + k];
    }
    __syncthreads();
    for (int te = w; te < TEC; te += 8) {
        const float* ep = enc + (size_t)(b * TEC + te) * HDIM;
        float a8[8] = {};
        for (int k = lane; k < HDIM; k += 32) {
            float e = ep[k];
#pragma unroll
            for (int tt = 0; tt < 8; tt++) a8[tt] += e * hS[tt][k];
        }
#pragma unroll
        for (int tt = 0; tt < 8; tt++) {
            float v = a8[tt];
#pragma unroll
            for (int off = 16; off; off >>= 1) v += __shfl_xor_sync(0xffffffffu, v, off);
            if (lane == 0) sS[tt][te] = v;
        }
    }
    __syncthreads();
    {
        int row = w;
        float sv[4], mx = -1e30f;
#pragma unroll
        for (int q = 0; q < 4; q++) { sv[q] = sS[row][lane + 32 * q]; mx = fmaxf(mx, sv[q]); }
#pragma unroll
        for (int off = 16; off; off >>= 1) mx = fmaxf(mx, __shfl_xor_sync(0xffffffffu, mx, off));
        float sum = 0.0f;
#pragma unroll
        for (int q = 0; q < 4; q++) { sv[q] = expf(sv[q] - mx); sum += sv[q]; }
#pragma unroll
        for (int off = 16; off; off >>= 1) sum += __shfl_xor_sync(0xffffffffu, sum, off);
        float inv = 1.0f / sum;
#pragma unroll
        for (int q = 0; q < 4; q++) sS[row][lane + 32 * q] = sv[q] * inv;
    }
    __syncthreads();
    for (int jj = tid; jj < HDIM; jj += 256) {
        float a8[8] = {};
        for (int te = 0; te < TEC; te++) {
            float e = enc[(size_t)(b * TEC + te) * HDIM + jj];
#pragma unroll
            for (int tt = 0; tt < 8; tt++) a8[tt] += sS[tt][te] * e;
        }
#pragma unroll
        for (int tt = 0; tt < 8; tt++) {
            int m = b * TD + t0 + tt;
            g_cat[(size_t)m * (2 * HDIM) + jj] = hS[tt][jj];
            g_cat[(size_t)m * (2 * HDIM) + HDIM + jj] = a8[tt];
        }
    }
}

__global__ void k_tail(float* __restrict__ out) {
    int i = blockIdx.x * 256 + threadIdx.x;
    if (i < BSZ * HDIM) {
        out[(size_t)M_BT * VOC + i] = g_hs[(size_t)(TD - 1) * BSZ * HDIM + i];
        out[(size_t)M_BT * VOC + BSZ * HDIM + i] = g_c[i];
    }
}

// ---------------------------------------------------------------------------
// Split-bf16 conversions
__global__ void k_cvt_a() {
    size_t i = ((size_t)blockIdx.x * 256 + threadIdx.x) * 4;
    if (i >= (size_t)M_BT * HDIM) return;
    size_t m = i >> 9, k = i & 511;
    float4 x = *(const float4*)(g_aout + i);
    __nv_bfloat16 hi[4], lo[4];
    float xs[4] = {x.x, x.y, x.z, x.w};
#pragma unroll
    for (int q = 0; q < 4; q++) {
        hi[q] = __float2bfloat16(xs[q]);
        lo[q] = __float2bfloat16(xs[q] - __bfloat162float(hi[q]));
    }
    __nv_bfloat16* base = g_Aext + m * KEXT + k;
    *(uint2*)(base)        = *(uint2*)hi;
    *(uint2*)(base + 512)  = *(uint2*)hi;
    *(uint2*)(base + 1024) = *(uint2*)lo;
}

__global__ void k_cvt_b(const float* __restrict__ W) {
    size_t i = ((size_t)blockIdx.x * 256 + threadIdx.x) * 4;
    if (i >= (size_t)VOC * HDIM) return;
    size_t n = i >> 9, k = i & 511;
    float4 x = *(const float4*)(W + i);
    __nv_bfloat16 hi[4], lo[4];
    float xs[4] = {x.x, x.y, x.z, x.w};
#pragma unroll
    for (int q = 0; q < 4; q++) {
        hi[q] = __float2bfloat16(xs[q]);
        lo[q] = __float2bfloat16(xs[q] - __bfloat162float(hi[q]));
    }
    __nv_bfloat16* base = g_Bext + n * KEXT + k;
    *(uint2*)(base)        = *(uint2*)hi;
    *(uint2*)(base + 512)  = *(uint2*)lo;
    *(uint2*)(base + 1024) = *(uint2*)hi;
}

// ---------------------------------------------------------------------------
// HMMA fc GEMM: C[2048,32000] = Aext @ Bext^T + fcb (mma.sync m16n8k16 bf16)
__global__ __launch_bounds__(256, 1)
void k_hgemm(const float* __restrict__ fcb, float* __restrict__ C) {
    extern __shared__ char smem[];
    uint32_t sb = smem_u32(smem);
    int tid = threadIdx.x;
    int wid = tid >> 5, lane = tid & 31;
    int wm = wid & 3, wn = wid >> 2;
    int m0 = blockIdx.x * BM, n0 = blockIdx.y * BN;

    const __nv_bfloat16* gA0 = g_Aext + (size_t)m0 * KEXT;
    const __nv_bfloat16* gB0 = g_Bext + (size_t)n0 * KEXT;

    auto load_stage = [&](int kt, int s) {
        uint32_t sa = sb + s * STAGE;
        const __nv_bfloat16* gA = gA0 + kt * BK;
#pragma unroll
        for (int r8 = 0; r8 < 8; r8++) {
            int li = r8 * 256 + tid;
            int row = li >> 3, seg = li & 7;
            uint32_t dst = sa + row * ROWB + seg * 16;
            const void* src = gA + (size_t)row * KEXT + seg * 8;
            asm volatile("cp.async.cg.shared.global [%0], [%1], 16;" :: "r"(dst), "l"(src));
        }
        uint32_t sbB = sa + SA_BYTES;
        const __nv_bfloat16* gB = gB0 + kt * BK;
#pragma unroll
        for (int r4 = 0; r4 < 4; r4++) {
            int li = r4 * 256 + tid;
            int row = li >> 3, seg = li & 7;
            uint32_t dst = sbB + row * ROWB + seg * 16;
            const void* src = gB + (size_t)row * KEXT + seg * 8;
            asm volatile("cp.async.cg.shared.global [%0], [%1], 16;" :: "r"(dst), "l"(src));
        }
        asm volatile("cp.async.commit_group;" ::: "memory");
    };

    float acc[4][8][4];
#pragma unroll
    for (int i = 0; i < 4; i++)
#pragma unroll
        for (int j = 0; j < 8; j++)
#pragma unroll
            for (int q = 0; q < 4; q++) acc[i][j][q] = 0.0f;

    load_stage(0, 0);
    load_stage(1, 1);

    for (int kt = 0; kt < KI; kt++) {
        asm volatile("cp.async.wait_group 1;" ::: "memory");
        __syncthreads();
        int s = kt % NSTAGE;
        if (kt + 2 < KI) load_stage(kt + 2, (kt + 2) % NSTAGE);

        uint32_t sa = sb + s * STAGE;
        uint32_t sB = sa + SA_BYTES;
#pragma unroll
        for (int kk = 0; kk < 4; kk++) {
            uint32_t a[4][4], b[4][4];
#pragma unroll
            for (int i = 0; i < 4; i++) {
                int row = wm * 64 + i * 16 + (lane & 15);
                int ko = kk * 16 + ((lane >> 4) << 3);
                uint32_t ad = sa + row * ROWB + ko * 2;
                asm volatile("ldmatrix.sync.aligned.m8n8.x4.shared.b16 {%0,%1,%2,%3}, [%4];"
                             : "=r"(a[i][0]), "=r"(a[i][1]), "=r"(a[i][2]), "=r"(a[i][3])
                             : "r"(ad));
            }
#pragma unroll
            for (int j2 = 0; j2 < 4; j2++) {
                int nrow = wn * 64 + j2 * 16 + (lane & 7) + (((lane >> 4) & 1) << 3);
                int ko = kk * 16 + (((lane >> 3) & 1) << 3);
                uint32_t bd = sB + nrow * ROWB + ko * 2;
                asm volatile("ldmatrix.sync.aligned.m8n8.x4.shared.b16 {%0,%1,%2,%3}, [%4];"
                             : "=r"(b[j2][0]), "=r"(b[j2][1]), "=r"(b[j2][2]), "=r"(b[j2][3])
                             : "r"(bd));
            }
#pragma unroll
            for (int i = 0; i < 4; i++)
#pragma unroll
                for (int j2 = 0; j2 < 4; j2++) {
                    asm volatile(
                        "mma.sync.aligned.m16n8k16.row.col.f32.bf16.bf16.f32 "
                        "{%0,%1,%2,%3}, {%4,%5,%6,%7}, {%8,%9}, {%0,%1,%2,%3};"
                        : "+f"(acc[i][2*j2][0]), "+f"(acc[i][2*j2][1]),
                          "+f"(acc[i][2*j2][2]), "+f"(acc[i][2*j2][3])
                        : "r"(a[i][0]), "r"(a[i][1]), "r"(a[i][2]), "r"(a[i][3]),
                          "r"(b[j2][0]), "r"(b[j2][1]));
                    asm volatile(
                        "mma.sync.aligned.m16n8k16.row.col.f32.bf16.bf16.f32 "
                        "{%0,%1,%2,%3}, {%4,%5,%6,%7}, {%8,%9}, {%0,%1,%2,%3};"
                        : "+f"(acc[i][2*j2+1][0]), "+f"(acc[i][2*j2+1][1]),
                          "+f"(acc[i][2*j2+1][2]), "+f"(acc[i][2*j2+1][3])
                        : "r"(a[i][0]), "r"(a[i][1]), "r"(a[i][2]), "r"(a[i][3]),
                          "r"(b[j2][2]), "r"(b[j2][3]));
                }
        }
        __syncthreads();
    }
    asm volatile("cp.async.wait_group 0;" ::: "memory");

#pragma unroll
    for (int j = 0; j < 8; j++) {
        int ncol = n0 + wn * 64 + j * 8 + (lane & 3) * 2;
        float b0 = fcb[ncol], b1 = fcb[ncol + 1];
#pragma unroll
        for (int i = 0; i < 4; i++) {
            int mrow = m0 + wm * 64 + i * 16 + (lane >> 2);
            float2 v0 = {acc[i][j][0] + b0, acc[i][j][1] + b1};
            float2 v1 = {acc[i][j][2] + b0, acc[i][j][3] + b1};
            *(float2*)(C + (size_t)mrow * VOC + ncol) = v0;
            *(float2*)(C + (size_t)(mrow + 8) * VOC + ncol) = v1;
        }
    }
}

// ---------------------------------------------------------------------------
extern "C" void kernel_launch(void* const* d_in, const int* in_sizes, int n_in,
                              void* d_out, int out_size) {
    const int*   decX = (const int*)d_in[0];
    const float* enc  = (const float*)d_in[1];
    const float* h0   = (const float*)d_in[2];
    const float* c0   = (const float*)d_in[3];
    const float* embW = (const float*)d_in[4];
    const float* Wih  = (const float*)d_in[5];
    const float* Whh  = (const float*)d_in[6];
    const float* bih  = (const float*)d_in[7];
    const float* bhh  = (const float*)d_in[8];
    const float* attW = (const float*)d_in[9];
    const float* attb = (const float*)d_in[10];
    const float* fcW  = (const float*)d_in[11];
    const float* fcb  = (const float*)d_in[12];
    float* out = (float*)d_out;

    float *p_emb, *p_xih, *p_cat, *p_aout, *p_bias;
    cudaGetSymbolAddress((void**)&p_emb,  g_emb);
    cudaGetSymbolAddress((void**)&p_xih,  g_xih);
    cudaGetSymbolAddress((void**)&p_cat,  g_cat);
    cudaGetSymbolAddress((void**)&p_aout, g_aout);
    cudaGetSymbolAddress((void**)&p_bias, g_bias);

    cudaFuncSetAttribute(k_hgemm, cudaFuncAttributeMaxDynamicSharedMemorySize, SM_TOTAL);
    cudaFuncSetAttribute(k_lstm,  cudaFuncAttributeMaxDynamicSharedMemorySize, LSTM_SMEM);

    k_cvt_b<<<(VOC * HDIM / 4 + 255) / 256, 256>>>(fcW);

    k_bias<<<8, 256>>>(bih, bhh);          // also resets g_bar
    k_embed<<<M_BT, 256>>>(decX, embW);
    k_sgemm<<<dim3(G4 / 128, M_BT / 128), 256>>>(p_emb, Wih, p_bias, p_xih,
                                                 M_BT, G4, EDIM, 0);
    // Fused persistent LSTM (all 64 steps, one launch)
    k_lstm<<<LCTA, 256, LSTM_SMEM>>>(h0, c0, Whh);

    k_attn<<<256, 256>>>(enc);
    k_sgemm<<<dim3(HDIM / 128, M_BT / 128), 256>>>(p_cat, attW, attb, p_aout,
                                                   M_BT, HDIM, 2 * HDIM, 1);
    k_cvt_a<<<(M_BT * HDIM / 4 + 255) / 256, 256>>>();
    k_hgemm<<<dim3(M_BT / BM, VOC / BN), 256, SM_TOTAL>>>(fcb, out);
    k_tail<<<64, 256>>>(out);
}

// round 6
// speedup vs baseline: 1.4654x; 1.4654x over previous
#include <cuda_runtime.h>
#include <cuda_fp16.h>
#include <math.h>
#include <stdint.h>

// Problem constants
#define BSZ   32
#define TD    64
#define TEC   128
#define EDIM  256
#define HDIM  512
#define G4    2048
#define VOC   32000
#define KCH   8
#define M_BT  2048

// HMMA fc-GEMM tiling (fp16, K = 512, no split)
#define BM    256
#define BN    128
#define BK    64
#define KDIM  512
#define KI    (KDIM / BK)   // 8
#define ROWB  144           // padded SMEM row stride (64*2 + 16)
#define SA_BYTES (BM * ROWB)
#define SB_BYTES (BN * ROWB)
#define STAGE    (SA_BYTES + SB_BYTES)
#define NSTAGE   3
#define SM_TOTAL (NSTAGE * STAGE)

// Scratch
__device__ float g_bias[G4];
__device__ float g_emb [M_BT * EDIM];
__device__ float g_xih [TD * BSZ * G4];
__device__ float g_part[KCH * BSZ * G4];
__device__ float g_hs  [TD * BSZ * HDIM];
__device__ float g_c   [BSZ * HDIM];
__device__ float g_cat [M_BT * 2 * HDIM];
__device__ float g_aout[M_BT * HDIM];
__device__ __align__(16) __half g_Ah[(size_t)M_BT * KDIM];
__device__ __align__(16) __half g_Bh[(size_t)VOC * KDIM];

__device__ __forceinline__ float sigf(float x) { return 1.0f / (1.0f + expf(-x)); }

__device__ __forceinline__ uint32_t smem_u32(const void* p) {
    uint32_t a;
    asm("{ .reg .u64 t; cvta.to.shared.u64 t, %1; cvt.u32.u64 %0, t; }" : "=r"(a) : "l"(p));
    return a;
}

// ---------------------------------------------------------------------------
__global__ void k_bias(const float* __restrict__ bih, const float* __restrict__ bhh) {
    int i = blockIdx.x * 256 + threadIdx.x;
    if (i < G4) g_bias[i] = bih[i] + bhh[i];
}

__global__ void k_embed(const int* __restrict__ decX, const float* __restrict__ embW) {
    int m = blockIdx.x;
    int e = threadIdx.x;
    int b = m & (BSZ - 1);
    int t = m >> 5;
    int tok = decX[b * TD + t];
    g_emb[m * EDIM + e] = embW[tok * EDIM + e];
}

// Generic fp32 GEMM (xih / attn): C = act(A[M,K]*B[N,K]^T + bias)
__global__ __launch_bounds__(256, 2)
void k_sgemm(const float* __restrict__ A, const float* __restrict__ Bm,
             const float* __restrict__ bias, float* __restrict__ C,
             int M, int N, int K, int act) {
    __shared__ float As[8][132];
    __shared__ float Bs[8][132];
    int tid = threadIdx.x;
    int m0 = blockIdx.y * 128, n0 = blockIdx.x * 128;
    int lr = tid >> 1;
    int lc = (tid & 1) * 4;
    const float* Ap = A + (size_t)(m0 + lr) * K + lc;
    const float* Bp = Bm + (size_t)(n0 + lr) * K + lc;
    int tx = tid & 15, ty = tid >> 4;
    float acc[8][8] = {};
    for (int kt = 0; kt < K; kt += 8) {
        float4 av = *(const float4*)(Ap + kt);
        float4 bv = *(const float4*)(Bp + kt);
        As[lc + 0][lr] = av.x; As[lc + 1][lr] = av.y;
        As[lc + 2][lr] = av.z; As[lc + 3][lr] = av.w;
        Bs[lc + 0][lr] = bv.x; Bs[lc + 1][lr] = bv.y;
        Bs[lc + 2][lr] = bv.z; Bs[lc + 3][lr] = bv.w;
        __syncthreads();
#pragma unroll
        for (int k = 0; k < 8; k++) {
            float a[8], bb[8];
#pragma unroll
            for (int i = 0; i < 8; i++) a[i] = As[k][ty * 8 + i];
#pragma unroll
            for (int j = 0; j < 8; j++) bb[j] = Bs[k][tx * 8 + j];
#pragma unroll
            for (int i = 0; i < 8; i++)
#pragma unroll
                for (int j = 0; j < 8; j++) acc[i][j] += a[i] * bb[j];
        }
        __syncthreads();
    }
#pragma unroll
    for (int i = 0; i < 8; i++) {
        int m = m0 + ty * 8 + i;
#pragma unroll
        for (int j = 0; j < 8; j++) {
            int n = n0 + tx * 8 + j;
            float v = acc[i][j] + bias[n];
            if (act) v = tanhf(v);
            C[(size_t)m * N + n] = v;
        }
    }
}

// ---------------------------------------------------------------------------
// Per-step LSTM GEMM, K-split (R4 known-good version)
__global__ void k_ls(int t, const float* __restrict__ h0, const float* __restrict__ Whh) {
    __shared__ float hS[64][33];
    __shared__ float wS[64][129];
    int jt = blockIdx.x, kc = blockIdx.y;
    int tid = threadIdx.x;
    const float* hprev = (t == 0) ? h0 : (g_hs + (size_t)(t - 1) * BSZ * HDIM);
    int k0 = kc * 64;
#pragma unroll
    for (int r = 0; r < 8; r++) {
        int li = r * 256 + tid;
        int b = li >> 6, k = li & 63;
        hS[k][b] = hprev[b * HDIM + k0 + k];
    }
#pragma unroll
    for (int r = 0; r < 32; r++) {
        int li = r * 256 + tid;
        int j = li >> 6, k = li & 63;
        wS[k][j] = Whh[(size_t)(jt * 128 + j) * HDIM + k0 + k];
    }
    __syncthreads();
    int tx = tid & 31, ty = tid >> 5;
    float acc[4][4] = {};
#pragma unroll
    for (int k = 0; k < 64; k++) {
        float hv[4], wv[4];
#pragma unroll
        for (int i = 0; i < 4; i++) hv[i] = hS[k][ty * 4 + i];
#pragma unroll
        for (int j = 0; j < 4; j++) wv[j] = wS[k][tx * 4 + j];
#pragma unroll
        for (int i = 0; i < 4; i++)
#pragma unroll
            for (int j = 0; j < 4; j++) acc[i][j] += hv[i] * wv[j];
    }
#pragma unroll
    for (int i = 0; i < 4; i++)
#pragma unroll
        for (int j = 0; j < 4; j++)
            g_part[(size_t)(kc * BSZ + ty * 4 + i) * G4 + jt * 128 + tx * 4 + j] = acc[i][j];
}

__global__ void k_pw(int t, const float* __restrict__ c0) {
    int i = blockIdx.x * 256 + threadIdx.x;
    int b = i >> 9, h = i & 511;
    size_t base = (size_t)(t * BSZ + b) * G4 + h;
    float gi = g_xih[base];
    float gf = g_xih[base + HDIM];
    float gg = g_xih[base + 2 * HDIM];
    float go = g_xih[base + 3 * HDIM];
#pragma unroll
    for (int kc = 0; kc < KCH; kc++) {
        size_t pb = (size_t)(kc * BSZ + b) * G4 + h;
        gi += g_part[pb];
        gf += g_part[pb + HDIM];
        gg += g_part[pb + 2 * HDIM];
        go += g_part[pb + 3 * HDIM];
    }
    float cp = (t == 0) ? c0[i] : g_c[i];
    float c = sigf(gf) * cp + sigf(gi) * tanhf(gg);
    float hh = sigf(go) * tanhf(c);
    g_c[i] = c;
    g_hs[(size_t)t * BSZ * HDIM + i] = hh;
}

// ---------------------------------------------------------------------------
__global__ void k_attn(const float* __restrict__ enc) {
    __shared__ float hS[8][HDIM];
    __shared__ float sS[8][TEC];
    int bi = blockIdx.x;
    int b = bi >> 3;
    int t0 = (bi & 7) * 8;
    int tid = threadIdx.x;
    int w = tid >> 5, lane = tid & 31;
#pragma unroll
    for (int r = 0; r < 16; r++) {
        int li = r * 256 + tid;
        int tt = li >> 9, k = li & 511;
        hS[tt][k] = g_hs[(size_t)((t0 + tt) * BSZ + b) * HDIM + k];
    }
    __syncthreads();
    for (int te = w; te < TEC; te += 8) {
        const float* ep = enc + (size_t)(b * TEC + te) * HDIM;
        float a8[8] = {};
        for (int k = lane; k < HDIM; k += 32) {
            float e = ep[k];
#pragma unroll
            for (int tt = 0; tt < 8; tt++) a8[tt] += e * hS[tt][k];
        }
#pragma unroll
        for (int tt = 0; tt < 8; tt++) {
            float v = a8[tt];
#pragma unroll
            for (int off = 16; off; off >>= 1) v += __shfl_xor_sync(0xffffffffu, v, off);
            if (lane == 0) sS[tt][te] = v;
        }
    }
    __syncthreads();
    {
        int row = w;
        float sv[4], mx = -1e30f;
#pragma unroll
        for (int q = 0; q < 4; q++) { sv[q] = sS[row][lane + 32 * q]; mx = fmaxf(mx, sv[q]); }
#pragma unroll
        for (int off = 16; off; off >>= 1) mx = fmaxf(mx, __shfl_xor_sync(0xffffffffu, mx, off));
        float sum = 0.0f;
#pragma unroll
        for (int q = 0; q < 4; q++) { sv[q] = expf(sv[q] - mx); sum += sv[q]; }
#pragma unroll
        for (int off = 16; off; off >>= 1) sum += __shfl_xor_sync(0xffffffffu, sum, off);
        float inv = 1.0f / sum;
#pragma unroll
        for (int q = 0; q < 4; q++) sS[row][lane + 32 * q] = sv[q] * inv;
    }
    __syncthreads();
    for (int jj = tid; jj < HDIM; jj += 256) {
        float a8[8] = {};
        for (int te = 0; te < TEC; te++) {
            float e = enc[(size_t)(b * TEC + te) * HDIM + jj];
#pragma unroll
            for (int tt = 0; tt < 8; tt++) a8[tt] += sS[tt][te] * e;
        }
#pragma unroll
        for (int tt = 0; tt < 8; tt++) {
            int m = b * TD + t0 + tt;
            g_cat[(size_t)m * (2 * HDIM) + jj] = hS[tt][jj];
            g_cat[(size_t)m * (2 * HDIM) + HDIM + jj] = a8[tt];
        }
    }
}

__global__ void k_tail(float* __restrict__ out) {
    int i = blockIdx.x * 256 + threadIdx.x;
    if (i < BSZ * HDIM) {
        out[(size_t)M_BT * VOC + i] = g_hs[(size_t)(TD - 1) * BSZ * HDIM + i];
        out[(size_t)M_BT * VOC + BSZ * HDIM + i] = g_c[i];
    }
}

// ---------------------------------------------------------------------------
// fp16 conversions (no split — fp16 rounding 2^-11 keeps rel_err ~4e-4)
__global__ void k_cvt_a() {   // g_aout [2048x512] -> fp16
    size_t i = ((size_t)blockIdx.x * 256 + threadIdx.x) * 4;
    if (i >= (size_t)M_BT * HDIM) return;
    float4 x = *(const float4*)(g_aout + i);
    __half h[4] = {__float2half(x.x), __float2half(x.y),
                   __float2half(x.z), __float2half(x.w)};
    *(uint2*)(g_Ah + i) = *(uint2*)h;
}

__global__ void k_cvt_b(const float* __restrict__ W) {  // fcW [32000x512] -> fp16
    size_t i = ((size_t)blockIdx.x * 256 + threadIdx.x) * 4;
    if (i >= (size_t)VOC * HDIM) return;
    float4 x = *(const float4*)(W + i);
    __half h[4] = {__float2half(x.x), __float2half(x.y),
                   __float2half(x.z), __float2half(x.w)};
    *(uint2*)(g_Bh + i) = *(uint2*)h;
}

// ---------------------------------------------------------------------------
// HMMA fc GEMM: C[2048,32000] = Ah @ Bh^T + fcb (mma.sync m16n8k16 fp16, fp32 acc)
__global__ __launch_bounds__(256, 1)
void k_hgemm(const float* __restrict__ fcb, float* __restrict__ C) {
    extern __shared__ char smem[];
    uint32_t sb = smem_u32(smem);
    int tid = threadIdx.x;
    int wid = tid >> 5, lane = tid & 31;
    int wm = wid & 3, wn = wid >> 2;
    int m0 = blockIdx.x * BM, n0 = blockIdx.y * BN;

    const __half* gA0 = g_Ah + (size_t)m0 * KDIM;
    const __half* gB0 = g_Bh + (size_t)n0 * KDIM;

    auto load_stage = [&](int kt, int s) {
        uint32_t sa = sb + s * STAGE;
        const __half* gA = gA0 + kt * BK;
#pragma unroll
        for (int r8 = 0; r8 < 8; r8++) {
            int li = r8 * 256 + tid;
            int row = li >> 3, seg = li & 7;
            uint32_t dst = sa + row * ROWB + seg * 16;
            const void* src = gA + (size_t)row * KDIM + seg * 8;
            asm volatile("cp.async.cg.shared.global [%0], [%1], 16;" :: "r"(dst), "l"(src));
        }
        uint32_t sbB = sa + SA_BYTES;
        const __half* gB = gB0 + kt * BK;
#pragma unroll
        for (int r4 = 0; r4 < 4; r4++) {
            int li = r4 * 256 + tid;
            int row = li >> 3, seg = li & 7;
            uint32_t dst = sbB + row * ROWB + seg * 16;
            const void* src = gB + (size_t)row * KDIM + seg * 8;
            asm volatile("cp.async.cg.shared.global [%0], [%1], 16;" :: "r"(dst), "l"(src));
        }
        asm volatile("cp.async.commit_group;" ::: "memory");
    };

    float acc[4][8][4];
#pragma unroll
    for (int i = 0; i < 4; i++)
#pragma unroll
        for (int j = 0; j < 8; j++)
#pragma unroll
            for (int q = 0; q < 4; q++) acc[i][j][q] = 0.0f;

    load_stage(0, 0);
    load_stage(1, 1);

    for (int kt = 0; kt < KI; kt++) {
        asm volatile("cp.async.wait_group 1;" ::: "memory");
        __syncthreads();
        int s = kt % NSTAGE;
        if (kt + 2 < KI) load_stage(kt + 2, (kt + 2) % NSTAGE);

        uint32_t sa = sb + s * STAGE;
        uint32_t sB = sa + SA_BYTES;
#pragma unroll
        for (int kk = 0; kk < 4; kk++) {
            uint32_t a[4][4], b[4][4];
#pragma unroll
            for (int i = 0; i < 4; i++) {
                int row = wm * 64 + i * 16 + (lane & 15);
                int ko = kk * 16 + ((lane >> 4) << 3);
                uint32_t ad = sa + row * ROWB + ko * 2;
                asm volatile("ldmatrix.sync.aligned.m8n8.x4.shared.b16 {%0,%1,%2,%3}, [%4];"
                             : "=r"(a[i][0]), "=r"(a[i][1]), "=r"(a[i][2]), "=r"(a[i][3])
                             : "r"(ad));
            }
#pragma unroll
            for (int j2 = 0; j2 < 4; j2++) {
                int nrow = wn * 64 + j2 * 16 + (lane & 7) + (((lane >> 4) & 1) << 3);
                int ko = kk * 16 + (((lane >> 3) & 1) << 3);
                uint32_t bd = sB + nrow * ROWB + ko * 2;
                asm volatile("ldmatrix.sync.aligned.m8n8.x4.shared.b16 {%0,%1,%2,%3}, [%4];"
                             : "=r"(b[j2][0]), "=r"(b[j2][1]), "=r"(b[j2][2]), "=r"(b[j2][3])
                             : "r"(bd));
            }
#pragma unroll
            for (int i = 0; i < 4; i++)
#pragma unroll
                for (int j2 = 0; j2 < 4; j2++) {
                    asm volatile(
                        "mma.sync.aligned.m16n8k16.row.col.f32.f16.f16.f32 "
                        "{%0,%1,%2,%3}, {%4,%5,%6,%7}, {%8,%9}, {%0,%1,%2,%3};"
                        : "+f"(acc[i][2*j2][0]), "+f"(acc[i][2*j2][1]),
                          "+f"(acc[i][2*j2][2]), "+f"(acc[i][2*j2][3])
                        : "r"(a[i][0]), "r"(a[i][1]), "r"(a[i][2]), "r"(a[i][3]),
                          "r"(b[j2][0]), "r"(b[j2][1]));
                    asm volatile(
                        "mma.sync.aligned.m16n8k16.row.col.f32.f16.f16.f32 "
                        "{%0,%1,%2,%3}, {%4,%5,%6,%7}, {%8,%9}, {%0,%1,%2,%3};"
                        : "+f"(acc[i][2*j2+1][0]), "+f"(acc[i][2*j2+1][1]),
                          "+f"(acc[i][2*j2+1][2]), "+f"(acc[i][2*j2+1][3])
                        : "r"(a[i][0]), "r"(a[i][1]), "r"(a[i][2]), "r"(a[i][3]),
                          "r"(b[j2][2]), "r"(b[j2][3]));
                }
        }
        __syncthreads();
    }
    asm volatile("cp.async.wait_group 0;" ::: "memory");

#pragma unroll
    for (int j = 0; j < 8; j++) {
        int ncol = n0 + wn * 64 + j * 8 + (lane & 3) * 2;
        float b0 = fcb[ncol], b1 = fcb[ncol + 1];
#pragma unroll
        for (int i = 0; i < 4; i++) {
            int mrow = m0 + wm * 64 + i * 16 + (lane >> 2);
            float2 v0 = {acc[i][j][0] + b0, acc[i][j][1] + b1};
            float2 v1 = {acc[i][j][2] + b0, acc[i][j][3] + b1};
            *(float2*)(C + (size_t)mrow * VOC + ncol) = v0;
            *(float2*)(C + (size_t)(mrow + 8) * VOC + ncol) = v1;
        }
    }
}

// ---------------------------------------------------------------------------
extern "C" void kernel_launch(void* const* d_in, const int* in_sizes, int n_in,
                              void* d_out, int out_size) {
    const int*   decX = (const int*)d_in[0];
    const float* enc  = (const float*)d_in[1];
    const float* h0   = (const float*)d_in[2];
    const float* c0   = (const float*)d_in[3];
    const float* embW = (const float*)d_in[4];
    const float* Wih  = (const float*)d_in[5];
    const float* Whh  = (const float*)d_in[6];
    const float* bih  = (const float*)d_in[7];
    const float* bhh  = (const float*)d_in[8];
    const float* attW = (const float*)d_in[9];
    const float* attb = (const float*)d_in[10];
    const float* fcW  = (const float*)d_in[11];
    const float* fcb  = (const float*)d_in[12];
    float* out = (float*)d_out;

    float *p_emb, *p_xih, *p_cat, *p_aout, *p_bias;
    cudaGetSymbolAddress((void**)&p_emb,  g_emb);
    cudaGetSymbolAddress((void**)&p_xih,  g_xih);
    cudaGetSymbolAddress((void**)&p_cat,  g_cat);
    cudaGetSymbolAddress((void**)&p_aout, g_aout);
    cudaGetSymbolAddress((void**)&p_bias, g_bias);

    cudaFuncSetAttribute(k_hgemm, cudaFuncAttributeMaxDynamicSharedMemorySize, SM_TOTAL);

    k_cvt_b<<<(VOC * HDIM / 4 + 255) / 256, 256>>>(fcW);

    k_bias<<<8, 256>>>(bih, bhh);
    k_embed<<<M_BT, 256>>>(decX, embW);
    k_sgemm<<<dim3(G4 / 128, M_BT / 128), 256>>>(p_emb, Wih, p_bias, p_xih,
                                                 M_BT, G4, EDIM, 0);
    for (int t = 0; t < TD; t++) {
        k_ls<<<dim3(16, KCH), 256>>>(t, h0, Whh);
        k_pw<<<64, 256>>>(t, c0);
    }
    k_attn<<<256, 256>>>(enc);
    k_sgemm<<<dim3(HDIM / 128, M_BT / 128), 256>>>(p_cat, attW, attb, p_aout,
                                                   M_BT, HDIM, 2 * HDIM, 1);
    k_cvt_a<<<(M_BT * HDIM / 4 + 255) / 256, 256>>>();
    k_hgemm<<<dim3(M_BT / BM, VOC / BN), 256, SM_TOTAL>>>(fcb, out);
    k_tail<<<64, 256>>>(out);
}

// round 7
// speedup vs baseline: 1.5631x; 1.0667x over previous
#include <cuda_runtime.h>
#include <cuda_fp16.h>
#include <math.h>
#include <stdint.h>

// Problem constants
#define BSZ   32
#define TD    64
#define TEC   128
#define EDIM  256
#define HDIM  512
#define G4    2048
#define VOC   32000
#define M_BT  2048

// HMMA fc-GEMM tiling (fp16, K = 512)
#define BM    256
#define BN    128
#define BK    64
#define KDIM  512
#define KI    (KDIM / BK)
#define ROWB  144
#define SA_BYTES (BM * ROWB)
#define SB_BYTES (BN * ROWB)
#define STAGE    (SA_BYTES + SB_BYTES)
#define NSTAGE   3
#define SM_TOTAL (NSTAGE * STAGE)

// Fused per-step LSTM kernel: 64 CTAs, CTA owns 8 units (32 permuted W rows)
#define SAROW 1040                       // 512*2 + 16 pad
#define SMA   0
#define SMH   (32 * SAROW)               // 33280
#define SMG   (SMH + 32 * SAROW)         // 66560
#define STEP_SMEM (SMG + 32 * 33 * 4)    // 70784

// Scratch
__device__ float g_bias[G4];
__device__ float g_emb [M_BT * EDIM];
__device__ float g_xihp[(size_t)TD * G4 * BSZ];   // permuted: [t][u*4+g][b]
__device__ float g_hs  [TD * BSZ * HDIM];
__device__ float g_c   [BSZ * HDIM];
__device__ float g_cat [M_BT * 2 * HDIM];
__device__ float g_aout[M_BT * HDIM];
__device__ __align__(16) __half g_Whp[(size_t)G4 * HDIM];   // permuted W_hh fp16
__device__ __align__(16) __half g_hf [BSZ * HDIM];          // running h fp16
__device__ __align__(16) __half g_Ah[(size_t)M_BT * KDIM];
__device__ __align__(16) __half g_Bh[(size_t)VOC * KDIM];

__device__ __forceinline__ float sigf(float x) { return 1.0f / (1.0f + expf(-x)); }

__device__ __forceinline__ uint32_t smem_u32(const void* p) {
    uint32_t a;
    asm("{ .reg .u64 t; cvta.to.shared.u64 t, %1; cvt.u32.u64 %0, t; }" : "=r"(a) : "l"(p));
    return a;
}

// ---------------------------------------------------------------------------
__global__ void k_bias(const float* __restrict__ bih, const float* __restrict__ bhh) {
    int i = blockIdx.x * 256 + threadIdx.x;
    if (i < G4) g_bias[i] = bih[i] + bhh[i];
}

__global__ void k_embed(const int* __restrict__ decX, const float* __restrict__ embW) {
    int m = blockIdx.x;
    int e = threadIdx.x;
    int b = m & (BSZ - 1);
    int t = m >> 5;
    int tok = decX[b * TD + t];
    g_emb[m * EDIM + e] = embW[tok * EDIM + e];
}

// Generic fp32 GEMM: C = act(A[M,K]*B[N,K]^T + bias)
// act: 0=none, 1=tanh, 2=permuted x_ih store into g_xihp (no activation)
__global__ __launch_bounds__(256, 2)
void k_sgemm(const float* __restrict__ A, const float* __restrict__ Bm,
             const float* __restrict__ bias, float* __restrict__ C,
             int M, int N, int K, int act) {
    __shared__ float As[8][132];
    __shared__ float Bs[8][132];
    int tid = threadIdx.x;
    int m0 = blockIdx.y * 128, n0 = blockIdx.x * 128;
    int lr = tid >> 1;
    int lc = (tid & 1) * 4;
    const float* Ap = A + (size_t)(m0 + lr) * K + lc;
    const float* Bp = Bm + (size_t)(n0 + lr) * K + lc;
    int tx = tid & 15, ty = tid >> 4;
    float acc[8][8] = {};
    for (int kt = 0; kt < K; kt += 8) {
        float4 av = *(const float4*)(Ap + kt);
        float4 bv = *(const float4*)(Bp + kt);
        As[lc + 0][lr] = av.x; As[lc + 1][lr] = av.y;
        As[lc + 2][lr] = av.z; As[lc + 3][lr] = av.w;
        Bs[lc + 0][lr] = bv.x; Bs[lc + 1][lr] = bv.y;
        Bs[lc + 2][lr] = bv.z; Bs[lc + 3][lr] = bv.w;
        __syncthreads();
#pragma unroll
        for (int k = 0; k < 8; k++) {
            float a[8], bb[8];
#pragma unroll
            for (int i = 0; i < 8; i++) a[i] = As[k][ty * 8 + i];
#pragma unroll
            for (int j = 0; j < 8; j++) bb[j] = Bs[k][tx * 8 + j];
#pragma unroll
            for (int i = 0; i < 8; i++)
#pragma unroll
                for (int j = 0; j < 8; j++) acc[i][j] += a[i] * bb[j];
        }
        __syncthreads();
    }
#pragma unroll
    for (int i = 0; i < 8; i++) {
        int m = m0 + ty * 8 + i;
#pragma unroll
        for (int j = 0; j < 8; j++) {
            int n = n0 + tx * 8 + j;
            float v = acc[i][j] + bias[n];
            if (act == 1) v = tanhf(v);
            if (act == 2) {
                int tt = m >> 5, bb2 = m & 31;
                int rowp = ((n & 511) << 2) | (n >> 9);
                C[((size_t)tt * G4 + rowp) * 32 + bb2] = v;
            } else {
                C[(size_t)m * N + n] = v;
            }
        }
    }
}

// ---------------------------------------------------------------------------
// Permute + convert W_hh: g_Whp[(u*4+g)*512 + k] = (half)Whh[(g*512+u)*512 + k]
__global__ void k_cvt_w(const float* __restrict__ Whh) {
    int rp = blockIdx.x;               // 0..2047 permuted row
    int u = rp >> 2, g = rp & 3;
    const float* src = Whh + (size_t)(g * HDIM + u) * HDIM;
    __half* dst = g_Whp + (size_t)rp * HDIM;
    int k = threadIdx.x * 4;
    float4 v = *(const float4*)(src + k);
    __half h4[4] = {__float2half(v.x), __float2half(v.y),
                    __float2half(v.z), __float2half(v.w)};
    *(uint2*)(dst + k) = *(uint2*)h4;
}

__global__ void k_cvt_h0(const float* __restrict__ h0) {
    int i = blockIdx.x * 256 + threadIdx.x;
    if (i < BSZ * HDIM) g_hf[i] = __float2half(h0[i]);
}

// ---------------------------------------------------------------------------
// Fused per-step LSTM: one kernel per timestep.
// CTA jt owns units [8jt, 8jt+8) = permuted rows [32jt, 32jt+32).
// MMA: g[32 rows, 32 b] = Whp_tile[32,512] @ h[32,512]^T (fp16, fp32 acc),
// then gate pointwise + state update, all in one kernel.
__global__ __launch_bounds__(128, 1)
void k_step(int t, const float* __restrict__ c0) {
    extern __shared__ char sm[];
    uint32_t sb = smem_u32(sm);
    int tid = threadIdx.x, w = tid >> 5, lane = tid & 31;
    int jt = blockIdx.x;

    // Stage W rows + h into smem (cp.async, padded rows)
    const __half* Wp = g_Whp + (size_t)(jt * 32) * HDIM;
#pragma unroll
    for (int p = 0; p < 16; p++) {
        int idx = p * 128 + tid;               // 2048 segs: 32 rows x 64
        int row = idx >> 6, seg = idx & 63;
        uint32_t dst = sb + SMA + row * SAROW + seg * 16;
        const void* src = Wp + row * HDIM + seg * 8;
        asm volatile("cp.async.cg.shared.global [%0], [%1], 16;" :: "r"(dst), "l"(src));
    }
#pragma unroll
    for (int p = 0; p < 16; p++) {
        int idx = p * 128 + tid;
        int row = idx >> 6, seg = idx & 63;
        uint32_t dst = sb + SMH + row * SAROW + seg * 16;
        const void* src = g_hf + row * HDIM + seg * 8;
        asm volatile("cp.async.cg.shared.global [%0], [%1], 16;" :: "r"(dst), "l"(src));
    }
    asm volatile("cp.async.commit_group;" ::: "memory");
    asm volatile("cp.async.wait_group 0;" ::: "memory");
    __syncthreads();

    // Warp layout: wm = w>>1 (row-tile of 16), wn = w&1 (b-tile of 16)
    int wm = w >> 1, wn = w & 1;
    float acc[2][4] = {};
#pragma unroll
    for (int kk = 0; kk < 32; kk++) {
        uint32_t a[4], b[4];
        {
            int row = wm * 16 + (lane & 15);
            int ko = kk * 16 + ((lane >> 4) << 3);
            uint32_t ad = sb + SMA + row * SAROW + ko * 2;
            asm volatile("ldmatrix.sync.aligned.m8n8.x4.shared.b16 {%0,%1,%2,%3}, [%4];"
                         : "=r"(a[0]), "=r"(a[1]), "=r"(a[2]), "=r"(a[3]) : "r"(ad));
        }
        {
            int nrow = wn * 16 + (lane & 7) + (((lane >> 4) & 1) << 3);
            int ko = kk * 16 + (((lane >> 3) & 1) << 3);
            uint32_t bd = sb + SMH + nrow * SAROW + ko * 2;
            asm volatile("ldmatrix.sync.aligned.m8n8.x4.shared.b16 {%0,%1,%2,%3}, [%4];"
                         : "=r"(b[0]), "=r"(b[1]), "=r"(b[2]), "=r"(b[3]) : "r"(bd));
        }
#pragma unroll
        for (int s = 0; s < 2; s++) {
            asm volatile(
                "mma.sync.aligned.m16n8k16.row.col.f32.f16.f16.f32 "
                "{%0,%1,%2,%3}, {%4,%5,%6,%7}, {%8,%9}, {%0,%1,%2,%3};"
                : "+f"(acc[s][0]), "+f"(acc[s][1]), "+f"(acc[s][2]), "+f"(acc[s][3])
                : "r"(a[0]), "r"(a[1]), "r"(a[2]), "r"(a[3]),
                  "r"(b[2*s]), "r"(b[2*s+1]));
        }
    }

    // Scatter accumulators to gS[row][b]
    float* gS = (float*)(sm + SMG);
    {
        int r0 = wm * 16 + (lane >> 2);
#pragma unroll
        for (int s = 0; s < 2; s++) {
            int c0i = wn * 16 + s * 8 + 2 * (lane & 3);
            gS[r0 * 33 + c0i]           = acc[s][0];
            gS[r0 * 33 + c0i + 1]       = acc[s][1];
            gS[(r0 + 8) * 33 + c0i]     = acc[s][2];
            gS[(r0 + 8) * 33 + c0i + 1] = acc[s][3];
        }
    }
    __syncthreads();

    // Pointwise: 8 units x 32 b = 256 outputs, 2 per thread
    int b = tid & 31, ug = tid >> 5;
#pragma unroll
    for (int q = 0; q < 2; q++) {
        int ul = ug * 2 + q;                   // 0..7
        int u = jt * 8 + ul;
        const float* xp = g_xihp + ((size_t)t * G4 + u * 4) * 32 + b;
        float gi = gS[(4 * ul + 0) * 33 + b] + xp[0];
        float gf = gS[(4 * ul + 1) * 33 + b] + xp[32];
        float gg = gS[(4 * ul + 2) * 33 + b] + xp[64];
        float go = gS[(4 * ul + 3) * 33 + b] + xp[96];
        float cp = (t == 0) ? c0[b * HDIM + u] : g_c[b * HDIM + u];
        float c = sigf(gf) * cp + sigf(gi) * tanhf(gg);
        g_c[b * HDIM + u] = c;
        float hh = sigf(go) * tanhf(c);
        g_hs[((size_t)t * BSZ + b) * HDIM + u] = hh;
        g_hf[b * HDIM + u] = __float2half(hh);
    }
}

// ---------------------------------------------------------------------------
__global__ void k_attn(const float* __restrict__ enc) {
    __shared__ float hS[8][HDIM];
    __shared__ float sS[8][TEC];
    int bi = blockIdx.x;
    int b = bi >> 3;
    int t0 = (bi & 7) * 8;
    int tid = threadIdx.x;
    int w = tid >> 5, lane = tid & 31;
#pragma unroll
    for (int r = 0; r < 16; r++) {
        int li = r * 256 + tid;
        int tt = li >> 9, k = li & 511;
        hS[tt][k] = g_hs[(size_t)((t0 + tt) * BSZ + b) * HDIM + k];
    }
    __syncthreads();
    for (int te = w; te < TEC; te += 8) {
        const float* ep = enc + (size_t)(b * TEC + te) * HDIM;
        float a8[8] = {};
        for (int k = lane; k < HDIM; k += 32) {
            float e = ep[k];
#pragma unroll
            for (int tt = 0; tt < 8; tt++) a8[tt] += e * hS[tt][k];
        }
#pragma unroll
        for (int tt = 0; tt < 8; tt++) {
            float v = a8[tt];
#pragma unroll
            for (int off = 16; off; off >>= 1) v += __shfl_xor_sync(0xffffffffu, v, off);
            if (lane == 0) sS[tt][te] = v;
        }
    }
    __syncthreads();
    {
        int row = w;
        float sv[4], mx = -1e30f;
#pragma unroll
        for (int q = 0; q < 4; q++) { sv[q] = sS[row][lane + 32 * q]; mx = fmaxf(mx, sv[q]); }
#pragma unroll
        for (int off = 16; off; off >>= 1) mx = fmaxf(mx, __shfl_xor_sync(0xffffffffu, mx, off));
        float sum = 0.0f;
#pragma unroll
        for (int q = 0; q < 4; q++) { sv[q] = expf(sv[q] - mx); sum += sv[q]; }
#pragma unroll
        for (int off = 16; off; off >>= 1) sum += __shfl_xor_sync(0xffffffffu, sum, off);
        float inv = 1.0f / sum;
#pragma unroll
        for (int q = 0; q < 4; q++) sS[row][lane + 32 * q] = sv[q] * inv;
    }
    __syncthreads();
    for (int jj = tid; jj < HDIM; jj += 256) {
        float a8[8] = {};
        for (int te = 0; te < TEC; te++) {
            float e = enc[(size_t)(b * TEC + te) * HDIM + jj];
#pragma unroll
            for (int tt = 0; tt < 8; tt++) a8[tt] += sS[tt][te] * e;
        }
#pragma unroll
        for (int tt = 0; tt < 8; tt++) {
            int m = b * TD + t0 + tt;
            g_cat[(size_t)m * (2 * HDIM) + jj] = hS[tt][jj];
            g_cat[(size_t)m * (2 * HDIM) + HDIM + jj] = a8[tt];
        }
    }
}

__global__ void k_tail(float* __restrict__ out) {
    int i = blockIdx.x * 256 + threadIdx.x;
    if (i < BSZ * HDIM) {
        out[(size_t)M_BT * VOC + i] = g_hs[(size_t)(TD - 1) * BSZ * HDIM + i];
        out[(size_t)M_BT * VOC + BSZ * HDIM + i] = g_c[i];
    }
}

// ---------------------------------------------------------------------------
__global__ void k_cvt_a() {
    size_t i = ((size_t)blockIdx.x * 256 + threadIdx.x) * 4;
    if (i >= (size_t)M_BT * HDIM) return;
    float4 x = *(const float4*)(g_aout + i);
    __half h[4] = {__float2half(x.x), __float2half(x.y),
                   __float2half(x.z), __float2half(x.w)};
    *(uint2*)(g_Ah + i) = *(uint2*)h;
}

__global__ void k_cvt_b(const float* __restrict__ W) {
    size_t i = ((size_t)blockIdx.x * 256 + threadIdx.x) * 4;
    if (i >= (size_t)VOC * HDIM) return;
    float4 x = *(const float4*)(W + i);
    __half h[4] = {__float2half(x.x), __float2half(x.y),
                   __float2half(x.z), __float2half(x.w)};
    *(uint2*)(g_Bh + i) = *(uint2*)h;
}

// ---------------------------------------------------------------------------
// HMMA fc GEMM (unchanged from R6)
__global__ __launch_bounds__(256, 1)
void k_hgemm(const float* __restrict__ fcb, float* __restrict__ C) {
    extern __shared__ char smem[];
    uint32_t sb = smem_u32(smem);
    int tid = threadIdx.x;
    int wid = tid >> 5, lane = tid & 31;
    int wm = wid & 3, wn = wid >> 2;
    int m0 = blockIdx.x * BM, n0 = blockIdx.y * BN;

    const __half* gA0 = g_Ah + (size_t)m0 * KDIM;
    const __half* gB0 = g_Bh + (size_t)n0 * KDIM;

    auto load_stage = [&](int kt, int s) {
        uint32_t sa = sb + s * STAGE;
        const __half* gA = gA0 + kt * BK;
#pragma unroll
        for (int r8 = 0; r8 < 8; r8++) {
            int li = r8 * 256 + tid;
            int row = li >> 3, seg = li & 7;
            uint32_t dst = sa + row * ROWB + seg * 16;
            const void* src = gA + (size_t)row * KDIM + seg * 8;
            asm volatile("cp.async.cg.shared.global [%0], [%1], 16;" :: "r"(dst), "l"(src));
        }
        uint32_t sbB = sa + SA_BYTES;
        const __half* gB = gB0 + kt * BK;
#pragma unroll
        for (int r4 = 0; r4 < 4; r4++) {
            int li = r4 * 256 + tid;
            int row = li >> 3, seg = li & 7;
            uint32_t dst = sbB + row * ROWB + seg * 16;
            const void* src = gB + (size_t)row * KDIM + seg * 8;
            asm volatile("cp.async.cg.shared.global [%0], [%1], 16;" :: "r"(dst), "l"(src));
        }
        asm volatile("cp.async.commit_group;" ::: "memory");
    };

    float acc[4][8][4];
#pragma unroll
    for (int i = 0; i < 4; i++)
#pragma unroll
        for (int j = 0; j < 8; j++)
#pragma unroll
            for (int q = 0; q < 4; q++) acc[i][j][q] = 0.0f;

    load_stage(0, 0);
    load_stage(1, 1);

    for (int kt = 0; kt < KI; kt++) {
        asm volatile("cp.async.wait_group 1;" ::: "memory");
        __syncthreads();
        int s = kt % NSTAGE;
        if (kt + 2 < KI) load_stage(kt + 2, (kt + 2) % NSTAGE);

        uint32_t sa = sb + s * STAGE;
        uint32_t sB = sa + SA_BYTES;
#pragma unroll
        for (int kk = 0; kk < 4; kk++) {
            uint32_t a[4][4], b[4][4];
#pragma unroll
            for (int i = 0; i < 4; i++) {
                int row = wm * 64 + i * 16 + (lane & 15);
                int ko = kk * 16 + ((lane >> 4) << 3);
                uint32_t ad = sa + row * ROWB + ko * 2;
                asm volatile("ldmatrix.sync.aligned.m8n8.x4.shared.b16 {%0,%1,%2,%3}, [%4];"
                             : "=r"(a[i][0]), "=r"(a[i][1]), "=r"(a[i][2]), "=r"(a[i][3])
                             : "r"(ad));
            }
#pragma unroll
            for (int j2 = 0; j2 < 4; j2++) {
                int nrow = wn * 64 + j2 * 16 + (lane & 7) + (((lane >> 4) & 1) << 3);
                int ko = kk * 16 + (((lane >> 3) & 1) << 3);
                uint32_t bd = sB + nrow * ROWB + ko * 2;
                asm volatile("ldmatrix.sync.aligned.m8n8.x4.shared.b16 {%0,%1,%2,%3}, [%4];"
                             : "=r"(b[j2][0]), "=r"(b[j2][1]), "=r"(b[j2][2]), "=r"(b[j2][3])
                             : "r"(bd));
            }
#pragma unroll
            for (int i = 0; i < 4; i++)
#pragma unroll
                for (int j2 = 0; j2 < 4; j2++) {
                    asm volatile(
                        "mma.sync.aligned.m16n8k16.row.col.f32.f16.f16.f32 "
                        "{%0,%1,%2,%3}, {%4,%5,%6,%7}, {%8,%9}, {%0,%1,%2,%3};"
                        : "+f"(acc[i][2*j2][0]), "+f"(acc[i][2*j2][1]),
                          "+f"(acc[i][2*j2][2]), "+f"(acc[i][2*j2][3])
                        : "r"(a[i][0]), "r"(a[i][1]), "r"(a[i][2]), "r"(a[i][3]),
                          "r"(b[j2][0]), "r"(b[j2][1]));
                    asm volatile(
                        "mma.sync.aligned.m16n8k16.row.col.f32.f16.f16.f32 "
                        "{%0,%1,%2,%3}, {%4,%5,%6,%7}, {%8,%9}, {%0,%1,%2,%3};"
                        : "+f"(acc[i][2*j2+1][0]), "+f"(acc[i][2*j2+1][1]),
                          "+f"(acc[i][2*j2+1][2]), "+f"(acc[i][2*j2+1][3])
                        : "r"(a[i][0]), "r"(a[i][1]), "r"(a[i][2]), "r"(a[i][3]),
                          "r"(b[j2][2]), "r"(b[j2][3]));
                }
        }
        __syncthreads();
    }
    asm volatile("cp.async.wait_group 0;" ::: "memory");

#pragma unroll
    for (int j = 0; j < 8; j++) {
        int ncol = n0 + wn * 64 + j * 8 + (lane & 3) * 2;
        float b0 = fcb[ncol], b1 = fcb[ncol + 1];
#pragma unroll
        for (int i = 0; i < 4; i++) {
            int mrow = m0 + wm * 64 + i * 16 + (lane >> 2);
            float2 v0 = {acc[i][j][0] + b0, acc[i][j][1] + b1};
            float2 v1 = {acc[i][j][2] + b0, acc[i][j][3] + b1};
            *(float2*)(C + (size_t)mrow * VOC + ncol) = v0;
            *(float2*)(C + (size_t)(mrow + 8) * VOC + ncol) = v1;
        }
    }
}

// ---------------------------------------------------------------------------
extern "C" void kernel_launch(void* const* d_in, const int* in_sizes, int n_in,
                              void* d_out, int out_size) {
    const int*   decX = (const int*)d_in[0];
    const float* enc  = (const float*)d_in[1];
    const float* h0   = (const float*)d_in[2];
    const float* c0   = (const float*)d_in[3];
    const float* embW = (const float*)d_in[4];
    const float* Wih  = (const float*)d_in[5];
    const float* Whh  = (const float*)d_in[6];
    const float* bih  = (const float*)d_in[7];
    const float* bhh  = (const float*)d_in[8];
    const float* attW = (const float*)d_in[9];
    const float* attb = (const float*)d_in[10];
    const float* fcW  = (const float*)d_in[11];
    const float* fcb  = (const float*)d_in[12];
    float* out = (float*)d_out;

    float *p_emb, *p_xihp, *p_cat, *p_aout, *p_bias;
    cudaGetSymbolAddress((void**)&p_emb,  g_emb);
    cudaGetSymbolAddress((void**)&p_xihp, g_xihp);
    cudaGetSymbolAddress((void**)&p_cat,  g_cat);
    cudaGetSymbolAddress((void**)&p_aout, g_aout);
    cudaGetSymbolAddress((void**)&p_bias, g_bias);

    cudaFuncSetAttribute(k_hgemm, cudaFuncAttributeMaxDynamicSharedMemorySize, SM_TOTAL);
    cudaFuncSetAttribute(k_step,  cudaFuncAttributeMaxDynamicSharedMemorySize, STEP_SMEM);

    k_cvt_b<<<(VOC * HDIM / 4 + 255) / 256, 256>>>(fcW);
    k_cvt_w<<<G4, 128>>>(Whh);
    k_cvt_h0<<<64, 256>>>(h0);

    k_bias<<<8, 256>>>(bih, bhh);
    k_embed<<<M_BT, 256>>>(decX, embW);
    // x_ih (+bias), stored permuted [t][u*4+g][b] for the fused LSTM step
    k_sgemm<<<dim3(G4 / 128, M_BT / 128), 256>>>(p_emb, Wih, p_bias, p_xihp,
                                                 M_BT, G4, EDIM, 2);
    // Fused HMMA LSTM: one kernel per step
    for (int t = 0; t < TD; t++)
        k_step<<<64, 128, STEP_SMEM>>>(t, c0);

    k_attn<<<256, 256>>>(enc);
    k_sgemm<<<dim3(HDIM / 128, M_BT / 128), 256>>>(p_cat, attW, attb, p_aout,
                                                   M_BT, HDIM, 2 * HDIM, 1);
    k_cvt_a<<<(M_BT * HDIM / 4 + 255) / 256, 256>>>();
    k_hgemm<<<dim3(M_BT / BM, VOC / BN), 256, SM_TOTAL>>>(fcb, out);
    k_tail<<<64, 256>>>(out);
}

// round 8
// speedup vs baseline: 1.8017x; 1.1527x over previous
#include <cuda_runtime.h>
#include <cuda_fp16.h>
#include <math.h>
#include <stdint.h>

// Problem constants
#define BSZ   32
#define TD    64
#define TEC   128
#define EDIM  256
#define HDIM  512
#define G4    2048
#define VOC   32000
#define M_BT  2048

// HMMA fc-GEMM tiling (fp16, K = 512)
#define BM    256
#define BN    128
#define BK    64
#define KDIM  512
#define KI    (KDIM / BK)
#define ROWB  144
#define SA_BYTES (BM * ROWB)
#define SB_BYTES (BN * ROWB)
#define STAGE    (SA_BYTES + SB_BYTES)
#define NSTAGE   3
#define SM_TOTAL (NSTAGE * STAGE)

// Persistent LSTM kernel: 64 CTAs, CTA owns 8 units (32 permuted W rows)
#define LCTA  64
#define SAROW 1040                       // 512*2 + 16 pad
#define SMA   0
#define SMH   (32 * SAROW)               // 33280
#define SMG   (SMH + 32 * SAROW)         // 66560
#define STEP_SMEM (SMG + 32 * 33 * 4)    // 70784

// Scratch
__device__ float g_bias[G4];
__device__ float g_emb [M_BT * EDIM];
__device__ float g_xihp[(size_t)TD * G4 * BSZ];   // permuted: [t][u*4+g][b]
__device__ float g_hs  [TD * BSZ * HDIM];
__device__ float g_c   [BSZ * HDIM];
__device__ float g_cat [M_BT * 2 * HDIM];
__device__ float g_aout[M_BT * HDIM];
__device__ unsigned g_bar;
__device__ __align__(16) __half g_Whp[(size_t)G4 * HDIM];   // permuted W_hh fp16
__device__ __align__(16) __half g_hf [BSZ * HDIM];          // running h fp16
__device__ __align__(16) __half g_Ah[(size_t)M_BT * KDIM];
__device__ __align__(16) __half g_Bh[(size_t)VOC * KDIM];

__device__ __forceinline__ float sigf(float x) { return 1.0f / (1.0f + expf(-x)); }

__device__ __forceinline__ uint32_t smem_u32(const void* p) {
    uint32_t a;
    asm("{ .reg .u64 t; cvta.to.shared.u64 t, %1; cvt.u32.u64 %0, t; }" : "=r"(a) : "l"(p));
    return a;
}

// ---------------------------------------------------------------------------
__global__ void k_bias(const float* __restrict__ bih, const float* __restrict__ bhh) {
    int i = blockIdx.x * 256 + threadIdx.x;
    if (i < G4) g_bias[i] = bih[i] + bhh[i];
    if (i == 0) g_bar = 0u;              // reset persistent-kernel barrier each launch
}

__global__ void k_embed(const int* __restrict__ decX, const float* __restrict__ embW) {
    int m = blockIdx.x;
    int e = threadIdx.x;
    int b = m & (BSZ - 1);
    int t = m >> 5;
    int tok = decX[b * TD + t];
    g_emb[m * EDIM + e] = embW[tok * EDIM + e];
}

// Generic fp32 GEMM: C = act(A[M,K]*B[N,K]^T + bias)
// act: 0=none, 1=tanh, 2=permuted x_ih store into g_xihp
__global__ __launch_bounds__(256, 2)
void k_sgemm(const float* __restrict__ A, const float* __restrict__ Bm,
             const float* __restrict__ bias, float* __restrict__ C,
             int M, int N, int K, int act) {
    __shared__ float As[8][132];
    __shared__ float Bs[8][132];
    int tid = threadIdx.x;
    int m0 = blockIdx.y * 128, n0 = blockIdx.x * 128;
    int lr = tid >> 1;
    int lc = (tid & 1) * 4;
    const float* Ap = A + (size_t)(m0 + lr) * K + lc;
    const float* Bp = Bm + (size_t)(n0 + lr) * K + lc;
    int tx = tid & 15, ty = tid >> 4;
    float acc[8][8] = {};
    for (int kt = 0; kt < K; kt += 8) {
        float4 av = *(const float4*)(Ap + kt);
        float4 bv = *(const float4*)(Bp + kt);
        As[lc + 0][lr] = av.x; As[lc + 1][lr] = av.y;
        As[lc + 2][lr] = av.z; As[lc + 3][lr] = av.w;
        Bs[lc + 0][lr] = bv.x; Bs[lc + 1][lr] = bv.y;
        Bs[lc + 2][lr] = bv.z; Bs[lc + 3][lr] = bv.w;
        __syncthreads();
#pragma unroll
        for (int k = 0; k < 8; k++) {
            float a[8], bb[8];
#pragma unroll
            for (int i = 0; i < 8; i++) a[i] = As[k][ty * 8 + i];
#pragma unroll
            for (int j = 0; j < 8; j++) bb[j] = Bs[k][tx * 8 + j];
#pragma unroll
            for (int i = 0; i < 8; i++)
#pragma unroll
                for (int j = 0; j < 8; j++) acc[i][j] += a[i] * bb[j];
        }
        __syncthreads();
    }
#pragma unroll
    for (int i = 0; i < 8; i++) {
        int m = m0 + ty * 8 + i;
#pragma unroll
        for (int j = 0; j < 8; j++) {
            int n = n0 + tx * 8 + j;
            float v = acc[i][j] + bias[n];
            if (act == 1) v = tanhf(v);
            if (act == 2) {
                int tt = m >> 5, bb2 = m & 31;
                int rowp = ((n & 511) << 2) | (n >> 9);
                C[((size_t)tt * G4 + rowp) * 32 + bb2] = v;
            } else {
                C[(size_t)m * N + n] = v;
            }
        }
    }
}

// ---------------------------------------------------------------------------
// Permute + convert W_hh: g_Whp[(u*4+g)*512 + k] = (half)Whh[(g*512+u)*512 + k]
__global__ void k_cvt_w(const float* __restrict__ Whh) {
    int rp = blockIdx.x;
    int u = rp >> 2, g = rp & 3;
    const float* src = Whh + (size_t)(g * HDIM + u) * HDIM;
    __half* dst = g_Whp + (size_t)rp * HDIM;
    int k = threadIdx.x * 4;
    float4 v = *(const float4*)(src + k);
    __half h4[4] = {__float2half(v.x), __float2half(v.y),
                    __float2half(v.z), __float2half(v.w)};
    *(uint2*)(dst + k) = *(uint2*)h4;
}

__global__ void k_cvt_h0(const float* __restrict__ h0) {
    int i = blockIdx.x * 256 + threadIdx.x;
    if (i < BSZ * HDIM) g_hf[i] = __float2half(h0[i]);
}

// ---------------------------------------------------------------------------
// Persistent fused LSTM: ALL 64 timesteps in one launch.
// CTA jt owns units [8jt, 8jt+8) = permuted rows [32jt, 32jt+32).
// W tile lives in SMEM for the whole run; cell state in registers.
// Per step: cp.async restage h -> 32 HMMA k-steps -> pointwise -> global barrier.
__global__ __launch_bounds__(128, 1)
void k_lstm_p(const float* __restrict__ h0f, const float* __restrict__ c0) {
    extern __shared__ char sm[];
    uint32_t sb = smem_u32(sm);
    int tid = threadIdx.x, w = tid >> 5, lane = tid & 31;
    int jt = blockIdx.x;

    // Load W tile once (persists across all 64 steps)
    const __half* Wp = g_Whp + (size_t)(jt * 32) * HDIM;
#pragma unroll
    for (int p = 0; p < 16; p++) {
        int idx = p * 128 + tid;               // 2048 segs: 32 rows x 64
        int row = idx >> 6, seg = idx & 63;
        uint32_t dst = sb + SMA + row * SAROW + seg * 16;
        const void* src = Wp + row * HDIM + seg * 8;
        asm volatile("cp.async.cg.shared.global [%0], [%1], 16;" :: "r"(dst), "l"(src));
    }
    asm volatile("cp.async.commit_group;" ::: "memory");

    // Cell state in registers: thread (ug= tid>>5, b= tid&31) owns units ug*2, ug*2+1
    int b = tid & 31, ug = tid >> 5;
    float creg[2];
#pragma unroll
    for (int q = 0; q < 2; q++)
        creg[q] = c0[b * HDIM + jt * 8 + ug * 2 + q];

    float* gS = (float*)(sm + SMG);
    int wm = w >> 1, wn = w & 1;

    for (int t = 0; t < TD; t++) {
        // Stage h (fp16, 32 KB) into smem
#pragma unroll
        for (int p = 0; p < 16; p++) {
            int idx = p * 128 + tid;
            int row = idx >> 6, seg = idx & 63;
            uint32_t dst = sb + SMH + row * SAROW + seg * 16;
            const void* src = g_hf + row * HDIM + seg * 8;
            asm volatile("cp.async.cg.shared.global [%0], [%1], 16;" :: "r"(dst), "l"(src));
        }
        asm volatile("cp.async.commit_group;" ::: "memory");
        asm volatile("cp.async.wait_group 0;" ::: "memory");
        __syncthreads();

        // MMA: g[32 rows, 32 b] = W[32,512] @ h[32,512]^T
        float acc[2][4] = {};
#pragma unroll
        for (int kk = 0; kk < 32; kk++) {
            uint32_t a[4], bb[4];
            {
                int row = wm * 16 + (lane & 15);
                int ko = kk * 16 + ((lane >> 4) << 3);
                uint32_t ad = sb + SMA + row * SAROW + ko * 2;
                asm volatile("ldmatrix.sync.aligned.m8n8.x4.shared.b16 {%0,%1,%2,%3}, [%4];"
                             : "=r"(a[0]), "=r"(a[1]), "=r"(a[2]), "=r"(a[3]) : "r"(ad));
            }
            {
                int nrow = wn * 16 + (lane & 7) + (((lane >> 4) & 1) << 3);
                int ko = kk * 16 + (((lane >> 3) & 1) << 3);
                uint32_t bd = sb + SMH + nrow * SAROW + ko * 2;
                asm volatile("ldmatrix.sync.aligned.m8n8.x4.shared.b16 {%0,%1,%2,%3}, [%4];"
                             : "=r"(bb[0]), "=r"(bb[1]), "=r"(bb[2]), "=r"(bb[3]) : "r"(bd));
            }
#pragma unroll
            for (int s = 0; s < 2; s++) {
                asm volatile(
                    "mma.sync.aligned.m16n8k16.row.col.f32.f16.f16.f32 "
                    "{%0,%1,%2,%3}, {%4,%5,%6,%7}, {%8,%9}, {%0,%1,%2,%3};"
                    : "+f"(acc[s][0]), "+f"(acc[s][1]), "+f"(acc[s][2]), "+f"(acc[s][3])
                    : "r"(a[0]), "r"(a[1]), "r"(a[2]), "r"(a[3]),
                      "r"(bb[2*s]), "r"(bb[2*s+1]));
            }
        }

        // Scatter accumulators to gS[row][b]
        {
            int r0 = wm * 16 + (lane >> 2);
#pragma unroll
            for (int s = 0; s < 2; s++) {
                int c0i = wn * 16 + s * 8 + 2 * (lane & 3);
                gS[r0 * 33 + c0i]           = acc[s][0];
                gS[r0 * 33 + c0i + 1]       = acc[s][1];
                gS[(r0 + 8) * 33 + c0i]     = acc[s][2];
                gS[(r0 + 8) * 33 + c0i + 1] = acc[s][3];
            }
        }
        __syncthreads();

        // Pointwise: 8 units x 32 b, 2 per thread; c in registers
#pragma unroll
        for (int q = 0; q < 2; q++) {
            int ul = ug * 2 + q;
            int u = jt * 8 + ul;
            const float* xp = g_xihp + ((size_t)t * G4 + u * 4) * 32 + b;
            float gi = gS[(4 * ul + 0) * 33 + b] + xp[0];
            float gf = gS[(4 * ul + 1) * 33 + b] + xp[32];
            float gg = gS[(4 * ul + 2) * 33 + b] + xp[64];
            float go = gS[(4 * ul + 3) * 33 + b] + xp[96];
            float c = sigf(gf) * creg[q] + sigf(gi) * tanhf(gg);
            creg[q] = c;
            float hh = sigf(go) * tanhf(c);
            g_hs[((size_t)t * BSZ + b) * HDIM + u] = hh;
            g_hf[b * HDIM + u] = __float2half(hh);
        }

        // Grid barrier (monotonic counter, plain spin — no nanosleep)
        __threadfence();
        __syncthreads();
        if (tid == 0) {
            atomicAdd(&g_bar, 1u);
            unsigned target = (unsigned)(t + 1) * LCTA;
            volatile unsigned* vb = &g_bar;
            while (*vb < target) { }
        }
        __syncthreads();
    }

    // Write final cell state
#pragma unroll
    for (int q = 0; q < 2; q++)
        g_c[b * HDIM + jt * 8 + ug * 2 + q] = creg[q];
}

// ---------------------------------------------------------------------------
__global__ void k_attn(const float* __restrict__ enc) {
    __shared__ float hS[8][HDIM];
    __shared__ float sS[8][TEC];
    int bi = blockIdx.x;
    int b = bi >> 3;
    int t0 = (bi & 7) * 8;
    int tid = threadIdx.x;
    int w = tid >> 5, lane = tid & 31;
#pragma unroll
    for (int r = 0; r < 16; r++) {
        int li = r * 256 + tid;
        int tt = li >> 9, k = li & 511;
        hS[tt][k] = g_hs[(size_t)((t0 + tt) * BSZ + b) * HDIM + k];
    }
    __syncthreads();
    for (int te = w; te < TEC; te += 8) {
        const float* ep = enc + (size_t)(b * TEC + te) * HDIM;
        float a8[8] = {};
        for (int k = lane; k < HDIM; k += 32) {
            float e = ep[k];
#pragma unroll
            for (int tt = 0; tt < 8; tt++) a8[tt] += e * hS[tt][k];
        }
#pragma unroll
        for (int tt = 0; tt < 8; tt++) {
            float v = a8[tt];
#pragma unroll
            for (int off = 16; off; off >>= 1) v += __shfl_xor_sync(0xffffffffu, v, off);
            if (lane == 0) sS[tt][te] = v;
        }
    }
    __syncthreads();
    {
        int row = w;
        float sv[4], mx = -1e30f;
#pragma unroll
        for (int q = 0; q < 4; q++) { sv[q] = sS[row][lane + 32 * q]; mx = fmaxf(mx, sv[q]); }
#pragma unroll
        for (int off = 16; off; off >>= 1) mx = fmaxf(mx, __shfl_xor_sync(0xffffffffu, mx, off));
        float sum = 0.0f;
#pragma unroll
        for (int q = 0; q < 4; q++) { sv[q] = expf(sv[q] - mx); sum += sv[q]; }
#pragma unroll
        for (int off = 16; off; off >>= 1) sum += __shfl_xor_sync(0xffffffffu, sum, off);
        float inv = 1.0f / sum;
#pragma unroll
        for (int q = 0; q < 4; q++) sS[row][lane + 32 * q] = sv[q] * inv;
    }
    __syncthreads();
    for (int jj = tid; jj < HDIM; jj += 256) {
        float a8[8] = {};
        for (int te = 0; te < TEC; te++) {
            float e = enc[(size_t)(b * TEC + te) * HDIM + jj];
#pragma unroll
            for (int tt = 0; tt < 8; tt++) a8[tt] += sS[tt][te] * e;
        }
#pragma unroll
        for (int tt = 0; tt < 8; tt++) {
            int m = b * TD + t0 + tt;
            g_cat[(size_t)m * (2 * HDIM) + jj] = hS[tt][jj];
            g_cat[(size_t)m * (2 * HDIM) + HDIM + jj] = a8[tt];
        }
    }
}

__global__ void k_tail(float* __restrict__ out) {
    int i = blockIdx.x * 256 + threadIdx.x;
    if (i < BSZ * HDIM) {
        out[(size_t)M_BT * VOC + i] = g_hs[(size_t)(TD - 1) * BSZ * HDIM + i];
        out[(size_t)M_BT * VOC + BSZ * HDIM + i] = g_c[i];
    }
}

// ---------------------------------------------------------------------------
__global__ void k_cvt_a() {
    size_t i = ((size_t)blockIdx.x * 256 + threadIdx.x) * 4;
    if (i >= (size_t)M_BT * HDIM) return;
    float4 x = *(const float4*)(g_aout + i);
    __half h[4] = {__float2half(x.x), __float2half(x.y),
                   __float2half(x.z), __float2half(x.w)};
    *(uint2*)(g_Ah + i) = *(uint2*)h;
}

__global__ void k_cvt_b(const float* __restrict__ W) {
    size_t i = ((size_t)blockIdx.x * 256 + threadIdx.x) * 4;
    if (i >= (size_t)VOC * HDIM) return;
    float4 x = *(const float4*)(W + i);
    __half h[4] = {__float2half(x.x), __float2half(x.y),
                   __float2half(x.z), __float2half(x.w)};
    *(uint2*)(g_Bh + i) = *(uint2*)h;
}

// ---------------------------------------------------------------------------
// HMMA fc GEMM (unchanged)
__global__ __launch_bounds__(256, 1)
void k_hgemm(const float* __restrict__ fcb, float* __restrict__ C) {
    extern __shared__ char smem[];
    uint32_t sb = smem_u32(smem);
    int tid = threadIdx.x;
    int wid = tid >> 5, lane = tid & 31;
    int wm = wid & 3, wn = wid >> 2;
    int m0 = blockIdx.x * BM, n0 = blockIdx.y * BN;

    const __half* gA0 = g_Ah + (size_t)m0 * KDIM;
    const __half* gB0 = g_Bh + (size_t)n0 * KDIM;

    auto load_stage = [&](int kt, int s) {
        uint32_t sa = sb + s * STAGE;
        const __half* gA = gA0 + kt * BK;
#pragma unroll
        for (int r8 = 0; r8 < 8; r8++) {
            int li = r8 * 256 + tid;
            int row = li >> 3, seg = li & 7;
            uint32_t dst = sa + row * ROWB + seg * 16;
            const void* src = gA + (size_t)row * KDIM + seg * 8;
            asm volatile("cp.async.cg.shared.global [%0], [%1], 16;" :: "r"(dst), "l"(src));
        }
        uint32_t sbB = sa + SA_BYTES;
        const __half* gB = gB0 + kt * BK;
#pragma unroll
        for (int r4 = 0; r4 < 4; r4++) {
            int li = r4 * 256 + tid;
            int row = li >> 3, seg = li & 7;
            uint32_t dst = sbB + row * ROWB + seg * 16;
            const void* src = gB + (size_t)row * KDIM + seg * 8;
            asm volatile("cp.async.cg.shared.global [%0], [%1], 16;" :: "r"(dst), "l"(src));
        }
        asm volatile("cp.async.commit_group;" ::: "memory");
    };

    float acc[4][8][4];
#pragma unroll
    for (int i = 0; i < 4; i++)
#pragma unroll
        for (int j = 0; j < 8; j++)
#pragma unroll
            for (int q = 0; q < 4; q++) acc[i][j][q] = 0.0f;

    load_stage(0, 0);
    load_stage(1, 1);

    for (int kt = 0; kt < KI; kt++) {
        asm volatile("cp.async.wait_group 1;" ::: "memory");
        __syncthreads();
        int s = kt % NSTAGE;
        if (kt + 2 < KI) load_stage(kt + 2, (kt + 2) % NSTAGE);

        uint32_t sa = sb + s * STAGE;
        uint32_t sB = sa + SA_BYTES;
#pragma unroll
        for (int kk = 0; kk < 4; kk++) {
            uint32_t a[4][4], b[4][4];
#pragma unroll
            for (int i = 0; i < 4; i++) {
                int row = wm * 64 + i * 16 + (lane & 15);
                int ko = kk * 16 + ((lane >> 4) << 3);
                uint32_t ad = sa + row * ROWB + ko * 2;
                asm volatile("ldmatrix.sync.aligned.m8n8.x4.shared.b16 {%0,%1,%2,%3}, [%4];"
                             : "=r"(a[i][0]), "=r"(a[i][1]), "=r"(a[i][2]), "=r"(a[i][3])
                             : "r"(ad));
            }
#pragma unroll
            for (int j2 = 0; j2 < 4; j2++) {
                int nrow = wn * 64 + j2 * 16 + (lane & 7) + (((lane >> 4) & 1) << 3);
                int ko = kk * 16 + (((lane >> 3) & 1) << 3);
                uint32_t bd = sB + nrow * ROWB + ko * 2;
                asm volatile("ldmatrix.sync.aligned.m8n8.x4.shared.b16 {%0,%1,%2,%3}, [%4];"
                             : "=r"(b[j2][0]), "=r"(b[j2][1]), "=r"(b[j2][2]), "=r"(b[j2][3])
                             : "r"(bd));
            }
#pragma unroll
            for (int i = 0; i < 4; i++)
#pragma unroll
                for (int j2 = 0; j2 < 4; j2++) {
                    asm volatile(
                        "mma.sync.aligned.m16n8k16.row.col.f32.f16.f16.f32 "
                        "{%0,%1,%2,%3}, {%4,%5,%6,%7}, {%8,%9}, {%0,%1,%2,%3};"
                        : "+f"(acc[i][2*j2][0]), "+f"(acc[i][2*j2][1]),
                          "+f"(acc[i][2*j2][2]), "+f"(acc[i][2*j2][3])
                        : "r"(a[i][0]), "r"(a[i][1]), "r"(a[i][2]), "r"(a[i][3]),
                          "r"(b[j2][0]), "r"(b[j2][1]));
                    asm volatile(
                        "mma.sync.aligned.m16n8k16.row.col.f32.f16.f16.f32 "
                        "{%0,%1,%2,%3}, {%4,%5,%6,%7}, {%8,%9}, {%0,%1,%2,%3};"
                        : "+f"(acc[i][2*j2+1][0]), "+f"(acc[i][2*j2+1][1]),
                          "+f"(acc[i][2*j2+1][2]), "+f"(acc[i][2*j2+1][3])
                        : "r"(a[i][0]), "r"(a[i][1]), "r"(a[i][2]), "r"(a[i][3]),
                          "r"(b[j2][2]), "r"(b[j2][3]));
                }
        }
        __syncthreads();
    }
    asm volatile("cp.async.wait_group 0;" ::: "memory");

#pragma unroll
    for (int j = 0; j < 8; j++) {
        int ncol = n0 + wn * 64 + j * 8 + (lane & 3) * 2;
        float b0 = fcb[ncol], b1 = fcb[ncol + 1];
#pragma unroll
        for (int i = 0; i < 4; i++) {
            int mrow = m0 + wm * 64 + i * 16 + (lane >> 2);
            float2 v0 = {acc[i][j][0] + b0, acc[i][j][1] + b1};
            float2 v1 = {acc[i][j][2] + b0, acc[i][j][3] + b1};
            *(float2*)(C + (size_t)mrow * VOC + ncol) = v0;
            *(float2*)(C + (size_t)(mrow + 8) * VOC + ncol) = v1;
        }
    }
}

// ---------------------------------------------------------------------------
extern "C" void kernel_launch(void* const* d_in, const int* in_sizes, int n_in,
                              void* d_out, int out_size) {
    const int*   decX = (const int*)d_in[0];
    const float* enc  = (const float*)d_in[1];
    const float* h0   = (const float*)d_in[2];
    const float* c0   = (const float*)d_in[3];
    const float* embW = (const float*)d_in[4];
    const float* Wih  = (const float*)d_in[5];
    const float* Whh  = (const float*)d_in[6];
    const float* bih  = (const float*)d_in[7];
    const float* bhh  = (const float*)d_in[8];
    const float* attW = (const float*)d_in[9];
    const float* attb = (const float*)d_in[10];
    const float* fcW  = (const float*)d_in[11];
    const float* fcb  = (const float*)d_in[12];
    float* out = (float*)d_out;

    float *p_emb, *p_xihp, *p_cat, *p_aout, *p_bias;
    cudaGetSymbolAddress((void**)&p_emb,  g_emb);
    cudaGetSymbolAddress((void**)&p_xihp, g_xihp);
    cudaGetSymbolAddress((void**)&p_cat,  g_cat);
    cudaGetSymbolAddress((void**)&p_aout, g_aout);
    cudaGetSymbolAddress((void**)&p_bias, g_bias);

    cudaFuncSetAttribute(k_hgemm,  cudaFuncAttributeMaxDynamicSharedMemorySize, SM_TOTAL);
    cudaFuncSetAttribute(k_lstm_p, cudaFuncAttributeMaxDynamicSharedMemorySize, STEP_SMEM);

    k_cvt_b<<<(VOC * HDIM / 4 + 255) / 256, 256>>>(fcW);
    k_cvt_w<<<G4, 128>>>(Whh);
    k_cvt_h0<<<64, 256>>>(h0);

    k_bias<<<8, 256>>>(bih, bhh);          // also resets g_bar
    k_embed<<<M_BT, 256>>>(decX, embW);
    k_sgemm<<<dim3(G4 / 128, M_BT / 128), 256>>>(p_emb, Wih, p_bias, p_xihp,
                                                 M_BT, G4, EDIM, 2);
    // Persistent fused HMMA LSTM (all 64 steps, one launch)
    k_lstm_p<<<LCTA, 128, STEP_SMEM>>>(h0, c0);

    k_attn<<<256, 256>>>(enc);
    k_sgemm<<<dim3(HDIM / 128, M_BT / 128), 256>>>(p_cat, attW, attb, p_aout,
                                                   M_BT, HDIM, 2 * HDIM, 1);
    k_cvt_a<<<(M_BT * HDIM / 4 + 255) / 256, 256>>>();
    k_hgemm<<<dim3(M_BT / BM, VOC / BN), 256, SM_TOTAL>>>(fcb, out);
    k_tail<<<64, 256>>>(out);
}

// round 9
// speedup vs baseline: 2.3190x; 1.2871x over previous
#include <cuda_runtime.h>
#include <cuda_fp16.h>
#include <math.h>
#include <stdint.h>

// Problem constants
#define BSZ   32
#define TD    64
#define TEC   128
#define EDIM  256
#define HDIM  512
#define G4    2048
#define VOC   32000
#define M_BT  2048

// HMMA GEMM tiling (shared by fc / xih / attn gemms)
#define BM    256
#define BN    128
#define BK    64
#define KDIM  512
#define KI    (KDIM / BK)
#define ROWB  144
#define SA_BYTES (BM * ROWB)
#define SB_BYTES (BN * ROWB)
#define STAGE    (SA_BYTES + SB_BYTES)
#define NSTAGE   3
#define SM_TOTAL (NSTAGE * STAGE)

// Persistent LSTM kernel
#define LCTA  64
#define SAROW 1040
#define SMA   0
#define SMH   (32 * SAROW)
#define SMG   (SMH + 32 * SAROW)
#define STEP_SMEM (SMG + 32 * 33 * 4)

// Scratch
__device__ float g_bias[G4];
__device__ float g_xihp[(size_t)TD * G4 * BSZ];   // permuted: [t][u*4+g][b]
__device__ float g_hs  [TD * BSZ * HDIM];
__device__ float g_c   [BSZ * HDIM];
__device__ unsigned g_bar;
__device__ __align__(16) __half g_embh[M_BT * EDIM];          // fp16 embeddings
__device__ __align__(16) __half g_Wihh[(size_t)G4 * EDIM];    // fp16 W_ih
__device__ __align__(16) __half g_cath[(size_t)M_BT * 2 * HDIM];
__device__ __align__(16) __half g_attWh[(size_t)HDIM * 2 * HDIM];
__device__ __align__(16) __half g_Whp[(size_t)G4 * HDIM];     // permuted W_hh fp16
__device__ __align__(16) __half g_hf [BSZ * HDIM];            // running h fp16
__device__ __align__(16) __half g_Ah[(size_t)M_BT * KDIM];    // fc A (attn output)
__device__ __align__(16) __half g_Bh[(size_t)VOC * KDIM];     // fc B (fcW)

__device__ __forceinline__ float sigf(float x) { return 1.0f / (1.0f + expf(-x)); }

__device__ __forceinline__ uint32_t smem_u32(const void* p) {
    uint32_t a;
    asm("{ .reg .u64 t; cvta.to.shared.u64 t, %1; cvt.u32.u64 %0, t; }" : "=r"(a) : "l"(p));
    return a;
}

// ---------------------------------------------------------------------------
__global__ void k_bias(const float* __restrict__ bih, const float* __restrict__ bhh) {
    int i = blockIdx.x * 256 + threadIdx.x;
    if (i < G4) g_bias[i] = bih[i] + bhh[i];
    if (i == 0) g_bar = 0u;
}

// Embedding gather -> fp16
__global__ void k_embed(const int* __restrict__ decX, const float* __restrict__ embW) {
    int m = blockIdx.x;
    int e = threadIdx.x;
    int b = m & (BSZ - 1);
    int t = m >> 5;
    int tok = decX[b * TD + t];
    g_embh[m * EDIM + e] = __float2half(embW[tok * EDIM + e]);
}

// Generic fp32 -> fp16 conversion (vectorized x4)
__global__ void k_cvtf(const float* __restrict__ src, __half* __restrict__ dst, int n4) {
    int i = blockIdx.x * 256 + threadIdx.x;
    if (i >= n4) return;
    float4 x = *(const float4*)(src + (size_t)i * 4);
    __half h[4] = {__float2half(x.x), __float2half(x.y),
                   __float2half(x.z), __float2half(x.w)};
    *(uint2*)(dst + (size_t)i * 4) = *(uint2*)h;
}

// Permute + convert W_hh: g_Whp[(u*4+g)*512 + k] = (half)Whh[(g*512+u)*512 + k]
__global__ void k_cvt_w(const float* __restrict__ Whh) {
    int rp = blockIdx.x;
    int u = rp >> 2, g = rp & 3;
    const float* src = Whh + (size_t)(g * HDIM + u) * HDIM;
    __half* dst = g_Whp + (size_t)rp * HDIM;
    int k = threadIdx.x * 4;
    float4 v = *(const float4*)(src + k);
    __half h4[4] = {__float2half(v.x), __float2half(v.y),
                    __float2half(v.z), __float2half(v.w)};
    *(uint2*)(dst + k) = *(uint2*)h4;
}

__global__ void k_cvt_h0(const float* __restrict__ h0) {
    int i = blockIdx.x * 256 + threadIdx.x;
    if (i < BSZ * HDIM) g_hf[i] = __float2half(h0[i]);
}

// ---------------------------------------------------------------------------
// Generalized fp16 HMMA GEMM: acc[M,N] = A[M,K] @ B[N,K]^T (+bias epilogue).
// mode 0: v = acc + bias -> permuted fp32 store to g_xihp   (xih, N=2048)
// mode 1: v = tanh(acc + bias) -> fp16 store to g_Ah[m*512+n] (attn-out, N=512)
__global__ __launch_bounds__(256, 1)
void k_hgemm2(const __half* __restrict__ A, const __half* __restrict__ B,
              const float* __restrict__ bias, int K, int nI, int mode) {
    extern __shared__ char smem[];
    uint32_t sb = smem_u32(smem);
    int tid = threadIdx.x;
    int wid = tid >> 5, lane = tid & 31;
    int wm = wid & 3, wn = wid >> 2;
    int m0 = blockIdx.x * BM, n0 = blockIdx.y * BN;

    const __half* gA0 = A + (size_t)m0 * K;
    const __half* gB0 = B + (size_t)n0 * K;

    auto load_stage = [&](int kt, int s) {
        uint32_t sa = sb + s * STAGE;
        const __half* gA = gA0 + kt * BK;
#pragma unroll
        for (int r8 = 0; r8 < 8; r8++) {
            int li = r8 * 256 + tid;
            int row = li >> 3, seg = li & 7;
            uint32_t dst = sa + row * ROWB + seg * 16;
            const void* src = gA + (size_t)row * K + seg * 8;
            asm volatile("cp.async.cg.shared.global [%0], [%1], 16;" :: "r"(dst), "l"(src));
        }
        uint32_t sbB = sa + SA_BYTES;
        const __half* gB = gB0 + kt * BK;
#pragma unroll
        for (int r4 = 0; r4 < 4; r4++) {
            int li = r4 * 256 + tid;
            int row = li >> 3, seg = li & 7;
            uint32_t dst = sbB + row * ROWB + seg * 16;
            const void* src = gB + (size_t)row * K + seg * 8;
            asm volatile("cp.async.cg.shared.global [%0], [%1], 16;" :: "r"(dst), "l"(src));
        }
        asm volatile("cp.async.commit_group;" ::: "memory");
    };

    float acc[4][8][4];
#pragma unroll
    for (int i = 0; i < 4; i++)
#pragma unroll
        for (int j = 0; j < 8; j++)
#pragma unroll
            for (int q = 0; q < 4; q++) acc[i][j][q] = 0.0f;

    load_stage(0, 0);
    load_stage(1, 1);

    for (int kt = 0; kt < nI; kt++) {
        asm volatile("cp.async.wait_group 1;" ::: "memory");
        __syncthreads();
        int s = kt % NSTAGE;
        if (kt + 2 < nI) load_stage(kt + 2, (kt + 2) % NSTAGE);

        uint32_t sa = sb + s * STAGE;
        uint32_t sB = sa + SA_BYTES;
#pragma unroll
        for (int kk = 0; kk < 4; kk++) {
            uint32_t a[4][4], b[4][4];
#pragma unroll
            for (int i = 0; i < 4; i++) {
                int row = wm * 64 + i * 16 + (lane & 15);
                int ko = kk * 16 + ((lane >> 4) << 3);
                uint32_t ad = sa + row * ROWB + ko * 2;
                asm volatile("ldmatrix.sync.aligned.m8n8.x4.shared.b16 {%0,%1,%2,%3}, [%4];"
                             : "=r"(a[i][0]), "=r"(a[i][1]), "=r"(a[i][2]), "=r"(a[i][3])
                             : "r"(ad));
            }
#pragma unroll
            for (int j2 = 0; j2 < 4; j2++) {
                int nrow = wn * 64 + j2 * 16 + (lane & 7) + (((lane >> 4) & 1) << 3);
                int ko = kk * 16 + (((lane >> 3) & 1) << 3);
                uint32_t bd = sB + nrow * ROWB + ko * 2;
                asm volatile("ldmatrix.sync.aligned.m8n8.x4.shared.b16 {%0,%1,%2,%3}, [%4];"
                             : "=r"(b[j2][0]), "=r"(b[j2][1]), "=r"(b[j2][2]), "=r"(b[j2][3])
                             : "r"(bd));
            }
#pragma unroll
            for (int i = 0; i < 4; i++)
#pragma unroll
                for (int j2 = 0; j2 < 4; j2++) {
                    asm volatile(
                        "mma.sync.aligned.m16n8k16.row.col.f32.f16.f16.f32 "
                        "{%0,%1,%2,%3}, {%4,%5,%6,%7}, {%8,%9}, {%0,%1,%2,%3};"
                        : "+f"(acc[i][2*j2][0]), "+f"(acc[i][2*j2][1]),
                          "+f"(acc[i][2*j2][2]), "+f"(acc[i][2*j2][3])
                        : "r"(a[i][0]), "r"(a[i][1]), "r"(a[i][2]), "r"(a[i][3]),
                          "r"(b[j2][0]), "r"(b[j2][1]));
                    asm volatile(
                        "mma.sync.aligned.m16n8k16.row.col.f32.f16.f16.f32 "
                        "{%0,%1,%2,%3}, {%4,%5,%6,%7}, {%8,%9}, {%0,%1,%2,%3};"
                        : "+f"(acc[i][2*j2+1][0]), "+f"(acc[i][2*j2+1][1]),
                          "+f"(acc[i][2*j2+1][2]), "+f"(acc[i][2*j2+1][3])
                        : "r"(a[i][0]), "r"(a[i][1]), "r"(a[i][2]), "r"(a[i][3]),
                          "r"(b[j2][2]), "r"(b[j2][3]));
                }
        }
        __syncthreads();
    }
    asm volatile("cp.async.wait_group 0;" ::: "memory");

#pragma unroll
    for (int j = 0; j < 8; j++) {
        int ncol = n0 + wn * 64 + j * 8 + (lane & 3) * 2;
        float b0 = bias[ncol], b1 = bias[ncol + 1];
#pragma unroll
        for (int i = 0; i < 4; i++) {
            int mr0 = m0 + wm * 64 + i * 16 + (lane >> 2);
#pragma unroll
            for (int h = 0; h < 2; h++) {
                int mrow = mr0 + h * 8;
                float v0 = acc[i][j][2*h + 0] + b0;
                float v1 = acc[i][j][2*h + 1] + b1;
                if (mode == 0) {
                    int tt = mrow >> 5, bb2 = mrow & 31;
                    int rp0 = ((ncol & 511) << 2) | (ncol >> 9);
                    int rp1 = (((ncol + 1) & 511) << 2) | ((ncol + 1) >> 9);
                    g_xihp[((size_t)tt * G4 + rp0) * 32 + bb2] = v0;
                    g_xihp[((size_t)tt * G4 + rp1) * 32 + bb2] = v1;
                } else {
                    __half2 hv = __floats2half2_rn(tanhf(v0), tanhf(v1));
                    *(__half2*)(g_Ah + (size_t)mrow * KDIM + ncol) = hv;
                }
            }
        }
    }
}

// ---------------------------------------------------------------------------
// Persistent fused LSTM (validated in R8)
__global__ __launch_bounds__(128, 1)
void k_lstm_p(const float* __restrict__ h0f, const float* __restrict__ c0) {
    extern __shared__ char sm[];
    uint32_t sb = smem_u32(sm);
    int tid = threadIdx.x, w = tid >> 5, lane = tid & 31;
    int jt = blockIdx.x;

    const __half* Wp = g_Whp + (size_t)(jt * 32) * HDIM;
#pragma unroll
    for (int p = 0; p < 16; p++) {
        int idx = p * 128 + tid;
        int row = idx >> 6, seg = idx & 63;
        uint32_t dst = sb + SMA + row * SAROW + seg * 16;
        const void* src = Wp + row * HDIM + seg * 8;
        asm volatile("cp.async.cg.shared.global [%0], [%1], 16;" :: "r"(dst), "l"(src));
    }
    asm volatile("cp.async.commit_group;" ::: "memory");

    int b = tid & 31, ug = tid >> 5;
    float creg[2];
#pragma unroll
    for (int q = 0; q < 2; q++)
        creg[q] = c0[b * HDIM + jt * 8 + ug * 2 + q];

    float* gS = (float*)(sm + SMG);
    int wm = w >> 1, wn = w & 1;

    for (int t = 0; t < TD; t++) {
#pragma unroll
        for (int p = 0; p < 16; p++) {
            int idx = p * 128 + tid;
            int row = idx >> 6, seg = idx & 63;
            uint32_t dst = sb + SMH + row * SAROW + seg * 16;
            const void* src = g_hf + row * HDIM + seg * 8;
            asm volatile("cp.async.cg.shared.global [%0], [%1], 16;" :: "r"(dst), "l"(src));
        }
        asm volatile("cp.async.commit_group;" ::: "memory");
        asm volatile("cp.async.wait_group 0;" ::: "memory");
        __syncthreads();

        float acc[2][4] = {};
#pragma unroll
        for (int kk = 0; kk < 32; kk++) {
            uint32_t a[4], bb[4];
            {
                int row = wm * 16 + (lane & 15);
                int ko = kk * 16 + ((lane >> 4) << 3);
                uint32_t ad = sb + SMA + row * SAROW + ko * 2;
                asm volatile("ldmatrix.sync.aligned.m8n8.x4.shared.b16 {%0,%1,%2,%3}, [%4];"
                             : "=r"(a[0]), "=r"(a[1]), "=r"(a[2]), "=r"(a[3]) : "r"(ad));
            }
            {
                int nrow = wn * 16 + (lane & 7) + (((lane >> 4) & 1) << 3);
                int ko = kk * 16 + (((lane >> 3) & 1) << 3);
                uint32_t bd = sb + SMH + nrow * SAROW + ko * 2;
                asm volatile("ldmatrix.sync.aligned.m8n8.x4.shared.b16 {%0,%1,%2,%3}, [%4];"
                             : "=r"(bb[0]), "=r"(bb[1]), "=r"(bb[2]), "=r"(bb[3]) : "r"(bd));
            }
#pragma unroll
            for (int s = 0; s < 2; s++) {
                asm volatile(
                    "mma.sync.aligned.m16n8k16.row.col.f32.f16.f16.f32 "
                    "{%0,%1,%2,%3}, {%4,%5,%6,%7}, {%8,%9}, {%0,%1,%2,%3};"
                    : "+f"(acc[s][0]), "+f"(acc[s][1]), "+f"(acc[s][2]), "+f"(acc[s][3])
                    : "r"(a[0]), "r"(a[1]), "r"(a[2]), "r"(a[3]),
                      "r"(bb[2*s]), "r"(bb[2*s+1]));
            }
        }
        {
            int r0 = wm * 16 + (lane >> 2);
#pragma unroll
            for (int s = 0; s < 2; s++) {
                int c0i = wn * 16 + s * 8 + 2 * (lane & 3);
                gS[r0 * 33 + c0i]           = acc[s][0];
                gS[r0 * 33 + c0i + 1]       = acc[s][1];
                gS[(r0 + 8) * 33 + c0i]     = acc[s][2];
                gS[(r0 + 8) * 33 + c0i + 1] = acc[s][3];
            }
        }
        __syncthreads();

#pragma unroll
        for (int q = 0; q < 2; q++) {
            int ul = ug * 2 + q;
            int u = jt * 8 + ul;
            const float* xp = g_xihp + ((size_t)t * G4 + u * 4) * 32 + b;
            float gi = gS[(4 * ul + 0) * 33 + b] + xp[0];
            float gf = gS[(4 * ul + 1) * 33 + b] + xp[32];
            float gg = gS[(4 * ul + 2) * 33 + b] + xp[64];
            float go = gS[(4 * ul + 3) * 33 + b] + xp[96];
            float c = sigf(gf) * creg[q] + sigf(gi) * tanhf(gg);
            creg[q] = c;
            float hh = sigf(go) * tanhf(c);
            g_hs[((size_t)t * BSZ + b) * HDIM + u] = hh;
            g_hf[b * HDIM + u] = __float2half(hh);
        }

        __threadfence();
        __syncthreads();
        if (tid == 0) {
            atomicAdd(&g_bar, 1u);
            unsigned target = (unsigned)(t + 1) * LCTA;
            volatile unsigned* vb = &g_bar;
            while (*vb < target) { }
        }
        __syncthreads();
    }
#pragma unroll
    for (int q = 0; q < 2; q++)
        g_c[b * HDIM + jt * 8 + ug * 2 + q] = creg[q];
}

// ---------------------------------------------------------------------------
// Attention — writes cat directly as fp16 [m][0:512)=h, [512:1024)=ctx
__global__ void k_attn(const float* __restrict__ enc) {
    __shared__ float hS[8][HDIM];
    __shared__ float sS[8][TEC];
    int bi = blockIdx.x;
    int b = bi >> 3;
    int t0 = (bi & 7) * 8;
    int tid = threadIdx.x;
    int w = tid >> 5, lane = tid & 31;
#pragma unroll
    for (int r = 0; r < 16; r++) {
        int li = r * 256 + tid;
        int tt = li >> 9, k = li & 511;
        hS[tt][k] = g_hs[(size_t)((t0 + tt) * BSZ + b) * HDIM + k];
    }
    __syncthreads();
    for (int te = w; te < TEC; te += 8) {
        const float* ep = enc + (size_t)(b * TEC + te) * HDIM;
        float a8[8] = {};
        for (int k = lane; k < HDIM; k += 32) {
            float e = ep[k];
#pragma unroll
            for (int tt = 0; tt < 8; tt++) a8[tt] += e * hS[tt][k];
        }
#pragma unroll
        for (int tt = 0; tt < 8; tt++) {
            float v = a8[tt];
#pragma unroll
            for (int off = 16; off; off >>= 1) v += __shfl_xor_sync(0xffffffffu, v, off);
            if (lane == 0) sS[tt][te] = v;
        }
    }
    __syncthreads();
    {
        int row = w;
        float sv[4], mx = -1e30f;
#pragma unroll
        for (int q = 0; q < 4; q++) { sv[q] = sS[row][lane + 32 * q]; mx = fmaxf(mx, sv[q]); }
#pragma unroll
        for (int off = 16; off; off >>= 1) mx = fmaxf(mx, __shfl_xor_sync(0xffffffffu, mx, off));
        float sum = 0.0f;
#pragma unroll
        for (int q = 0; q < 4; q++) { sv[q] = expf(sv[q] - mx); sum += sv[q]; }
#pragma unroll
        for (int off = 16; off; off >>= 1) sum += __shfl_xor_sync(0xffffffffu, sum, off);
        float inv = 1.0f / sum;
#pragma unroll
        for (int q = 0; q < 4; q++) sS[row][lane + 32 * q] = sv[q] * inv;
    }
    __syncthreads();
    for (int jj = tid; jj < HDIM; jj += 256) {
        float a8[8] = {};
        for (int te = 0; te < TEC; te++) {
            float e = enc[(size_t)(b * TEC + te) * HDIM + jj];
#pragma unroll
            for (int tt = 0; tt < 8; tt++) a8[tt] += sS[tt][te] * e;
        }
#pragma unroll
        for (int tt = 0; tt < 8; tt++) {
            int m = b * TD + t0 + tt;
            g_cath[(size_t)m * (2 * HDIM) + jj] = __float2half(hS[tt][jj]);
            g_cath[(size_t)m * (2 * HDIM) + HDIM + jj] = __float2half(a8[tt]);
        }
    }
}

__global__ void k_tail(float* __restrict__ out) {
    int i = blockIdx.x * 256 + threadIdx.x;
    if (i < BSZ * HDIM) {
        out[(size_t)M_BT * VOC + i] = g_hs[(size_t)(TD - 1) * BSZ * HDIM + i];
        out[(size_t)M_BT * VOC + BSZ * HDIM + i] = g_c[i];
    }
}

// ---------------------------------------------------------------------------
// HMMA fc GEMM (unchanged)
__global__ __launch_bounds__(256, 1)
void k_hgemm(const float* __restrict__ fcb, float* __restrict__ C) {
    extern __shared__ char smem[];
    uint32_t sb = smem_u32(smem);
    int tid = threadIdx.x;
    int wid = tid >> 5, lane = tid & 31;
    int wm = wid & 3, wn = wid >> 2;
    int m0 = blockIdx.x * BM, n0 = blockIdx.y * BN;

    const __half* gA0 = g_Ah + (size_t)m0 * KDIM;
    const __half* gB0 = g_Bh + (size_t)n0 * KDIM;

    auto load_stage = [&](int kt, int s) {
        uint32_t sa = sb + s * STAGE;
        const __half* gA = gA0 + kt * BK;
#pragma unroll
        for (int r8 = 0; r8 < 8; r8++) {
            int li = r8 * 256 + tid;
            int row = li >> 3, seg = li & 7;
            uint32_t dst = sa + row * ROWB + seg * 16;
            const void* src = gA + (size_t)row * KDIM + seg * 8;
            asm volatile("cp.async.cg.shared.global [%0], [%1], 16;" :: "r"(dst), "l"(src));
        }
        uint32_t sbB = sa + SA_BYTES;
        const __half* gB = gB0 + kt * BK;
#pragma unroll
        for (int r4 = 0; r4 < 4; r4++) {
            int li = r4 * 256 + tid;
            int row = li >> 3, seg = li & 7;
            uint32_t dst = sbB + row * ROWB + seg * 16;
            const void* src = gB + (size_t)row * KDIM + seg * 8;
            asm volatile("cp.async.cg.shared.global [%0], [%1], 16;" :: "r"(dst), "l"(src));
        }
        asm volatile("cp.async.commit_group;" ::: "memory");
    };

    float acc[4][8][4];
#pragma unroll
    for (int i = 0; i < 4; i++)
#pragma unroll
        for (int j = 0; j < 8; j++)
#pragma unroll
            for (int q = 0; q < 4; q++) acc[i][j][q] = 0.0f;

    load_stage(0, 0);
    load_stage(1, 1);

    for (int kt = 0; kt < KI; kt++) {
        asm volatile("cp.async.wait_group 1;" ::: "memory");
        __syncthreads();
        int s = kt % NSTAGE;
        if (kt + 2 < KI) load_stage(kt + 2, (kt + 2) % NSTAGE);

        uint32_t sa = sb + s * STAGE;
        uint32_t sB = sa + SA_BYTES;
#pragma unroll
        for (int kk = 0; kk < 4; kk++) {
            uint32_t a[4][4], b[4][4];
#pragma unroll
            for (int i = 0; i < 4; i++) {
                int row = wm * 64 + i * 16 + (lane & 15);
                int ko = kk * 16 + ((lane >> 4) << 3);
                uint32_t ad = sa + row * ROWB + ko * 2;
                asm volatile("ldmatrix.sync.aligned.m8n8.x4.shared.b16 {%0,%1,%2,%3}, [%4];"
                             : "=r"(a[i][0]), "=r"(a[i][1]), "=r"(a[i][2]), "=r"(a[i][3])
                             : "r"(ad));
            }
#pragma unroll
            for (int j2 = 0; j2 < 4; j2++) {
                int nrow = wn * 64 + j2 * 16 + (lane & 7) + (((lane >> 4) & 1) << 3);
                int ko = kk * 16 + (((lane >> 3) & 1) << 3);
                uint32_t bd = sB + nrow * ROWB + ko * 2;
                asm volatile("ldmatrix.sync.aligned.m8n8.x4.shared.b16 {%0,%1,%2,%3}, [%4];"
                             : "=r"(b[j2][0]), "=r"(b[j2][1]), "=r"(b[j2][2]), "=r"(b[j2][3])
                             : "r"(bd));
            }
#pragma unroll
            for (int i = 0; i < 4; i++)
#pragma unroll
                for (int j2 = 0; j2 < 4; j2++) {
                    asm volatile(
                        "mma.sync.aligned.m16n8k16.row.col.f32.f16.f16.f32 "
                        "{%0,%1,%2,%3}, {%4,%5,%6,%7}, {%8,%9}, {%0,%1,%2,%3};"
                        : "+f"(acc[i][2*j2][0]), "+f"(acc[i][2*j2][1]),
                          "+f"(acc[i][2*j2][2]), "+f"(acc[i][2*j2][3])
                        : "r"(a[i][0]), "r"(a[i][1]), "r"(a[i][2]), "r"(a[i][3]),
                          "r"(b[j2][0]), "r"(b[j2][1]));
                    asm volatile(
                        "mma.sync.aligned.m16n8k16.row.col.f32.f16.f16.f32 "
                        "{%0,%1,%2,%3}, {%4,%5,%6,%7}, {%8,%9}, {%0,%1,%2,%3};"
                        : "+f"(acc[i][2*j2+1][0]), "+f"(acc[i][2*j2+1][1]),
                          "+f"(acc[i][2*j2+1][2]), "+f"(acc[i][2*j2+1][3])
                        : "r"(a[i][0]), "r"(a[i][1]), "r"(a[i][2]), "r"(a[i][3]),
                          "r"(b[j2][2]), "r"(b[j2][3]));
                }
        }
        __syncthreads();
    }
    asm volatile("cp.async.wait_group 0;" ::: "memory");

#pragma unroll
    for (int j = 0; j < 8; j++) {
        int ncol = n0 + wn * 64 + j * 8 + (lane & 3) * 2;
        float b0 = fcb[ncol], b1 = fcb[ncol + 1];
#pragma unroll
        for (int i = 0; i < 4; i++) {
            int mrow = m0 + wm * 64 + i * 16 + (lane >> 2);
            float2 v0 = {acc[i][j][0] + b0, acc[i][j][1] + b1};
            float2 v1 = {acc[i][j][2] + b0, acc[i][j][3] + b1};
            *(float2*)(C + (size_t)mrow * VOC + ncol) = v0;
            *(float2*)(C + (size_t)(mrow + 8) * VOC + ncol) = v1;
        }
    }
}

// ---------------------------------------------------------------------------
extern "C" void kernel_launch(void* const* d_in, const int* in_sizes, int n_in,
                              void* d_out, int out_size) {
    const int*   decX = (const int*)d_in[0];
    const float* enc  = (const float*)d_in[1];
    const float* h0   = (const float*)d_in[2];
    const float* c0   = (const float*)d_in[3];
    const float* embW = (const float*)d_in[4];
    const float* Wih  = (const float*)d_in[5];
    const float* Whh  = (const float*)d_in[6];
    const float* bih  = (const float*)d_in[7];
    const float* bhh  = (const float*)d_in[8];
    const float* attW = (const float*)d_in[9];
    const float* attb = (const float*)d_in[10];
    const float* fcW  = (const float*)d_in[11];
    const float* fcb  = (const float*)d_in[12];
    float* out = (float*)d_out;

    __half *p_Bh, *p_Wihh, *p_attWh, *p_embh, *p_cath;
    float *p_bias;
    cudaGetSymbolAddress((void**)&p_Bh,    g_Bh);
    cudaGetSymbolAddress((void**)&p_Wihh,  g_Wihh);
    cudaGetSymbolAddress((void**)&p_attWh, g_attWh);
    cudaGetSymbolAddress((void**)&p_embh,  g_embh);
    cudaGetSymbolAddress((void**)&p_cath,  g_cath);
    cudaGetSymbolAddress((void**)&p_bias,  g_bias);

    cudaFuncSetAttribute(k_hgemm,  cudaFuncAttributeMaxDynamicSharedMemorySize, SM_TOTAL);
    cudaFuncSetAttribute(k_hgemm2, cudaFuncAttributeMaxDynamicSharedMemorySize, SM_TOTAL);
    cudaFuncSetAttribute(k_lstm_p, cudaFuncAttributeMaxDynamicSharedMemorySize, STEP_SMEM);

    // Weight conversions
    k_cvtf<<<(VOC * HDIM / 4 + 255) / 256, 256>>>(fcW, p_Bh, VOC * HDIM / 4);
    k_cvtf<<<(G4 * EDIM / 4 + 255) / 256, 256>>>(Wih, p_Wihh, G4 * EDIM / 4);
    k_cvtf<<<(HDIM * 2 * HDIM / 4 + 255) / 256, 256>>>(attW, p_attWh, HDIM * 2 * HDIM / 4);
    k_cvt_w<<<G4, 128>>>(Whh);
    k_cvt_h0<<<64, 256>>>(h0);

    k_bias<<<8, 256>>>(bih, bhh);          // also resets g_bar
    k_embed<<<M_BT, 256>>>(decX, embW);
    // x_ih (+bias) via HMMA, permuted store
    k_hgemm2<<<dim3(M_BT / BM, G4 / BN), 256, SM_TOTAL>>>(p_embh, p_Wihh, p_bias,
                                                          EDIM, EDIM / BK, 0);
    // Persistent fused HMMA LSTM
    k_lstm_p<<<LCTA, 128, STEP_SMEM>>>(h0, c0);

    k_attn<<<256, 256>>>(enc);
    // attn out = tanh(cat @ attW^T + attb) via HMMA, fp16 store to g_Ah
    k_hgemm2<<<dim3(M_BT / BM, HDIM / BN), 256, SM_TOTAL>>>(p_cath, p_attWh, attb,
                                                            2 * HDIM, 2 * HDIM / BK, 1);
    // fc
    k_hgemm<<<dim3(M_BT / BM, VOC / BN), 256, SM_TOTAL>>>(fcb, out);
    k_tail<<<64, 256>>>(out);
}

// round 10
// speedup vs baseline: 2.4740x; 1.0668x over previous
#include <cuda_runtime.h>
#include <cuda_fp16.h>
#include <math.h>
#include <stdint.h>

// Problem constants
#define BSZ   32
#define TD    64
#define TEC   128
#define EDIM  256
#define HDIM  512
#define G4    2048
#define VOC   32000
#define M_BT  2048

// HMMA GEMM tiling
#define BM    256
#define BN    128
#define BK    64
#define KDIM  512
#define KI    (KDIM / BK)
#define ROWB  144
#define SA_BYTES (BM * ROWB)
#define SB_BYTES (BN * ROWB)
#define STAGE    (SA_BYTES + SB_BYTES)
#define NSTAGE   3
#define SM_TOTAL (NSTAGE * STAGE)

// Persistent LSTM kernel: 64 CTAs x 256 threads, CTA owns 8 units (32 W rows)
#define LCTA  64
#define SAROW 1040
#define SMH   (32 * SAROW)
#define SMG   (SMH + 32 * SAROW)               // 66560
#define STEP_SMEM (SMG + 2 * 32 * 33 * 4)      // 75008

// Init kernel grid sections (256 threads each)
#define NB_FC   16000     // fcW cvt: 32000*512/4/256
#define NB_WIH  512       // Wih cvt
#define NB_ATT  512       // attW cvt
#define NB_WHH  1024      // Whh permute+cvt
#define NB_BIAS 8
#define NB_H0   64
#define NB_EMB  2048
#define NB_INIT (NB_FC + NB_WIH + NB_ATT + NB_WHH + NB_BIAS + NB_H0 + NB_EMB)

// Scratch
__device__ float g_bias[G4];
__device__ float g_xihp[(size_t)TD * G4 * BSZ];   // permuted: [t][u*4+g][b]
__device__ float g_hs  [TD * BSZ * HDIM];
__device__ float g_c   [BSZ * HDIM];
__device__ unsigned g_bar;
__device__ __align__(16) __half g_embh[M_BT * EDIM];
__device__ __align__(16) __half g_Wihh[(size_t)G4 * EDIM];
__device__ __align__(16) __half g_cath[(size_t)M_BT * 2 * HDIM];
__device__ __align__(16) __half g_attWh[(size_t)HDIM * 2 * HDIM];
__device__ __align__(16) __half g_Whp[(size_t)G4 * HDIM];
__device__ __align__(16) __half g_hf [BSZ * HDIM];
__device__ __align__(16) __half g_Ah[(size_t)M_BT * KDIM];
__device__ __align__(16) __half g_Bh[(size_t)VOC * KDIM];

__device__ __forceinline__ float sigf(float x) { return 1.0f / (1.0f + expf(-x)); }

__device__ __forceinline__ uint32_t smem_u32(const void* p) {
    uint32_t a;
    asm("{ .reg .u64 t; cvta.to.shared.u64 t, %1; cvt.u32.u64 %0, t; }" : "=r"(a) : "l"(p));
    return a;
}

__device__ __forceinline__ void cvt4(const float* src, __half* dst) {
    float4 x = *(const float4*)src;
    __half h[4] = {__float2half(x.x), __float2half(x.y),
                   __float2half(x.z), __float2half(x.w)};
    *(uint2*)dst = *(uint2*)h;
}

// ---------------------------------------------------------------------------
// ONE fused init kernel: all weight conversions + bias + h0 + embed + bar reset
__global__ void k_init(const float* __restrict__ fcW, const float* __restrict__ Wih,
                       const float* __restrict__ attW, const float* __restrict__ Whh,
                       const float* __restrict__ bih, const float* __restrict__ bhh,
                       const float* __restrict__ h0, const int* __restrict__ decX,
                       const float* __restrict__ embW) {
    int blk = blockIdx.x, tid = threadIdx.x;
    if (blk < NB_FC) {                       // fcW -> g_Bh
        size_t i4 = (size_t)blk * 256 + tid;
        cvt4(fcW + i4 * 4, g_Bh + i4 * 4);
        return;
    }
    blk -= NB_FC;
    if (blk < NB_WIH) {                      // Wih -> g_Wihh
        size_t i4 = (size_t)blk * 256 + tid;
        cvt4(Wih + i4 * 4, g_Wihh + i4 * 4);
        return;
    }
    blk -= NB_WIH;
    if (blk < NB_ATT) {                      // attW -> g_attWh
        size_t i4 = (size_t)blk * 256 + tid;
        cvt4(attW + i4 * 4, g_attWh + i4 * 4);
        return;
    }
    blk -= NB_ATT;
    if (blk < NB_WHH) {                      // Whh permute+cvt -> g_Whp
        size_t i4 = (size_t)blk * 256 + tid;
        size_t e = i4 * 4;
        int rp = (int)(e >> 9), k = (int)(e & 511);
        int u = rp >> 2, g = rp & 3;
        cvt4(Whh + (size_t)(g * HDIM + u) * HDIM + k, g_Whp + (size_t)rp * HDIM + k);
        return;
    }
    blk -= NB_WHH;
    if (blk < NB_BIAS) {                     // bias + barrier reset
        int i = blk * 256 + tid;
        g_bias[i] = bih[i] + bhh[i];
        if (i == 0) g_bar = 0u;
        return;
    }
    blk -= NB_BIAS;
    if (blk < NB_H0) {                       // h0 -> g_hf
        int i = blk * 256 + tid;
        g_hf[i] = __float2half(h0[i]);
        return;
    }
    blk -= NB_H0;
    {                                        // embedding gather -> g_embh
        int m = blk, e = tid;
        int b = m & (BSZ - 1), t = m >> 5;
        int tok = decX[b * TD + t];
        g_embh[m * EDIM + e] = __float2half(embW[tok * EDIM + e]);
    }
}

// ---------------------------------------------------------------------------
// Generalized fp16 HMMA GEMM (unchanged from R9)
__global__ __launch_bounds__(256, 1)
void k_hgemm2(const __half* __restrict__ A, const __half* __restrict__ B,
              const float* __restrict__ bias, int K, int nI, int mode) {
    extern __shared__ char smem[];
    uint32_t sb = smem_u32(smem);
    int tid = threadIdx.x;
    int wid = tid >> 5, lane = tid & 31;
    int wm = wid & 3, wn = wid >> 2;
    int m0 = blockIdx.x * BM, n0 = blockIdx.y * BN;

    const __half* gA0 = A + (size_t)m0 * K;
    const __half* gB0 = B + (size_t)n0 * K;

    auto load_stage = [&](int kt, int s) {
        uint32_t sa = sb + s * STAGE;
        const __half* gA = gA0 + kt * BK;
#pragma unroll
        for (int r8 = 0; r8 < 8; r8++) {
            int li = r8 * 256 + tid;
            int row = li >> 3, seg = li & 7;
            uint32_t dst = sa + row * ROWB + seg * 16;
            const void* src = gA + (size_t)row * K + seg * 8;
            asm volatile("cp.async.cg.shared.global [%0], [%1], 16;" :: "r"(dst), "l"(src));
        }
        uint32_t sbB = sa + SA_BYTES;
        const __half* gB = gB0 + kt * BK;
#pragma unroll
        for (int r4 = 0; r4 < 4; r4++) {
            int li = r4 * 256 + tid;
            int row = li >> 3, seg = li & 7;
            uint32_t dst = sbB + row * ROWB + seg * 16;
            const void* src = gB + (size_t)row * K + seg * 8;
            asm volatile("cp.async.cg.shared.global [%0], [%1], 16;" :: "r"(dst), "l"(src));
        }
        asm volatile("cp.async.commit_group;" ::: "memory");
    };

    float acc[4][8][4];
#pragma unroll
    for (int i = 0; i < 4; i++)
#pragma unroll
        for (int j = 0; j < 8; j++)
#pragma unroll
            for (int q = 0; q < 4; q++) acc[i][j][q] = 0.0f;

    load_stage(0, 0);
    load_stage(1, 1);

    for (int kt = 0; kt < nI; kt++) {
        asm volatile("cp.async.wait_group 1;" ::: "memory");
        __syncthreads();
        int s = kt % NSTAGE;
        if (kt + 2 < nI) load_stage(kt + 2, (kt + 2) % NSTAGE);

        uint32_t sa = sb + s * STAGE;
        uint32_t sB = sa + SA_BYTES;
#pragma unroll
        for (int kk = 0; kk < 4; kk++) {
            uint32_t a[4][4], b[4][4];
#pragma unroll
            for (int i = 0; i < 4; i++) {
                int row = wm * 64 + i * 16 + (lane & 15);
                int ko = kk * 16 + ((lane >> 4) << 3);
                uint32_t ad = sa + row * ROWB + ko * 2;
                asm volatile("ldmatrix.sync.aligned.m8n8.x4.shared.b16 {%0,%1,%2,%3}, [%4];"
                             : "=r"(a[i][0]), "=r"(a[i][1]), "=r"(a[i][2]), "=r"(a[i][3])
                             : "r"(ad));
            }
#pragma unroll
            for (int j2 = 0; j2 < 4; j2++) {
                int nrow = wn * 64 + j2 * 16 + (lane & 7) + (((lane >> 4) & 1) << 3);
                int ko = kk * 16 + (((lane >> 3) & 1) << 3);
                uint32_t bd = sB + nrow * ROWB + ko * 2;
                asm volatile("ldmatrix.sync.aligned.m8n8.x4.shared.b16 {%0,%1,%2,%3}, [%4];"
                             : "=r"(b[j2][0]), "=r"(b[j2][1]), "=r"(b[j2][2]), "=r"(b[j2][3])
                             : "r"(bd));
            }
#pragma unroll
            for (int i = 0; i < 4; i++)
#pragma unroll
                for (int j2 = 0; j2 < 4; j2++) {
                    asm volatile(
                        "mma.sync.aligned.m16n8k16.row.col.f32.f16.f16.f32 "
                        "{%0,%1,%2,%3}, {%4,%5,%6,%7}, {%8,%9}, {%0,%1,%2,%3};"
                        : "+f"(acc[i][2*j2][0]), "+f"(acc[i][2*j2][1]),
                          "+f"(acc[i][2*j2][2]), "+f"(acc[i][2*j2][3])
                        : "r"(a[i][0]), "r"(a[i][1]), "r"(a[i][2]), "r"(a[i][3]),
                          "r"(b[j2][0]), "r"(b[j2][1]));
                    asm volatile(
                        "mma.sync.aligned.m16n8k16.row.col.f32.f16.f16.f32 "
                        "{%0,%1,%2,%3}, {%4,%5,%6,%7}, {%8,%9}, {%0,%1,%2,%3};"
                        : "+f"(acc[i][2*j2+1][0]), "+f"(acc[i][2*j2+1][1]),
                          "+f"(acc[i][2*j2+1][2]), "+f"(acc[i][2*j2+1][3])
                        : "r"(a[i][0]), "r"(a[i][1]), "r"(a[i][2]), "r"(a[i][3]),
                          "r"(b[j2][2]), "r"(b[j2][3]));
                }
        }
        __syncthreads();
    }
    asm volatile("cp.async.wait_group 0;" ::: "memory");

#pragma unroll
    for (int j = 0; j < 8; j++) {
        int ncol = n0 + wn * 64 + j * 8 + (lane & 3) * 2;
        float b0 = bias[ncol], b1 = bias[ncol + 1];
#pragma unroll
        for (int i = 0; i < 4; i++) {
            int mr0 = m0 + wm * 64 + i * 16 + (lane >> 2);
#pragma unroll
            for (int h = 0; h < 2; h++) {
                int mrow = mr0 + h * 8;
                float v0 = acc[i][j][2*h + 0] + b0;
                float v1 = acc[i][j][2*h + 1] + b1;
                if (mode == 0) {
                    int tt = mrow >> 5, bb2 = mrow & 31;
                    int rp0 = ((ncol & 511) << 2) | (ncol >> 9);
                    int rp1 = (((ncol + 1) & 511) << 2) | ((ncol + 1) >> 9);
                    g_xihp[((size_t)tt * G4 + rp0) * 32 + bb2] = v0;
                    g_xihp[((size_t)tt * G4 + rp1) * 32 + bb2] = v1;
                } else {
                    __half2 hv = __floats2half2_rn(tanhf(v0), tanhf(v1));
                    *(__half2*)(g_Ah + (size_t)mrow * KDIM + ncol) = hv;
                }
            }
        }
    }
}

// ---------------------------------------------------------------------------
// Persistent fused LSTM v2: 256 threads, kk-split across warp halves,
// x_ih prefetched into registers before the h-dependency. Writes tail output.
__global__ __launch_bounds__(256, 1)
void k_lstm_p(const float* __restrict__ c0, float* __restrict__ out) {
    extern __shared__ char sm[];
    uint32_t sb = smem_u32(sm);
    int tid = threadIdx.x, w = tid >> 5, lane = tid & 31;
    int jt = blockIdx.x;

    // Stage W tile once (32 rows x 512 halves = 2048 16B segs)
    const __half* Wp = g_Whp + (size_t)(jt * 32) * HDIM;
#pragma unroll
    for (int p = 0; p < 8; p++) {
        int idx = p * 256 + tid;
        int row = idx >> 6, seg = idx & 63;
        uint32_t dst = sb + row * SAROW + seg * 16;
        const void* src = Wp + row * HDIM + seg * 8;
        asm volatile("cp.async.cg.shared.global [%0], [%1], 16;" :: "r"(dst), "l"(src));
    }
    asm volatile("cp.async.commit_group;" ::: "memory");

    int b = tid & 31, ul = tid >> 5;      // one (unit, batch) output per thread
    int u = jt * 8 + ul;
    float creg = c0[b * HDIM + u];
    float hlast = 0.0f;

    float* gS0 = (float*)(sm + SMG);
    float* gS1 = gS0 + 32 * 33;
    int wg = w >> 2, wq = w & 3;          // wg: kk half, wq: quad within half
    int wm = wq >> 1, wn = wq & 1;

    for (int t = 0; t < TD; t++) {
        // Prefetch x_ih gates (independent of h) — overlaps h stage + MMA
        const float* xp = g_xihp + ((size_t)t * G4 + u * 4) * 32 + b;
        float x0 = xp[0], x1 = xp[32], x2 = xp[64], x3 = xp[96];

        // Stage h (32 rows x 64 segs, 256 threads -> 8 iters)
#pragma unroll
        for (int p = 0; p < 8; p++) {
            int idx = p * 256 + tid;
            int row = idx >> 6, seg = idx & 63;
            uint32_t dst = sb + SMH + row * SAROW + seg * 16;
            const void* src = g_hf + row * HDIM + seg * 8;
            asm volatile("cp.async.cg.shared.global [%0], [%1], 16;" :: "r"(dst), "l"(src));
        }
        asm volatile("cp.async.commit_group;" ::: "memory");
        asm volatile("cp.async.wait_group 0;" ::: "memory");
        __syncthreads();

        // MMA: each warp handles 16 of 32 kk steps on its 16x16 tile
        float acc[2][4] = {};
#pragma unroll
        for (int kk2 = 0; kk2 < 16; kk2++) {
            int kk = wg * 16 + kk2;
            uint32_t a[4], bb[4];
            {
                int row = wm * 16 + (lane & 15);
                int ko = kk * 16 + ((lane >> 4) << 3);
                uint32_t ad = sb + row * SAROW + ko * 2;
                asm volatile("ldmatrix.sync.aligned.m8n8.x4.shared.b16 {%0,%1,%2,%3}, [%4];"
                             : "=r"(a[0]), "=r"(a[1]), "=r"(a[2]), "=r"(a[3]) : "r"(ad));
            }
            {
                int nrow = wn * 16 + (lane & 7) + (((lane >> 4) & 1) << 3);
                int ko = kk * 16 + (((lane >> 3) & 1) << 3);
                uint32_t bd = sb + SMH + nrow * SAROW + ko * 2;
                asm volatile("ldmatrix.sync.aligned.m8n8.x4.shared.b16 {%0,%1,%2,%3}, [%4];"
                             : "=r"(bb[0]), "=r"(bb[1]), "=r"(bb[2]), "=r"(bb[3]) : "r"(bd));
            }
#pragma unroll
            for (int s = 0; s < 2; s++) {
                asm volatile(
                    "mma.sync.aligned.m16n8k16.row.col.f32.f16.f16.f32 "
                    "{%0,%1,%2,%3}, {%4,%5,%6,%7}, {%8,%9}, {%0,%1,%2,%3};"
                    : "+f"(acc[s][0]), "+f"(acc[s][1]), "+f"(acc[s][2]), "+f"(acc[s][3])
                    : "r"(a[0]), "r"(a[1]), "r"(a[2]), "r"(a[3]),
                      "r"(bb[2*s]), "r"(bb[2*s+1]));
            }
        }
        // Scatter partials (wg selects buffer)
        {
            float* gD = wg ? gS1 : gS0;
            int r0 = wm * 16 + (lane >> 2);
#pragma unroll
            for (int s = 0; s < 2; s++) {
                int c0i = wn * 16 + s * 8 + 2 * (lane & 3);
                gD[r0 * 33 + c0i]           = acc[s][0];
                gD[r0 * 33 + c0i + 1]       = acc[s][1];
                gD[(r0 + 8) * 33 + c0i]     = acc[s][2];
                gD[(r0 + 8) * 33 + c0i + 1] = acc[s][3];
            }
        }
        __syncthreads();

        // Pointwise: sum the two kk-half partials + prefetched x_ih
        {
            float gi = gS0[(4 * ul + 0) * 33 + b] + gS1[(4 * ul + 0) * 33 + b] + x0;
            float gf = gS0[(4 * ul + 1) * 33 + b] + gS1[(4 * ul + 1) * 33 + b] + x1;
            float gg = gS0[(4 * ul + 2) * 33 + b] + gS1[(4 * ul + 2) * 33 + b] + x2;
            float go = gS0[(4 * ul + 3) * 33 + b] + gS1[(4 * ul + 3) * 33 + b] + x3;
            float c = sigf(gf) * creg + sigf(gi) * tanhf(gg);
            creg = c;
            float hh = sigf(go) * tanhf(c);
            hlast = hh;
            g_hs[((size_t)t * BSZ + b) * HDIM + u] = hh;
            g_hf[b * HDIM + u] = __float2half(hh);
        }

        // Grid barrier (R8-proven pattern)
        __threadfence();
        __syncthreads();
        if (tid == 0) {
            atomicAdd(&g_bar, 1u);
            unsigned target = (unsigned)(t + 1) * LCTA;
            volatile unsigned* vb = &g_bar;
            while (*vb < target) { }
        }
        __syncthreads();
    }

    g_c[b * HDIM + u] = creg;
    // Fused tail: output tuple layout [logits][h][c]
    out[(size_t)M_BT * VOC + b * HDIM + u] = hlast;
    out[(size_t)M_BT * VOC + BSZ * HDIM + b * HDIM + u] = creg;
}

// ---------------------------------------------------------------------------
// Attention — writes cat directly as fp16
__global__ void k_attn(const float* __restrict__ enc) {
    __shared__ float hS[8][HDIM];
    __shared__ float sS[8][TEC];
    int bi = blockIdx.x;
    int b = bi >> 3;
    int t0 = (bi & 7) * 8;
    int tid = threadIdx.x;
    int w = tid >> 5, lane = tid & 31;
#pragma unroll
    for (int r = 0; r < 16; r++) {
        int li = r * 256 + tid;
        int tt = li >> 9, k = li & 511;
        hS[tt][k] = g_hs[(size_t)((t0 + tt) * BSZ + b) * HDIM + k];
    }
    __syncthreads();
    for (int te = w; te < TEC; te += 8) {
        const float* ep = enc + (size_t)(b * TEC + te) * HDIM;
        float a8[8] = {};
        for (int k = lane; k < HDIM; k += 32) {
            float e = ep[k];
#pragma unroll
            for (int tt = 0; tt < 8; tt++) a8[tt] += e * hS[tt][k];
        }
#pragma unroll
        for (int tt = 0; tt < 8; tt++) {
            float v = a8[tt];
#pragma unroll
            for (int off = 16; off; off >>= 1) v += __shfl_xor_sync(0xffffffffu, v, off);
            if (lane == 0) sS[tt][te] = v;
        }
    }
    __syncthreads();
    {
        int row = w;
        float sv[4], mx = -1e30f;
#pragma unroll
        for (int q = 0; q < 4; q++) { sv[q] = sS[row][lane + 32 * q]; mx = fmaxf(mx, sv[q]); }
#pragma unroll
        for (int off = 16; off; off >>= 1) mx = fmaxf(mx, __shfl_xor_sync(0xffffffffu, mx, off));
        float sum = 0.0f;
#pragma unroll
        for (int q = 0; q < 4; q++) { sv[q] = expf(sv[q] - mx); sum += sv[q]; }
#pragma unroll
        for (int off = 16; off; off >>= 1) sum += __shfl_xor_sync(0xffffffffu, sum, off);
        float inv = 1.0f / sum;
#pragma unroll
        for (int q = 0; q < 4; q++) sS[row][lane + 32 * q] = sv[q] * inv;
    }
    __syncthreads();
    for (int jj = tid; jj < HDIM; jj += 256) {
        float a8[8] = {};
        for (int te = 0; te < TEC; te++) {
            float e = enc[(size_t)(b * TEC + te) * HDIM + jj];
#pragma unroll
            for (int tt = 0; tt < 8; tt++) a8[tt] += sS[tt][te] * e;
        }
#pragma unroll
        for (int tt = 0; tt < 8; tt++) {
            int m = b * TD + t0 + tt;
            g_cath[(size_t)m * (2 * HDIM) + jj] = __float2half(hS[tt][jj]);
            g_cath[(size_t)m * (2 * HDIM) + HDIM + jj] = __float2half(a8[tt]);
        }
    }
}

// ---------------------------------------------------------------------------
// HMMA fc GEMM (unchanged)
__global__ __launch_bounds__(256, 1)
void k_hgemm(const float* __restrict__ fcb, float* __restrict__ C) {
    extern __shared__ char smem[];
    uint32_t sb = smem_u32(smem);
    int tid = threadIdx.x;
    int wid = tid >> 5, lane = tid & 31;
    int wm = wid & 3, wn = wid >> 2;
    int m0 = blockIdx.x * BM, n0 = blockIdx.y * BN;

    const __half* gA0 = g_Ah + (size_t)m0 * KDIM;
    const __half* gB0 = g_Bh + (size_t)n0 * KDIM;

    auto load_stage = [&](int kt, int s) {
        uint32_t sa = sb + s * STAGE;
        const __half* gA = gA0 + kt * BK;
#pragma unroll
        for (int r8 = 0; r8 < 8; r8++) {
            int li = r8 * 256 + tid;
            int row = li >> 3, seg = li & 7;
            uint32_t dst = sa + row * ROWB + seg * 16;
            const void* src = gA + (size_t)row * KDIM + seg * 8;
            asm volatile("cp.async.cg.shared.global [%0], [%1], 16;" :: "r"(dst), "l"(src));
        }
        uint32_t sbB = sa + SA_BYTES;
        const __half* gB = gB0 + kt * BK;
#pragma unroll
        for (int r4 = 0; r4 < 4; r4++) {
            int li = r4 * 256 + tid;
            int row = li >> 3, seg = li & 7;
            uint32_t dst = sbB + row * ROWB + seg * 16;
            const void* src = gB + (size_t)row * KDIM + seg * 8;
            asm volatile("cp.async.cg.shared.global [%0], [%1], 16;" :: "r"(dst), "l"(src));
        }
        asm volatile("cp.async.commit_group;" ::: "memory");
    };

    float acc[4][8][4];
#pragma unroll
    for (int i = 0; i < 4; i++)
#pragma unroll
        for (int j = 0; j < 8; j++)
#pragma unroll
            for (int q = 0; q < 4; q++) acc[i][j][q] = 0.0f;

    load_stage(0, 0);
    load_stage(1, 1);

    for (int kt = 0; kt < KI; kt++) {
        asm volatile("cp.async.wait_group 1;" ::: "memory");
        __syncthreads();
        int s = kt % NSTAGE;
        if (kt + 2 < KI) load_stage(kt + 2, (kt + 2) % NSTAGE);

        uint32_t sa = sb + s * STAGE;
        uint32_t sB = sa + SA_BYTES;
#pragma unroll
        for (int kk = 0; kk < 4; kk++) {
            uint32_t a[4][4], b[4][4];
#pragma unroll
            for (int i = 0; i < 4; i++) {
                int row = wm * 64 + i * 16 + (lane & 15);
                int ko = kk * 16 + ((lane >> 4) << 3);
                uint32_t ad = sa + row * ROWB + ko * 2;
                asm volatile("ldmatrix.sync.aligned.m8n8.x4.shared.b16 {%0,%1,%2,%3}, [%4];"
                             : "=r"(a[i][0]), "=r"(a[i][1]), "=r"(a[i][2]), "=r"(a[i][3])
                             : "r"(ad));
            }
#pragma unroll
            for (int j2 = 0; j2 < 4; j2++) {
                int nrow = wn * 64 + j2 * 16 + (lane & 7) + (((lane >> 4) & 1) << 3);
                int ko = kk * 16 + (((lane >> 3) & 1) << 3);
                uint32_t bd = sB + nrow * ROWB + ko * 2;
                asm volatile("ldmatrix.sync.aligned.m8n8.x4.shared.b16 {%0,%1,%2,%3}, [%4];"
                             : "=r"(b[j2][0]), "=r"(b[j2][1]), "=r"(b[j2][2]), "=r"(b[j2][3])
                             : "r"(bd));
            }
#pragma unroll
            for (int i = 0; i < 4; i++)
#pragma unroll
                for (int j2 = 0; j2 < 4; j2++) {
                    asm volatile(
                        "mma.sync.aligned.m16n8k16.row.col.f32.f16.f16.f32 "
                        "{%0,%1,%2,%3}, {%4,%5,%6,%7}, {%8,%9}, {%0,%1,%2,%3};"
                        : "+f"(acc[i][2*j2][0]), "+f"(acc[i][2*j2][1]),
                          "+f"(acc[i][2*j2][2]), "+f"(acc[i][2*j2][3])
                        : "r"(a[i][0]), "r"(a[i][1]), "r"(a[i][2]), "r"(a[i][3]),
                          "r"(b[j2][0]), "r"(b[j2][1]));
                    asm volatile(
                        "mma.sync.aligned.m16n8k16.row.col.f32.f16.f16.f32 "
                        "{%0,%1,%2,%3}, {%4,%5,%6,%7}, {%8,%9}, {%0,%1,%2,%3};"
                        : "+f"(acc[i][2*j2+1][0]), "+f"(acc[i][2*j2+1][1]),
                          "+f"(acc[i][2*j2+1][2]), "+f"(acc[i][2*j2+1][3])
                        : "r"(a[i][0]), "r"(a[i][1]), "r"(a[i][2]), "r"(a[i][3]),
                          "r"(b[j2][2]), "r"(b[j2][3]));
                }
        }
        __syncthreads();
    }
    asm volatile("cp.async.wait_group 0;" ::: "memory");

#pragma unroll
    for (int j = 0; j < 8; j++) {
        int ncol = n0 + wn * 64 + j * 8 + (lane & 3) * 2;
        float b0 = fcb[ncol], b1 = fcb[ncol + 1];
#pragma unroll
        for (int i = 0; i < 4; i++) {
            int mrow = m0 + wm * 64 + i * 16 + (lane >> 2);
            float2 v0 = {acc[i][j][0] + b0, acc[i][j][1] + b1};
            float2 v1 = {acc[i][j][2] + b0, acc[i][j][3] + b1};
            *(float2*)(C + (size_t)mrow * VOC + ncol) = v0;
            *(float2*)(C + (size_t)(mrow + 8) * VOC + ncol) = v1;
        }
    }
}

// ---------------------------------------------------------------------------
extern "C" void kernel_launch(void* const* d_in, const int* in_sizes, int n_in,
                              void* d_out, int out_size) {
    const int*   decX = (const int*)d_in[0];
    const float* enc  = (const float*)d_in[1];
    const float* h0   = (const float*)d_in[2];
    const float* c0   = (const float*)d_in[3];
    const float* embW = (const float*)d_in[4];
    const float* Wih  = (const float*)d_in[5];
    const float* Whh  = (const float*)d_in[6];
    const float* bih  = (const float*)d_in[7];
    const float* bhh  = (const float*)d_in[8];
    const float* attW = (const float*)d_in[9];
    const float* attb = (const float*)d_in[10];
    const float* fcW  = (const float*)d_in[11];
    const float* fcb  = (const float*)d_in[12];
    float* out = (float*)d_out;

    __half *p_Wihh, *p_attWh, *p_embh, *p_cath;
    float *p_bias;
    cudaGetSymbolAddress((void**)&p_Wihh,  g_Wihh);
    cudaGetSymbolAddress((void**)&p_attWh, g_attWh);
    cudaGetSymbolAddress((void**)&p_embh,  g_embh);
    cudaGetSymbolAddress((void**)&p_cath,  g_cath);
    cudaGetSymbolAddress((void**)&p_bias,  g_bias);

    cudaFuncSetAttribute(k_hgemm,  cudaFuncAttributeMaxDynamicSharedMemorySize, SM_TOTAL);
    cudaFuncSetAttribute(k_hgemm2, cudaFuncAttributeMaxDynamicSharedMemorySize, SM_TOTAL);
    cudaFuncSetAttribute(k_lstm_p, cudaFuncAttributeMaxDynamicSharedMemorySize, STEP_SMEM);

    // One fused init launch: all conversions + bias + h0 + embed + bar reset
    k_init<<<NB_INIT, 256>>>(fcW, Wih, attW, Whh, bih, bhh, h0, decX, embW);
    // x_ih (+bias) via HMMA, permuted store
    k_hgemm2<<<dim3(M_BT / BM, G4 / BN), 256, SM_TOTAL>>>(p_embh, p_Wihh, p_bias,
                                                          EDIM, EDIM / BK, 0);
    // Persistent fused HMMA LSTM (writes tail output too)
    k_lstm_p<<<LCTA, 256, STEP_SMEM>>>(c0, out);

    k_attn<<<256, 256>>>(enc);
    k_hgemm2<<<dim3(M_BT / BM, HDIM / BN), 256, SM_TOTAL>>>(p_cath, p_attWh, attb,
                                                            2 * HDIM, 2 * HDIM / BK, 1);
    k_hgemm<<<dim3(M_BT / BM, VOC / BN), 256, SM_TOTAL>>>(fcb, out);
}

// round 11
// speedup vs baseline: 2.6585x; 1.0746x over previous
#include <cuda_runtime.h>
#include <cuda_fp16.h>
#include <math.h>
#include <stdint.h>

// Problem constants
#define BSZ   32
#define TD    64
#define TEC   128
#define EDIM  256
#define HDIM  512
#define G4    2048
#define VOC   32000
#define M_BT  2048

// HMMA GEMM tiling
#define BM    256
#define BN    128
#define BK    64
#define KDIM  512
#define KI    (KDIM / BK)
#define ROWB  144
#define SA_BYTES (BM * ROWB)
#define SB_BYTES (BN * ROWB)
#define STAGE    (SA_BYTES + SB_BYTES)
#define NSTAGE   3
#define SM_TOTAL (NSTAGE * STAGE)

// Persistent LSTM kernel
#define LCTA  64
#define SAROW 1040
#define SMH   (32 * SAROW)
#define SMG   (SMH + 32 * SAROW)
#define STEP_SMEM (SMG + 2 * 32 * 33 * 4)

// HMMA attention kernel: 64 CTAs = (b, t-half of 32)
#define AT_ENC 0                         // 128 x SAROW fp16 enc tile
#define AT_H   (128 * SAROW)             // 133120: 32 x SAROW fp16 h
#define AT_SC  (AT_H + 32 * SAROW)       // 166400: 32 x 132 fp32 scores
#define AT_P   (AT_SC + 32 * 132 * 4)    // 183296: 32 x 136 fp16 P
#define ATN_SMEM (AT_P + 32 * 136 * 2)   // 192000

// Init kernel grid sections (256 threads each)
#define NB_FC   16000
#define NB_WIH  512
#define NB_ATT  512
#define NB_WHH  1024
#define NB_BIAS 8
#define NB_H0   64
#define NB_ENC  2048      // enc fp32 -> fp16 (32*128*512/1024)
#define NB_EMB  2048
#define NB_INIT (NB_FC + NB_WIH + NB_ATT + NB_WHH + NB_BIAS + NB_H0 + NB_ENC + NB_EMB)

// Scratch
__device__ float g_bias[G4];
__device__ float g_xihp[(size_t)TD * G4 * BSZ];
__device__ float g_c   [BSZ * HDIM];
__device__ unsigned g_bar;
__device__ __align__(16) __half g_hsh[(size_t)TD * BSZ * HDIM];  // h history fp16
__device__ __align__(16) __half g_ench[(size_t)BSZ * TEC * HDIM];
__device__ __align__(16) __half g_embh[M_BT * EDIM];
__device__ __align__(16) __half g_Wihh[(size_t)G4 * EDIM];
__device__ __align__(16) __half g_cath[(size_t)M_BT * 2 * HDIM];
__device__ __align__(16) __half g_attWh[(size_t)HDIM * 2 * HDIM];
__device__ __align__(16) __half g_Whp[(size_t)G4 * HDIM];
__device__ __align__(16) __half g_hf [BSZ * HDIM];
__device__ __align__(16) __half g_Ah[(size_t)M_BT * KDIM];
__device__ __align__(16) __half g_Bh[(size_t)VOC * KDIM];

__device__ __forceinline__ float sigf(float x) { return 1.0f / (1.0f + expf(-x)); }

__device__ __forceinline__ uint32_t smem_u32(const void* p) {
    uint32_t a;
    asm("{ .reg .u64 t; cvta.to.shared.u64 t, %1; cvt.u32.u64 %0, t; }" : "=r"(a) : "l"(p));
    return a;
}

__device__ __forceinline__ void cvt4(const float* src, __half* dst) {
    float4 x = *(const float4*)src;
    __half h[4] = {__float2half(x.x), __float2half(x.y),
                   __float2half(x.z), __float2half(x.w)};
    *(uint2*)dst = *(uint2*)h;
}

// ---------------------------------------------------------------------------
// ONE fused init kernel
__global__ void k_init(const float* __restrict__ fcW, const float* __restrict__ Wih,
                       const float* __restrict__ attW, const float* __restrict__ Whh,
                       const float* __restrict__ bih, const float* __restrict__ bhh,
                       const float* __restrict__ h0, const int* __restrict__ decX,
                       const float* __restrict__ embW, const float* __restrict__ enc) {
    int blk = blockIdx.x, tid = threadIdx.x;
    if (blk < NB_FC) {
        size_t i4 = (size_t)blk * 256 + tid;
        cvt4(fcW + i4 * 4, g_Bh + i4 * 4);
        return;
    }
    blk -= NB_FC;
    if (blk < NB_WIH) {
        size_t i4 = (size_t)blk * 256 + tid;
        cvt4(Wih + i4 * 4, g_Wihh + i4 * 4);
        return;
    }
    blk -= NB_WIH;
    if (blk < NB_ATT) {
        size_t i4 = (size_t)blk * 256 + tid;
        cvt4(attW + i4 * 4, g_attWh + i4 * 4);
        return;
    }
    blk -= NB_ATT;
    if (blk < NB_WHH) {
        size_t i4 = (size_t)blk * 256 + tid;
        size_t e = i4 * 4;
        int rp = (int)(e >> 9), k = (int)(e & 511);
        int u = rp >> 2, g = rp & 3;
        cvt4(Whh + (size_t)(g * HDIM + u) * HDIM + k, g_Whp + (size_t)rp * HDIM + k);
        return;
    }
    blk -= NB_WHH;
    if (blk < NB_BIAS) {
        int i = blk * 256 + tid;
        g_bias[i] = bih[i] + bhh[i];
        if (i == 0) g_bar = 0u;
        return;
    }
    blk -= NB_BIAS;
    if (blk < NB_H0) {
        int i = blk * 256 + tid;
        g_hf[i] = __float2half(h0[i]);
        return;
    }
    blk -= NB_H0;
    if (blk < NB_ENC) {
        size_t i4 = (size_t)blk * 256 + tid;
        cvt4(enc + i4 * 4, g_ench + i4 * 4);
        return;
    }
    blk -= NB_ENC;
    {
        int m = blk, e = tid;
        int b = m & (BSZ - 1), t = m >> 5;
        int tok = decX[b * TD + t];
        g_embh[m * EDIM + e] = __float2half(embW[tok * EDIM + e]);
    }
}

// ---------------------------------------------------------------------------
// Generalized fp16 HMMA GEMM (unchanged)
__global__ __launch_bounds__(256, 1)
void k_hgemm2(const __half* __restrict__ A, const __half* __restrict__ B,
              const float* __restrict__ bias, int K, int nI, int mode) {
    extern __shared__ char smem[];
    uint32_t sb = smem_u32(smem);
    int tid = threadIdx.x;
    int wid = tid >> 5, lane = tid & 31;
    int wm = wid & 3, wn = wid >> 2;
    int m0 = blockIdx.x * BM, n0 = blockIdx.y * BN;

    const __half* gA0 = A + (size_t)m0 * K;
    const __half* gB0 = B + (size_t)n0 * K;

    auto load_stage = [&](int kt, int s) {
        uint32_t sa = sb + s * STAGE;
        const __half* gA = gA0 + kt * BK;
#pragma unroll
        for (int r8 = 0; r8 < 8; r8++) {
            int li = r8 * 256 + tid;
            int row = li >> 3, seg = li & 7;
            uint32_t dst = sa + row * ROWB + seg * 16;
            const void* src = gA + (size_t)row * K + seg * 8;
            asm volatile("cp.async.cg.shared.global [%0], [%1], 16;" :: "r"(dst), "l"(src));
        }
        uint32_t sbB = sa + SA_BYTES;
        const __half* gB = gB0 + kt * BK;
#pragma unroll
        for (int r4 = 0; r4 < 4; r4++) {
            int li = r4 * 256 + tid;
            int row = li >> 3, seg = li & 7;
            uint32_t dst = sbB + row * ROWB + seg * 16;
            const void* src = gB + (size_t)row * K + seg * 8;
            asm volatile("cp.async.cg.shared.global [%0], [%1], 16;" :: "r"(dst), "l"(src));
        }
        asm volatile("cp.async.commit_group;" ::: "memory");
    };

    float acc[4][8][4];
#pragma unroll
    for (int i = 0; i < 4; i++)
#pragma unroll
        for (int j = 0; j < 8; j++)
#pragma unroll
            for (int q = 0; q < 4; q++) acc[i][j][q] = 0.0f;

    load_stage(0, 0);
    load_stage(1, 1);

    for (int kt = 0; kt < nI; kt++) {
        asm volatile("cp.async.wait_group 1;" ::: "memory");
        __syncthreads();
        int s = kt % NSTAGE;
        if (kt + 2 < nI) load_stage(kt + 2, (kt + 2) % NSTAGE);

        uint32_t sa = sb + s * STAGE;
        uint32_t sB = sa + SA_BYTES;
#pragma unroll
        for (int kk = 0; kk < 4; kk++) {
            uint32_t a[4][4], b[4][4];
#pragma unroll
            for (int i = 0; i < 4; i++) {
                int row = wm * 64 + i * 16 + (lane & 15);
                int ko = kk * 16 + ((lane >> 4) << 3);
                uint32_t ad = sa + row * ROWB + ko * 2;
                asm volatile("ldmatrix.sync.aligned.m8n8.x4.shared.b16 {%0,%1,%2,%3}, [%4];"
                             : "=r"(a[i][0]), "=r"(a[i][1]), "=r"(a[i][2]), "=r"(a[i][3])
                             : "r"(ad));
            }
#pragma unroll
            for (int j2 = 0; j2 < 4; j2++) {
                int nrow = wn * 64 + j2 * 16 + (lane & 7) + (((lane >> 4) & 1) << 3);
                int ko = kk * 16 + (((lane >> 3) & 1) << 3);
                uint32_t bd = sB + nrow * ROWB + ko * 2;
                asm volatile("ldmatrix.sync.aligned.m8n8.x4.shared.b16 {%0,%1,%2,%3}, [%4];"
                             : "=r"(b[j2][0]), "=r"(b[j2][1]), "=r"(b[j2][2]), "=r"(b[j2][3])
                             : "r"(bd));
            }
#pragma unroll
            for (int i = 0; i < 4; i++)
#pragma unroll
                for (int j2 = 0; j2 < 4; j2++) {
                    asm volatile(
                        "mma.sync.aligned.m16n8k16.row.col.f32.f16.f16.f32 "
                        "{%0,%1,%2,%3}, {%4,%5,%6,%7}, {%8,%9}, {%0,%1,%2,%3};"
                        : "+f"(acc[i][2*j2][0]), "+f"(acc[i][2*j2][1]),
                          "+f"(acc[i][2*j2][2]), "+f"(acc[i][2*j2][3])
                        : "r"(a[i][0]), "r"(a[i][1]), "r"(a[i][2]), "r"(a[i][3]),
                          "r"(b[j2][0]), "r"(b[j2][1]));
                    asm volatile(
                        "mma.sync.aligned.m16n8k16.row.col.f32.f16.f16.f32 "
                        "{%0,%1,%2,%3}, {%4,%5,%6,%7}, {%8,%9}, {%0,%1,%2,%3};"
                        : "+f"(acc[i][2*j2+1][0]), "+f"(acc[i][2*j2+1][1]),
                          "+f"(acc[i][2*j2+1][2]), "+f"(acc[i][2*j2+1][3])
                        : "r"(a[i][0]), "r"(a[i][1]), "r"(a[i][2]), "r"(a[i][3]),
                          "r"(b[j2][2]), "r"(b[j2][3]));
                }
        }
        __syncthreads();
    }
    asm volatile("cp.async.wait_group 0;" ::: "memory");

#pragma unroll
    for (int j = 0; j < 8; j++) {
        int ncol = n0 + wn * 64 + j * 8 + (lane & 3) * 2;
        float b0 = bias[ncol], b1 = bias[ncol + 1];
#pragma unroll
        for (int i = 0; i < 4; i++) {
            int mr0 = m0 + wm * 64 + i * 16 + (lane >> 2);
#pragma unroll
            for (int h = 0; h < 2; h++) {
                int mrow = mr0 + h * 8;
                float v0 = acc[i][j][2*h + 0] + b0;
                float v1 = acc[i][j][2*h + 1] + b1;
                if (mode == 0) {
                    int tt = mrow >> 5, bb2 = mrow & 31;
                    int rp0 = ((ncol & 511) << 2) | (ncol >> 9);
                    int rp1 = (((ncol + 1) & 511) << 2) | ((ncol + 1) >> 9);
                    g_xihp[((size_t)tt * G4 + rp0) * 32 + bb2] = v0;
                    g_xihp[((size_t)tt * G4 + rp1) * 32 + bb2] = v1;
                } else {
                    __half2 hv = __floats2half2_rn(tanhf(v0), tanhf(v1));
                    *(__half2*)(g_Ah + (size_t)mrow * KDIM + ncol) = hv;
                }
            }
        }
    }
}

// ---------------------------------------------------------------------------
// Persistent fused LSTM (R10 version; h history now stored fp16)
__global__ __launch_bounds__(256, 1)
void k_lstm_p(const float* __restrict__ c0, float* __restrict__ out) {
    extern __shared__ char sm[];
    uint32_t sb = smem_u32(sm);
    int tid = threadIdx.x, w = tid >> 5, lane = tid & 31;
    int jt = blockIdx.x;

    const __half* Wp = g_Whp + (size_t)(jt * 32) * HDIM;
#pragma unroll
    for (int p = 0; p < 8; p++) {
        int idx = p * 256 + tid;
        int row = idx >> 6, seg = idx & 63;
        uint32_t dst = sb + row * SAROW + seg * 16;
        const void* src = Wp + row * HDIM + seg * 8;
        asm volatile("cp.async.cg.shared.global [%0], [%1], 16;" :: "r"(dst), "l"(src));
    }
    asm volatile("cp.async.commit_group;" ::: "memory");

    int b = tid & 31, ul = tid >> 5;
    int u = jt * 8 + ul;
    float creg = c0[b * HDIM + u];
    float hlast = 0.0f;

    float* gS0 = (float*)(sm + SMG);
    float* gS1 = gS0 + 32 * 33;
    int wg = w >> 2, wq = w & 3;
    int wm = wq >> 1, wn = wq & 1;

    for (int t = 0; t < TD; t++) {
        const float* xp = g_xihp + ((size_t)t * G4 + u * 4) * 32 + b;
        float x0 = xp[0], x1 = xp[32], x2 = xp[64], x3 = xp[96];

#pragma unroll
        for (int p = 0; p < 8; p++) {
            int idx = p * 256 + tid;
            int row = idx >> 6, seg = idx & 63;
            uint32_t dst = sb + SMH + row * SAROW + seg * 16;
            const void* src = g_hf + row * HDIM + seg * 8;
            asm volatile("cp.async.cg.shared.global [%0], [%1], 16;" :: "r"(dst), "l"(src));
        }
        asm volatile("cp.async.commit_group;" ::: "memory");
        asm volatile("cp.async.wait_group 0;" ::: "memory");
        __syncthreads();

        float acc[2][4] = {};
#pragma unroll
        for (int kk2 = 0; kk2 < 16; kk2++) {
            int kk = wg * 16 + kk2;
            uint32_t a[4], bb[4];
            {
                int row = wm * 16 + (lane & 15);
                int ko = kk * 16 + ((lane >> 4) << 3);
                uint32_t ad = sb + row * SAROW + ko * 2;
                asm volatile("ldmatrix.sync.aligned.m8n8.x4.shared.b16 {%0,%1,%2,%3}, [%4];"
                             : "=r"(a[0]), "=r"(a[1]), "=r"(a[2]), "=r"(a[3]) : "r"(ad));
            }
            {
                int nrow = wn * 16 + (lane & 7) + (((lane >> 4) & 1) << 3);
                int ko = kk * 16 + (((lane >> 3) & 1) << 3);
                uint32_t bd = sb + SMH + nrow * SAROW + ko * 2;
                asm volatile("ldmatrix.sync.aligned.m8n8.x4.shared.b16 {%0,%1,%2,%3}, [%4];"
                             : "=r"(bb[0]), "=r"(bb[1]), "=r"(bb[2]), "=r"(bb[3]) : "r"(bd));
            }
#pragma unroll
            for (int s = 0; s < 2; s++) {
                asm volatile(
                    "mma.sync.aligned.m16n8k16.row.col.f32.f16.f16.f32 "
                    "{%0,%1,%2,%3}, {%4,%5,%6,%7}, {%8,%9}, {%0,%1,%2,%3};"
                    : "+f"(acc[s][0]), "+f"(acc[s][1]), "+f"(acc[s][2]), "+f"(acc[s][3])
                    : "r"(a[0]), "r"(a[1]), "r"(a[2]), "r"(a[3]),
                      "r"(bb[2*s]), "r"(bb[2*s+1]));
            }
        }
        {
            float* gD = wg ? gS1 : gS0;
            int r0 = wm * 16 + (lane >> 2);
#pragma unroll
            for (int s = 0; s < 2; s++) {
                int c0i = wn * 16 + s * 8 + 2 * (lane & 3);
                gD[r0 * 33 + c0i]           = acc[s][0];
                gD[r0 * 33 + c0i + 1]       = acc[s][1];
                gD[(r0 + 8) * 33 + c0i]     = acc[s][2];
                gD[(r0 + 8) * 33 + c0i + 1] = acc[s][3];
            }
        }
        __syncthreads();

        {
            float gi = gS0[(4 * ul + 0) * 33 + b] + gS1[(4 * ul + 0) * 33 + b] + x0;
            float gf = gS0[(4 * ul + 1) * 33 + b] + gS1[(4 * ul + 1) * 33 + b] + x1;
            float gg = gS0[(4 * ul + 2) * 33 + b] + gS1[(4 * ul + 2) * 33 + b] + x2;
            float go = gS0[(4 * ul + 3) * 33 + b] + gS1[(4 * ul + 3) * 33 + b] + x3;
            float c = sigf(gf) * creg + sigf(gi) * tanhf(gg);
            creg = c;
            float hh = sigf(go) * tanhf(c);
            hlast = hh;
            __half hv = __float2half(hh);
            g_hsh[((size_t)t * BSZ + b) * HDIM + u] = hv;
            g_hf[b * HDIM + u] = hv;
        }

        __threadfence();
        __syncthreads();
        if (tid == 0) {
            atomicAdd(&g_bar, 1u);
            unsigned target = (unsigned)(t + 1) * LCTA;
            volatile unsigned* vb = &g_bar;
            while (*vb < target) { }
        }
        __syncthreads();
    }

    g_c[b * HDIM + u] = creg;
    out[(size_t)M_BT * VOC + b * HDIM + u] = hlast;
    out[(size_t)M_BT * VOC + BSZ * HDIM + b * HDIM + u] = creg;
}

// ---------------------------------------------------------------------------
// HMMA attention: CTA = (b, t-half). scores MMA -> softmax -> ctx MMA (trans B).
__global__ __launch_bounds__(256, 1)
void k_attn2() {
    extern __shared__ char sm[];
    uint32_t sb = smem_u32(sm);
    int tid = threadIdx.x, wid = tid >> 5, lane = tid & 31;
    int bi = blockIdx.x;
    int b = bi >> 1, t0 = (bi & 1) * 32;

    // Stage enc[b] (128 x 512 fp16) + h (32 rows) into smem
    const __half* encp = g_ench + (size_t)b * TEC * HDIM;
#pragma unroll
    for (int p = 0; p < 32; p++) {
        int idx = p * 256 + tid;
        int row = idx >> 6, seg = idx & 63;
        uint32_t dst = sb + AT_ENC + row * SAROW + seg * 16;
        const void* src = encp + (size_t)row * HDIM + seg * 8;
        asm volatile("cp.async.cg.shared.global [%0], [%1], 16;" :: "r"(dst), "l"(src));
    }
#pragma unroll
    for (int p = 0; p < 8; p++) {
        int idx = p * 256 + tid;
        int row = idx >> 6, seg = idx & 63;
        uint32_t dst = sb + AT_H + row * SAROW + seg * 16;
        const void* src = g_hsh + ((size_t)(t0 + row) * BSZ + b) * HDIM + seg * 8;
        asm volatile("cp.async.cg.shared.global [%0], [%1], 16;" :: "r"(dst), "l"(src));
    }
    asm volatile("cp.async.commit_group;" ::: "memory");
    asm volatile("cp.async.wait_group 0;" ::: "memory");
    __syncthreads();

    int wm2 = wid >> 2, wn2 = wid & 3;     // 2 m-tiles x 4 n-tiles

    // ---- scores MMA: [32 t] x [128 te], K=512 ----
    float sacc[2][2][4] = {};
#pragma unroll
    for (int kk = 0; kk < 32; kk++) {
        uint32_t a[4];
        {
            int row = wm2 * 16 + (lane & 15);
            int ko = kk * 16 + ((lane >> 4) << 3);
            uint32_t ad = sb + AT_H + row * SAROW + ko * 2;
            asm volatile("ldmatrix.sync.aligned.m8n8.x4.shared.b16 {%0,%1,%2,%3}, [%4];"
                         : "=r"(a[0]), "=r"(a[1]), "=r"(a[2]), "=r"(a[3]) : "r"(ad));
        }
#pragma unroll
        for (int j2 = 0; j2 < 2; j2++) {
            uint32_t bb[4];
            int nrow = wn2 * 32 + j2 * 16 + (lane & 7) + (((lane >> 4) & 1) << 3);
            int ko = kk * 16 + (((lane >> 3) & 1) << 3);
            uint32_t bd = sb + AT_ENC + nrow * SAROW + ko * 2;
            asm volatile("ldmatrix.sync.aligned.m8n8.x4.shared.b16 {%0,%1,%2,%3}, [%4];"
                         : "=r"(bb[0]), "=r"(bb[1]), "=r"(bb[2]), "=r"(bb[3]) : "r"(bd));
#pragma unroll
            for (int s = 0; s < 2; s++) {
                asm volatile(
                    "mma.sync.aligned.m16n8k16.row.col.f32.f16.f16.f32 "
                    "{%0,%1,%2,%3}, {%4,%5,%6,%7}, {%8,%9}, {%0,%1,%2,%3};"
                    : "+f"(sacc[j2][s][0]), "+f"(sacc[j2][s][1]),
                      "+f"(sacc[j2][s][2]), "+f"(sacc[j2][s][3])
                    : "r"(a[0]), "r"(a[1]), "r"(a[2]), "r"(a[3]),
                      "r"(bb[2*s]), "r"(bb[2*s+1]));
            }
        }
    }
    // scatter scores to smem fp32
    float* sc = (float*)(sm + AT_SC);
    {
        int r0 = wm2 * 16 + (lane >> 2);
#pragma unroll
        for (int j2 = 0; j2 < 2; j2++)
#pragma unroll
            for (int nb = 0; nb < 2; nb++) {
                int c0i = wn2 * 32 + j2 * 16 + nb * 8 + 2 * (lane & 3);
                sc[r0 * 132 + c0i]           = sacc[j2][nb][0];
                sc[r0 * 132 + c0i + 1]       = sacc[j2][nb][1];
                sc[(r0 + 8) * 132 + c0i]     = sacc[j2][nb][2];
                sc[(r0 + 8) * 132 + c0i + 1] = sacc[j2][nb][3];
            }
    }
    __syncthreads();

    // ---- softmax (fp32), write P fp16 ----
    __half* Pp = (__half*)(sm + AT_P);
#pragma unroll
    for (int r = 0; r < 4; r++) {
        int row = wid * 4 + r;
        float sv[4], mx = -1e30f;
#pragma unroll
        for (int q = 0; q < 4; q++) { sv[q] = sc[row * 132 + lane + 32 * q]; mx = fmaxf(mx, sv[q]); }
#pragma unroll
        for (int off = 16; off; off >>= 1) mx = fmaxf(mx, __shfl_xor_sync(0xffffffffu, mx, off));
        float sum = 0.0f;
#pragma unroll
        for (int q = 0; q < 4; q++) { sv[q] = expf(sv[q] - mx); sum += sv[q]; }
#pragma unroll
        for (int off = 16; off; off >>= 1) sum += __shfl_xor_sync(0xffffffffu, sum, off);
        float inv = 1.0f / sum;
#pragma unroll
        for (int q = 0; q < 4; q++)
            Pp[row * 136 + lane + 32 * q] = __float2half(sv[q] * inv);
    }
    __syncthreads();

    // ---- ctx MMA: [32 t] x [512 j], K=128 te. B = enc (trans frags) ----
    float cacc[8][2][4];
#pragma unroll
    for (int j2 = 0; j2 < 8; j2++)
#pragma unroll
        for (int nb = 0; nb < 2; nb++)
#pragma unroll
            for (int q = 0; q < 4; q++) cacc[j2][nb][q] = 0.0f;

#pragma unroll
    for (int kk = 0; kk < 8; kk++) {
        uint32_t a[4];
        {
            int row = wm2 * 16 + (lane & 15);
            int ko = kk * 16 + ((lane >> 4) << 3);
            uint32_t ad = sb + AT_P + row * 272 + ko * 2;
            asm volatile("ldmatrix.sync.aligned.m8n8.x4.shared.b16 {%0,%1,%2,%3}, [%4];"
                         : "=r"(a[0]), "=r"(a[1]), "=r"(a[2]), "=r"(a[3]) : "r"(ad));
        }
#pragma unroll
        for (int j2 = 0; j2 < 8; j2++) {
            uint32_t bb[4];
            int j0 = wn2 * 128 + j2 * 16;
            int te = kk * 16 + (((lane >> 3) & 1) << 3) + (lane & 7);
            int jc = j0 + (((lane >> 4) & 1) << 3);
            uint32_t bd = sb + AT_ENC + te * SAROW + jc * 2;
            asm volatile("ldmatrix.sync.aligned.m8n8.x4.trans.shared.b16 {%0,%1,%2,%3}, [%4];"
                         : "=r"(bb[0]), "=r"(bb[1]), "=r"(bb[2]), "=r"(bb[3]) : "r"(bd));
#pragma unroll
            for (int s = 0; s < 2; s++) {
                asm volatile(
                    "mma.sync.aligned.m16n8k16.row.col.f32.f16.f16.f32 "
                    "{%0,%1,%2,%3}, {%4,%5,%6,%7}, {%8,%9}, {%0,%1,%2,%3};"
                    : "+f"(cacc[j2][s][0]), "+f"(cacc[j2][s][1]),
                      "+f"(cacc[j2][s][2]), "+f"(cacc[j2][s][3])
                    : "r"(a[0]), "r"(a[1]), "r"(a[2]), "r"(a[3]),
                      "r"(bb[2*s]), "r"(bb[2*s+1]));
            }
        }
    }

    // ---- epilogue: cat = [h ; ctx] fp16, row m = b*TD + t ----
    {
        int r0 = wm2 * 16 + (lane >> 2);
#pragma unroll
        for (int j2 = 0; j2 < 8; j2++)
#pragma unroll
            for (int nb = 0; nb < 2; nb++) {
                int c0i = wn2 * 128 + j2 * 16 + nb * 8 + 2 * (lane & 3);
                int m = b * TD + t0 + r0;
                *(__half2*)(g_cath + (size_t)m * (2 * HDIM) + HDIM + c0i) =
                    __floats2half2_rn(cacc[j2][nb][0], cacc[j2][nb][1]);
                *(__half2*)(g_cath + (size_t)(m + 8) * (2 * HDIM) + HDIM + c0i) =
                    __floats2half2_rn(cacc[j2][nb][2], cacc[j2][nb][3]);
            }
    }
    // h half of cat: copy from smem
#pragma unroll
    for (int p = 0; p < 8; p++) {
        int idx = p * 256 + tid;
        int row = idx >> 6, seg = idx & 63;
        uint4 v = *(uint4*)(sm + AT_H + row * SAROW + seg * 16);
        int m = b * TD + t0 + row;
        *(uint4*)(g_cath + (size_t)m * (2 * HDIM) + seg * 8) = v;
    }
}

// ---------------------------------------------------------------------------
// HMMA fc GEMM (unchanged)
__global__ __launch_bounds__(256, 1)
void k_hgemm(const float* __restrict__ fcb, float* __restrict__ C) {
    extern __shared__ char smem[];
    uint32_t sb = smem_u32(smem);
    int tid = threadIdx.x;
    int wid = tid >> 5, lane = tid & 31;
    int wm = wid & 3, wn = wid >> 2;
    int m0 = blockIdx.x * BM, n0 = blockIdx.y * BN;

    const __half* gA0 = g_Ah + (size_t)m0 * KDIM;
    const __half* gB0 = g_Bh + (size_t)n0 * KDIM;

    auto load_stage = [&](int kt, int s) {
        uint32_t sa = sb + s * STAGE;
        const __half* gA = gA0 + kt * BK;
#pragma unroll
        for (int r8 = 0; r8 < 8; r8++) {
            int li = r8 * 256 + tid;
            int row = li >> 3, seg = li & 7;
            uint32_t dst = sa + row * ROWB + seg * 16;
            const void* src = gA + (size_t)row * KDIM + seg * 8;
            asm volatile("cp.async.cg.shared.global [%0], [%1], 16;" :: "r"(dst), "l"(src));
        }
        uint32_t sbB = sa + SA_BYTES;
        const __half* gB = gB0 + kt * BK;
#pragma unroll
        for (int r4 = 0; r4 < 4; r4++) {
            int li = r4 * 256 + tid;
            int row = li >> 3, seg = li & 7;
            uint32_t dst = sbB + row * ROWB + seg * 16;
            const void* src = gB + (size_t)row * KDIM + seg * 8;
            asm volatile("cp.async.cg.shared.global [%0], [%1], 16;" :: "r"(dst), "l"(src));
        }
        asm volatile("cp.async.commit_group;" ::: "memory");
    };

    float acc[4][8][4];
#pragma unroll
    for (int i = 0; i < 4; i++)
#pragma unroll
        for (int j = 0; j < 8; j++)
#pragma unroll
            for (int q = 0; q < 4; q++) acc[i][j][q] = 0.0f;

    load_stage(0, 0);
    load_stage(1, 1);

    for (int kt = 0; kt < KI; kt++) {
        asm volatile("cp.async.wait_group 1;" ::: "memory");
        __syncthreads();
        int s = kt % NSTAGE;
        if (kt + 2 < KI) load_stage(kt + 2, (kt + 2) % NSTAGE);

        uint32_t sa = sb + s * STAGE;
        uint32_t sB = sa + SA_BYTES;
#pragma unroll
        for (int kk = 0; kk < 4; kk++) {
            uint32_t a[4][4], b[4][4];
#pragma unroll
            for (int i = 0; i < 4; i++) {
                int row = wm * 64 + i * 16 + (lane & 15);
                int ko = kk * 16 + ((lane >> 4) << 3);
                uint32_t ad = sa + row * ROWB + ko * 2;
                asm volatile("ldmatrix.sync.aligned.m8n8.x4.shared.b16 {%0,%1,%2,%3}, [%4];"
                             : "=r"(a[i][0]), "=r"(a[i][1]), "=r"(a[i][2]), "=r"(a[i][3])
                             : "r"(ad));
            }
#pragma unroll
            for (int j2 = 0; j2 < 4; j2++) {
                int nrow = wn * 64 + j2 * 16 + (lane & 7) + (((lane >> 4) & 1) << 3);
                int ko = kk * 16 + (((lane >> 3) & 1) << 3);
                uint32_t bd = sB + nrow * ROWB + ko * 2;
                asm volatile("ldmatrix.sync.aligned.m8n8.x4.shared.b16 {%0,%1,%2,%3}, [%4];"
                             : "=r"(b[j2][0]), "=r"(b[j2][1]), "=r"(b[j2][2]), "=r"(b[j2][3])
                             : "r"(bd));
            }
#pragma unroll
            for (int i = 0; i < 4; i++)
#pragma unroll
                for (int j2 = 0; j2 < 4; j2++) {
                    asm volatile(
                        "mma.sync.aligned.m16n8k16.row.col.f32.f16.f16.f32 "
                        "{%0,%1,%2,%3}, {%4,%5,%6,%7}, {%8,%9}, {%0,%1,%2,%3};"
                        : "+f"(acc[i][2*j2][0]), "+f"(acc[i][2*j2][1]),
                          "+f"(acc[i][2*j2][2]), "+f"(acc[i][2*j2][3])
                        : "r"(a[i][0]), "r"(a[i][1]), "r"(a[i][2]), "r"(a[i][3]),
                          "r"(b[j2][0]), "r"(b[j2][1]));
                    asm volatile(
                        "mma.sync.aligned.m16n8k16.row.col.f32.f16.f16.f32 "
                        "{%0,%1,%2,%3}, {%4,%5,%6,%7}, {%8,%9}, {%0,%1,%2,%3};"
                        : "+f"(acc[i][2*j2+1][0]), "+f"(acc[i][2*j2+1][1]),
                          "+f"(acc[i][2*j2+1][2]), "+f"(acc[i][2*j2+1][3])
                        : "r"(a[i][0]), "r"(a[i][1]), "r"(a[i][2]), "r"(a[i][3]),
                          "r"(b[j2][2]), "r"(b[j2][3]));
                }
        }
        __syncthreads();
    }
    asm volatile("cp.async.wait_group 0;" ::: "memory");

#pragma unroll
    for (int j = 0; j < 8; j++) {
        int ncol = n0 + wn * 64 + j * 8 + (lane & 3) * 2;
        float b0 = fcb[ncol], b1 = fcb[ncol + 1];
#pragma unroll
        for (int i = 0; i < 4; i++) {
            int mrow = m0 + wm * 64 + i * 16 + (lane >> 2);
            float2 v0 = {acc[i][j][0] + b0, acc[i][j][1] + b1};
            float2 v1 = {acc[i][j][2] + b0, acc[i][j][3] + b1};
            *(float2*)(C + (size_t)mrow * VOC + ncol) = v0;
            *(float2*)(C + (size_t)(mrow + 8) * VOC + ncol) = v1;
        }
    }
}

// ---------------------------------------------------------------------------
extern "C" void kernel_launch(void* const* d_in, const int* in_sizes, int n_in,
                              void* d_out, int out_size) {
    const int*   decX = (const int*)d_in[0];
    const float* enc  = (const float*)d_in[1];
    const float* h0   = (const float*)d_in[2];
    const float* c0   = (const float*)d_in[3];
    const float* embW = (const float*)d_in[4];
    const float* Wih  = (const float*)d_in[5];
    const float* Whh  = (const float*)d_in[6];
    const float* bih  = (const float*)d_in[7];
    const float* bhh  = (const float*)d_in[8];
    const float* attW = (const float*)d_in[9];
    const float* attb = (const float*)d_in[10];
    const float* fcW  = (const float*)d_in[11];
    const float* fcb  = (const float*)d_in[12];
    float* out = (float*)d_out;

    __half *p_Wihh, *p_attWh, *p_embh, *p_cath;
    float *p_bias;
    cudaGetSymbolAddress((void**)&p_Wihh,  g_Wihh);
    cudaGetSymbolAddress((void**)&p_attWh, g_attWh);
    cudaGetSymbolAddress((void**)&p_embh,  g_embh);
    cudaGetSymbolAddress((void**)&p_cath,  g_cath);
    cudaGetSymbolAddress((void**)&p_bias,  g_bias);

    cudaFuncSetAttribute(k_hgemm,  cudaFuncAttributeMaxDynamicSharedMemorySize, SM_TOTAL);
    cudaFuncSetAttribute(k_hgemm2, cudaFuncAttributeMaxDynamicSharedMemorySize, SM_TOTAL);
    cudaFuncSetAttribute(k_lstm_p, cudaFuncAttributeMaxDynamicSharedMemorySize, STEP_SMEM);
    cudaFuncSetAttribute(k_attn2,  cudaFuncAttributeMaxDynamicSharedMemorySize, ATN_SMEM);

    k_init<<<NB_INIT, 256>>>(fcW, Wih, attW, Whh, bih, bhh, h0, decX, embW, enc);
    k_hgemm2<<<dim3(M_BT / BM, G4 / BN), 256, SM_TOTAL>>>(p_embh, p_Wihh, p_bias,
                                                          EDIM, EDIM / BK, 0);
    k_lstm_p<<<LCTA, 256, STEP_SMEM>>>(c0, out);
    k_attn2<<<64, 256, ATN_SMEM>>>();
    k_hgemm2<<<dim3(M_BT / BM, HDIM / BN), 256, SM_TOTAL>>>(p_cath, p_attWh, attb,
                                                            2 * HDIM, 2 * HDIM / BK, 1);
    k_hgemm<<<dim3(M_BT / BM, VOC / BN), 256, SM_TOTAL>>>(fcb, out);
}

// round 12
// speedup vs baseline: 2.8307x; 1.0648x over previous
#include <cuda_runtime.h>
#include <cuda_fp16.h>
#include <math.h>
#include <stdint.h>

// Problem constants
#define BSZ   32
#define TD    64
#define TEC   128
#define EDIM  256
#define HDIM  512
#define G4    2048
#define VOC   32000
#define M_BT  2048

// HMMA GEMM tiling
#define BM    256
#define BN    128
#define BK    64
#define KDIM  512
#define KI    (KDIM / BK)
#define ROWB  144
#define SA_BYTES (BM * ROWB)
#define SB_BYTES (BN * ROWB)
#define STAGE    (SA_BYTES + SB_BYTES)
#define NSTAGE   3
#define SM_TOTAL (NSTAGE * STAGE)

// Persistent LSTM kernel
#define LCTA  64
#define SAROW 1040
#define SMH   (32 * SAROW)
#define SMG   (SMH + 32 * SAROW)
#define STEP_SMEM (SMG + 2 * 32 * 33 * 4)

// HMMA attention kernel
#define AT_ENC 0
#define AT_H   (128 * SAROW)
#define AT_SC  (AT_H + 32 * SAROW)
#define AT_P   (AT_SC + 32 * 132 * 4)
#define ATN_SMEM (AT_P + 32 * 136 * 2)

// Init kernel grid sections (256 threads each)
#define NB_FC   16000
#define NB_WIH  512
#define NB_ATT  512
#define NB_WHH  1024
#define NB_BIAS 8
#define NB_H0   64
#define NB_ENC  2048
#define NB_EMB  2048
#define NB_INIT (NB_FC + NB_WIH + NB_ATT + NB_WHH + NB_BIAS + NB_H0 + NB_ENC + NB_EMB)

// Scratch
__device__ float g_bias[G4];
__device__ float g_xihp[(size_t)TD * G4 * BSZ];
__device__ float g_c   [BSZ * HDIM];
__device__ unsigned g_bar;
// h history, slot-shifted: slot 0 = h0, slot t+1 = h_t.  LSTM reads slot t, writes t+1.
__device__ __align__(16) __half g_hsh[(size_t)(TD + 1) * BSZ * HDIM];
__device__ __align__(16) __half g_ench[(size_t)BSZ * TEC * HDIM];
__device__ __align__(16) __half g_embh[M_BT * EDIM];
__device__ __align__(16) __half g_Wihh[(size_t)G4 * EDIM];
__device__ __align__(16) __half g_cath[(size_t)M_BT * 2 * HDIM];
__device__ __align__(16) __half g_attWh[(size_t)HDIM * 2 * HDIM];
__device__ __align__(16) __half g_Whp[(size_t)G4 * HDIM];
__device__ __align__(16) __half g_Ah[(size_t)M_BT * KDIM];
__device__ __align__(16) __half g_Bh[(size_t)VOC * KDIM];

__device__ __forceinline__ float sigf(float x) { return 1.0f / (1.0f + expf(-x)); }

__device__ __forceinline__ uint32_t smem_u32(const void* p) {
    uint32_t a;
    asm("{ .reg .u64 t; cvta.to.shared.u64 t, %1; cvt.u32.u64 %0, t; }" : "=r"(a) : "l"(p));
    return a;
}

__device__ __forceinline__ void cvt4(const float* src, __half* dst) {
    float4 x = *(const float4*)src;
    __half h[4] = {__float2half(x.x), __float2half(x.y),
                   __float2half(x.z), __float2half(x.w)};
    *(uint2*)dst = *(uint2*)h;
}

// ---------------------------------------------------------------------------
// ONE fused init kernel
__global__ void k_init(const float* __restrict__ fcW, const float* __restrict__ Wih,
                       const float* __restrict__ attW, const float* __restrict__ Whh,
                       const float* __restrict__ bih, const float* __restrict__ bhh,
                       const float* __restrict__ h0, const int* __restrict__ decX,
                       const float* __restrict__ embW, const float* __restrict__ enc) {
    int blk = blockIdx.x, tid = threadIdx.x;
    if (blk < NB_FC) {
        size_t i4 = (size_t)blk * 256 + tid;
        cvt4(fcW + i4 * 4, g_Bh + i4 * 4);
        return;
    }
    blk -= NB_FC;
    if (blk < NB_WIH) {
        size_t i4 = (size_t)blk * 256 + tid;
        cvt4(Wih + i4 * 4, g_Wihh + i4 * 4);
        return;
    }
    blk -= NB_WIH;
    if (blk < NB_ATT) {
        size_t i4 = (size_t)blk * 256 + tid;
        cvt4(attW + i4 * 4, g_attWh + i4 * 4);
        return;
    }
    blk -= NB_ATT;
    if (blk < NB_WHH) {
        size_t i4 = (size_t)blk * 256 + tid;
        size_t e = i4 * 4;
        int rp = (int)(e >> 9), k = (int)(e & 511);
        int u = rp >> 2, g = rp & 3;
        cvt4(Whh + (size_t)(g * HDIM + u) * HDIM + k, g_Whp + (size_t)rp * HDIM + k);
        return;
    }
    blk -= NB_WHH;
    if (blk < NB_BIAS) {
        int i = blk * 256 + tid;
        g_bias[i] = bih[i] + bhh[i];
        if (i == 0) g_bar = 0u;
        return;
    }
    blk -= NB_BIAS;
    if (blk < NB_H0) {                       // h0 -> g_hsh slot 0
        int i = blk * 256 + tid;
        g_hsh[i] = __float2half(h0[i]);
        return;
    }
    blk -= NB_H0;
    if (blk < NB_ENC) {
        size_t i4 = (size_t)blk * 256 + tid;
        cvt4(enc + i4 * 4, g_ench + i4 * 4);
        return;
    }
    blk -= NB_ENC;
    {
        int m = blk, e = tid;
        int b = m & (BSZ - 1), t = m >> 5;
        int tok = decX[b * TD + t];
        g_embh[m * EDIM + e] = __float2half(embW[tok * EDIM + e]);
    }
}

// ---------------------------------------------------------------------------
// Generalized fp16 HMMA GEMM (unchanged)
__global__ __launch_bounds__(256, 1)
void k_hgemm2(const __half* __restrict__ A, const __half* __restrict__ B,
              const float* __restrict__ bias, int K, int nI, int mode) {
    extern __shared__ char smem[];
    uint32_t sb = smem_u32(smem);
    int tid = threadIdx.x;
    int wid = tid >> 5, lane = tid & 31;
    int wm = wid & 3, wn = wid >> 2;
    int m0 = blockIdx.x * BM, n0 = blockIdx.y * BN;

    const __half* gA0 = A + (size_t)m0 * K;
    const __half* gB0 = B + (size_t)n0 * K;

    auto load_stage = [&](int kt, int s) {
        uint32_t sa = sb + s * STAGE;
        const __half* gA = gA0 + kt * BK;
#pragma unroll
        for (int r8 = 0; r8 < 8; r8++) {
            int li = r8 * 256 + tid;
            int row = li >> 3, seg = li & 7;
            uint32_t dst = sa + row * ROWB + seg * 16;
            const void* src = gA + (size_t)row * K + seg * 8;
            asm volatile("cp.async.cg.shared.global [%0], [%1], 16;" :: "r"(dst), "l"(src));
        }
        uint32_t sbB = sa + SA_BYTES;
        const __half* gB = gB0 + kt * BK;
#pragma unroll
        for (int r4 = 0; r4 < 4; r4++) {
            int li = r4 * 256 + tid;
            int row = li >> 3, seg = li & 7;
            uint32_t dst = sbB + row * ROWB + seg * 16;
            const void* src = gB + (size_t)row * K + seg * 8;
            asm volatile("cp.async.cg.shared.global [%0], [%1], 16;" :: "r"(dst), "l"(src));
        }
        asm volatile("cp.async.commit_group;" ::: "memory");
    };

    float acc[4][8][4];
#pragma unroll
    for (int i = 0; i < 4; i++)
#pragma unroll
        for (int j = 0; j < 8; j++)
#pragma unroll
            for (int q = 0; q < 4; q++) acc[i][j][q] = 0.0f;

    load_stage(0, 0);
    load_stage(1, 1);

    for (int kt = 0; kt < nI; kt++) {
        asm volatile("cp.async.wait_group 1;" ::: "memory");
        __syncthreads();
        int s = kt % NSTAGE;
        if (kt + 2 < nI) load_stage(kt + 2, (kt + 2) % NSTAGE);

        uint32_t sa = sb + s * STAGE;
        uint32_t sB = sa + SA_BYTES;
#pragma unroll
        for (int kk = 0; kk < 4; kk++) {
            uint32_t a[4][4], b[4][4];
#pragma unroll
            for (int i = 0; i < 4; i++) {
                int row = wm * 64 + i * 16 + (lane & 15);
                int ko = kk * 16 + ((lane >> 4) << 3);
                uint32_t ad = sa + row * ROWB + ko * 2;
                asm volatile("ldmatrix.sync.aligned.m8n8.x4.shared.b16 {%0,%1,%2,%3}, [%4];"
                             : "=r"(a[i][0]), "=r"(a[i][1]), "=r"(a[i][2]), "=r"(a[i][3])
                             : "r"(ad));
            }
#pragma unroll
            for (int j2 = 0; j2 < 4; j2++) {
                int nrow = wn * 64 + j2 * 16 + (lane & 7) + (((lane >> 4) & 1) << 3);
                int ko = kk * 16 + (((lane >> 3) & 1) << 3);
                uint32_t bd = sB + nrow * ROWB + ko * 2;
                asm volatile("ldmatrix.sync.aligned.m8n8.x4.shared.b16 {%0,%1,%2,%3}, [%4];"
                             : "=r"(b[j2][0]), "=r"(b[j2][1]), "=r"(b[j2][2]), "=r"(b[j2][3])
                             : "r"(bd));
            }
#pragma unroll
            for (int i = 0; i < 4; i++)
#pragma unroll
                for (int j2 = 0; j2 < 4; j2++) {
                    asm volatile(
                        "mma.sync.aligned.m16n8k16.row.col.f32.f16.f16.f32 "
                        "{%0,%1,%2,%3}, {%4,%5,%6,%7}, {%8,%9}, {%0,%1,%2,%3};"
                        : "+f"(acc[i][2*j2][0]), "+f"(acc[i][2*j2][1]),
                          "+f"(acc[i][2*j2][2]), "+f"(acc[i][2*j2][3])
                        : "r"(a[i][0]), "r"(a[i][1]), "r"(a[i][2]), "r"(a[i][3]),
                          "r"(b[j2][0]), "r"(b[j2][1]));
                    asm volatile(
                        "mma.sync.aligned.m16n8k16.row.col.f32.f16.f16.f32 "
                        "{%0,%1,%2,%3}, {%4,%5,%6,%7}, {%8,%9}, {%0,%1,%2,%3};"
                        : "+f"(acc[i][2*j2+1][0]), "+f"(acc[i][2*j2+1][1]),
                          "+f"(acc[i][2*j2+1][2]), "+f"(acc[i][2*j2+1][3])
                        : "r"(a[i][0]), "r"(a[i][1]), "r"(a[i][2]), "r"(a[i][3]),
                          "r"(b[j2][2]), "r"(b[j2][3]));
                }
        }
        __syncthreads();
    }
    asm volatile("cp.async.wait_group 0;" ::: "memory");

#pragma unroll
    for (int j = 0; j < 8; j++) {
        int ncol = n0 + wn * 64 + j * 8 + (lane & 3) * 2;
        float b0 = bias[ncol], b1 = bias[ncol + 1];
#pragma unroll
        for (int i = 0; i < 4; i++) {
            int mr0 = m0 + wm * 64 + i * 16 + (lane >> 2);
#pragma unroll
            for (int h = 0; h < 2; h++) {
                int mrow = mr0 + h * 8;
                float v0 = acc[i][j][2*h + 0] + b0;
                float v1 = acc[i][j][2*h + 1] + b1;
                if (mode == 0) {
                    int tt = mrow >> 5, bb2 = mrow & 31;
                    int rp0 = ((ncol & 511) << 2) | (ncol >> 9);
                    int rp1 = (((ncol + 1) & 511) << 2) | ((ncol + 1) >> 9);
                    g_xihp[((size_t)tt * G4 + rp0) * 32 + bb2] = v0;
                    g_xihp[((size_t)tt * G4 + rp1) * 32 + bb2] = v1;
                } else {
                    __half2 hv = __floats2half2_rn(tanhf(v0), tanhf(v1));
                    *(__half2*)(g_Ah + (size_t)mrow * KDIM + ncol) = hv;
                }
            }
        }
    }
}

// ---------------------------------------------------------------------------
// Persistent fused LSTM: g_hsh slot-shifted (reads slot t, writes slot t+1);
// barrier = syncthreads + tid0 release-atomic + acquire-spin (no per-thread membar).
__global__ __launch_bounds__(256, 1)
void k_lstm_p(const float* __restrict__ c0, float* __restrict__ out) {
    extern __shared__ char sm[];
    uint32_t sb = smem_u32(sm);
    int tid = threadIdx.x, w = tid >> 5, lane = tid & 31;
    int jt = blockIdx.x;

    const __half* Wp = g_Whp + (size_t)(jt * 32) * HDIM;
#pragma unroll
    for (int p = 0; p < 8; p++) {
        int idx = p * 256 + tid;
        int row = idx >> 6, seg = idx & 63;
        uint32_t dst = sb + row * SAROW + seg * 16;
        const void* src = Wp + row * HDIM + seg * 8;
        asm volatile("cp.async.cg.shared.global [%0], [%1], 16;" :: "r"(dst), "l"(src));
    }
    asm volatile("cp.async.commit_group;" ::: "memory");

    int b = tid & 31, ul = tid >> 5;
    int u = jt * 8 + ul;
    float creg = c0[b * HDIM + u];
    float hlast = 0.0f;

    float* gS0 = (float*)(sm + SMG);
    float* gS1 = gS0 + 32 * 33;
    int wg = w >> 2, wq = w & 3;
    int wm = wq >> 1, wn = wq & 1;

    for (int t = 0; t < TD; t++) {
        const float* xp = g_xihp + ((size_t)t * G4 + u * 4) * 32 + b;
        float x0 = xp[0], x1 = xp[32], x2 = xp[64], x3 = xp[96];

        // Stage h_{t-1} from g_hsh slot t
        const __half* hp = g_hsh + (size_t)t * BSZ * HDIM;
#pragma unroll
        for (int p = 0; p < 8; p++) {
            int idx = p * 256 + tid;
            int row = idx >> 6, seg = idx & 63;
            uint32_t dst = sb + SMH + row * SAROW + seg * 16;
            const void* src = hp + row * HDIM + seg * 8;
            asm volatile("cp.async.cg.shared.global [%0], [%1], 16;" :: "r"(dst), "l"(src));
        }
        asm volatile("cp.async.commit_group;" ::: "memory");
        asm volatile("cp.async.wait_group 0;" ::: "memory");
        __syncthreads();

        float acc[2][4] = {};
#pragma unroll
        for (int kk2 = 0; kk2 < 16; kk2++) {
            int kk = wg * 16 + kk2;
            uint32_t a[4], bb[4];
            {
                int row = wm * 16 + (lane & 15);
                int ko = kk * 16 + ((lane >> 4) << 3);
                uint32_t ad = sb + row * SAROW + ko * 2;
                asm volatile("ldmatrix.sync.aligned.m8n8.x4.shared.b16 {%0,%1,%2,%3}, [%4];"
                             : "=r"(a[0]), "=r"(a[1]), "=r"(a[2]), "=r"(a[3]) : "r"(ad));
            }
            {
                int nrow = wn * 16 + (lane & 7) + (((lane >> 4) & 1) << 3);
                int ko = kk * 16 + (((lane >> 3) & 1) << 3);
                uint32_t bd = sb + SMH + nrow * SAROW + ko * 2;
                asm volatile("ldmatrix.sync.aligned.m8n8.x4.shared.b16 {%0,%1,%2,%3}, [%4];"
                             : "=r"(bb[0]), "=r"(bb[1]), "=r"(bb[2]), "=r"(bb[3]) : "r"(bd));
            }
#pragma unroll
            for (int s = 0; s < 2; s++) {
                asm volatile(
                    "mma.sync.aligned.m16n8k16.row.col.f32.f16.f16.f32 "
                    "{%0,%1,%2,%3}, {%4,%5,%6,%7}, {%8,%9}, {%0,%1,%2,%3};"
                    : "+f"(acc[s][0]), "+f"(acc[s][1]), "+f"(acc[s][2]), "+f"(acc[s][3])
                    : "r"(a[0]), "r"(a[1]), "r"(a[2]), "r"(a[3]),
                      "r"(bb[2*s]), "r"(bb[2*s+1]));
            }
        }
        {
            float* gD = wg ? gS1 : gS0;
            int r0 = wm * 16 + (lane >> 2);
#pragma unroll
            for (int s = 0; s < 2; s++) {
                int c0i = wn * 16 + s * 8 + 2 * (lane & 3);
                gD[r0 * 33 + c0i]           = acc[s][0];
                gD[r0 * 33 + c0i + 1]       = acc[s][1];
                gD[(r0 + 8) * 33 + c0i]     = acc[s][2];
                gD[(r0 + 8) * 33 + c0i + 1] = acc[s][3];
            }
        }
        __syncthreads();

        {
            float gi = gS0[(4 * ul + 0) * 33 + b] + gS1[(4 * ul + 0) * 33 + b] + x0;
            float gf = gS0[(4 * ul + 1) * 33 + b] + gS1[(4 * ul + 1) * 33 + b] + x1;
            float gg = gS0[(4 * ul + 2) * 33 + b] + gS1[(4 * ul + 2) * 33 + b] + x2;
            float go = gS0[(4 * ul + 3) * 33 + b] + gS1[(4 * ul + 3) * 33 + b] + x3;
            float c = sigf(gf) * creg + sigf(gi) * tanhf(gg);
            creg = c;
            float hh = sigf(go) * tanhf(c);
            hlast = hh;
            g_hsh[((size_t)(t + 1) * BSZ + b) * HDIM + u] = __float2half(hh);
        }

        // Grid barrier: syncthreads (intra-CTA HB) + tid0 release-add + acquire-spin
        __syncthreads();
        if (tid == 0) {
            asm volatile("red.release.gpu.global.add.u32 [%0], %1;"
                         :: "l"(&g_bar), "r"(1u) : "memory");
            unsigned target = (unsigned)(t + 1) * LCTA;
            unsigned v;
            do {
                asm volatile("ld.acquire.gpu.global.u32 %0, [%1];"
                             : "=r"(v) : "l"(&g_bar) : "memory");
            } while (v < target);
        }
        __syncthreads();
    }

    g_c[b * HDIM + u] = creg;
    out[(size_t)M_BT * VOC + b * HDIM + u] = hlast;
    out[(size_t)M_BT * VOC + BSZ * HDIM + b * HDIM + u] = creg;
}

// ---------------------------------------------------------------------------
// HMMA attention (reads h from slot t+1)
__global__ __launch_bounds__(256, 1)
void k_attn2() {
    extern __shared__ char sm[];
    uint32_t sb = smem_u32(sm);
    int tid = threadIdx.x, wid = tid >> 5, lane = tid & 31;
    int bi = blockIdx.x;
    int b = bi >> 1, t0 = (bi & 1) * 32;

    const __half* encp = g_ench + (size_t)b * TEC * HDIM;
#pragma unroll
    for (int p = 0; p < 32; p++) {
        int idx = p * 256 + tid;
        int row = idx >> 6, seg = idx & 63;
        uint32_t dst = sb + AT_ENC + row * SAROW + seg * 16;
        const void* src = encp + (size_t)row * HDIM + seg * 8;
        asm volatile("cp.async.cg.shared.global [%0], [%1], 16;" :: "r"(dst), "l"(src));
    }
#pragma unroll
    for (int p = 0; p < 8; p++) {
        int idx = p * 256 + tid;
        int row = idx >> 6, seg = idx & 63;
        uint32_t dst = sb + AT_H + row * SAROW + seg * 16;
        const void* src = g_hsh + ((size_t)(t0 + row + 1) * BSZ + b) * HDIM + seg * 8;
        asm volatile("cp.async.cg.shared.global [%0], [%1], 16;" :: "r"(dst), "l"(src));
    }
    asm volatile("cp.async.commit_group;" ::: "memory");
    asm volatile("cp.async.wait_group 0;" ::: "memory");
    __syncthreads();

    int wm2 = wid >> 2, wn2 = wid & 3;

    float sacc[2][2][4] = {};
#pragma unroll
    for (int kk = 0; kk < 32; kk++) {
        uint32_t a[4];
        {
            int row = wm2 * 16 + (lane & 15);
            int ko = kk * 16 + ((lane >> 4) << 3);
            uint32_t ad = sb + AT_H + row * SAROW + ko * 2;
            asm volatile("ldmatrix.sync.aligned.m8n8.x4.shared.b16 {%0,%1,%2,%3}, [%4];"
                         : "=r"(a[0]), "=r"(a[1]), "=r"(a[2]), "=r"(a[3]) : "r"(ad));
        }
#pragma unroll
        for (int j2 = 0; j2 < 2; j2++) {
            uint32_t bb[4];
            int nrow = wn2 * 32 + j2 * 16 + (lane & 7) + (((lane >> 4) & 1) << 3);
            int ko = kk * 16 + (((lane >> 3) & 1) << 3);
            uint32_t bd = sb + AT_ENC + nrow * SAROW + ko * 2;
            asm volatile("ldmatrix.sync.aligned.m8n8.x4.shared.b16 {%0,%1,%2,%3}, [%4];"
                         : "=r"(bb[0]), "=r"(bb[1]), "=r"(bb[2]), "=r"(bb[3]) : "r"(bd));
#pragma unroll
            for (int s = 0; s < 2; s++) {
                asm volatile(
                    "mma.sync.aligned.m16n8k16.row.col.f32.f16.f16.f32 "
                    "{%0,%1,%2,%3}, {%4,%5,%6,%7}, {%8,%9}, {%0,%1,%2,%3};"
                    : "+f"(sacc[j2][s][0]), "+f"(sacc[j2][s][1]),
                      "+f"(sacc[j2][s][2]), "+f"(sacc[j2][s][3])
                    : "r"(a[0]), "r"(a[1]), "r"(a[2]), "r"(a[3]),
                      "r"(bb[2*s]), "r"(bb[2*s+1]));
            }
        }
    }
    float* sc = (float*)(sm + AT_SC);
    {
        int r0 = wm2 * 16 + (lane >> 2);
#pragma unroll
        for (int j2 = 0; j2 < 2; j2++)
#pragma unroll
            for (int nb = 0; nb < 2; nb++) {
                int c0i = wn2 * 32 + j2 * 16 + nb * 8 + 2 * (lane & 3);
                sc[r0 * 132 + c0i]           = sacc[j2][nb][0];
                sc[r0 * 132 + c0i + 1]       = sacc[j2][nb][1];
                sc[(r0 + 8) * 132 + c0i]     = sacc[j2][nb][2];
                sc[(r0 + 8) * 132 + c0i + 1] = sacc[j2][nb][3];
            }
    }
    __syncthreads();

    __half* Pp = (__half*)(sm + AT_P);
#pragma unroll
    for (int r = 0; r < 4; r++) {
        int row = wid * 4 + r;
        float sv[4], mx = -1e30f;
#pragma unroll
        for (int q = 0; q < 4; q++) { sv[q] = sc[row * 132 + lane + 32 * q]; mx = fmaxf(mx, sv[q]); }
#pragma unroll
        for (int off = 16; off; off >>= 1) mx = fmaxf(mx, __shfl_xor_sync(0xffffffffu, mx, off));
        float sum = 0.0f;
#pragma unroll
        for (int q = 0; q < 4; q++) { sv[q] = expf(sv[q] - mx); sum += sv[q]; }
#pragma unroll
        for (int off = 16; off; off >>= 1) sum += __shfl_xor_sync(0xffffffffu, sum, off);
        float inv = 1.0f / sum;
#pragma unroll
        for (int q = 0; q < 4; q++)
            Pp[row * 136 + lane + 32 * q] = __float2half(sv[q] * inv);
    }
    __syncthreads();

    float cacc[8][2][4];
#pragma unroll
    for (int j2 = 0; j2 < 8; j2++)
#pragma unroll
        for (int nb = 0; nb < 2; nb++)
#pragma unroll
            for (int q = 0; q < 4; q++) cacc[j2][nb][q] = 0.0f;

#pragma unroll
    for (int kk = 0; kk < 8; kk++) {
        uint32_t a[4];
        {
            int row = wm2 * 16 + (lane & 15);
            int ko = kk * 16 + ((lane >> 4) << 3);
            uint32_t ad = sb + AT_P + row * 272 + ko * 2;
            asm volatile("ldmatrix.sync.aligned.m8n8.x4.shared.b16 {%0,%1,%2,%3}, [%4];"
                         : "=r"(a[0]), "=r"(a[1]), "=r"(a[2]), "=r"(a[3]) : "r"(ad));
        }
#pragma unroll
        for (int j2 = 0; j2 < 8; j2++) {
            uint32_t bb[4];
            int j0 = wn2 * 128 + j2 * 16;
            int te = kk * 16 + (((lane >> 3) & 1) << 3) + (lane & 7);
            int jc = j0 + (((lane >> 4) & 1) << 3);
            uint32_t bd = sb + AT_ENC + te * SAROW + jc * 2;
            asm volatile("ldmatrix.sync.aligned.m8n8.x4.trans.shared.b16 {%0,%1,%2,%3}, [%4];"
                         : "=r"(bb[0]), "=r"(bb[1]), "=r"(bb[2]), "=r"(bb[3]) : "r"(bd));
#pragma unroll
            for (int s = 0; s < 2; s++) {
                asm volatile(
                    "mma.sync.aligned.m16n8k16.row.col.f32.f16.f16.f32 "
                    "{%0,%1,%2,%3}, {%4,%5,%6,%7}, {%8,%9}, {%0,%1,%2,%3};"
                    : "+f"(cacc[j2][s][0]), "+f"(cacc[j2][s][1]),
                      "+f"(cacc[j2][s][2]), "+f"(cacc[j2][s][3])
                    : "r"(a[0]), "r"(a[1]), "r"(a[2]), "r"(a[3]),
                      "r"(bb[2*s]), "r"(bb[2*s+1]));
            }
        }
    }

    {
        int r0 = wm2 * 16 + (lane >> 2);
#pragma unroll
        for (int j2 = 0; j2 < 8; j2++)
#pragma unroll
            for (int nb = 0; nb < 2; nb++) {
                int c0i = wn2 * 128 + j2 * 16 + nb * 8 + 2 * (lane & 3);
                int m = b * TD + t0 + r0;
                *(__half2*)(g_cath + (size_t)m * (2 * HDIM) + HDIM + c0i) =
                    __floats2half2_rn(cacc[j2][nb][0], cacc[j2][nb][1]);
                *(__half2*)(g_cath + (size_t)(m + 8) * (2 * HDIM) + HDIM + c0i) =
                    __floats2half2_rn(cacc[j2][nb][2], cacc[j2][nb][3]);
            }
    }
#pragma unroll
    for (int p = 0; p < 8; p++) {
        int idx = p * 256 + tid;
        int row = idx >> 6, seg = idx & 63;
        uint4 v = *(uint4*)(sm + AT_H + row * SAROW + seg * 16);
        int m = b * TD + t0 + row;
        *(uint4*)(g_cath + (size_t)m * (2 * HDIM) + seg * 8) = v;
    }
}

// ---------------------------------------------------------------------------
// HMMA fc GEMM (unchanged)
__global__ __launch_bounds__(256, 1)
void k_hgemm(const float* __restrict__ fcb, float* __restrict__ C) {
    extern __shared__ char smem[];
    uint32_t sb = smem_u32(smem);
    int tid = threadIdx.x;
    int wid = tid >> 5, lane = tid & 31;
    int wm = wid & 3, wn = wid >> 2;
    int m0 = blockIdx.x * BM, n0 = blockIdx.y * BN;

    const __half* gA0 = g_Ah + (size_t)m0 * KDIM;
    const __half* gB0 = g_Bh + (size_t)n0 * KDIM;

    auto load_stage = [&](int kt, int s) {
        uint32_t sa = sb + s * STAGE;
        const __half* gA = gA0 + kt * BK;
#pragma unroll
        for (int r8 = 0; r8 < 8; r8++) {
            int li = r8 * 256 + tid;
            int row = li >> 3, seg = li & 7;
            uint32_t dst = sa + row * ROWB + seg * 16;
            const void* src = gA + (size_t)row * KDIM + seg * 8;
            asm volatile("cp.async.cg.shared.global [%0], [%1], 16;" :: "r"(dst), "l"(src));
        }
        uint32_t sbB = sa + SA_BYTES;
        const __half* gB = gB0 + kt * BK;
#pragma unroll
        for (int r4 = 0; r4 < 4; r4++) {
            int li = r4 * 256 + tid;
            int row = li >> 3, seg = li & 7;
            uint32_t dst = sbB + row * ROWB + seg * 16;
            const void* src = gB + (size_t)row * KDIM + seg * 8;
            asm volatile("cp.async.cg.shared.global [%0], [%1], 16;" :: "r"(dst), "l"(src));
        }
        asm volatile("cp.async.commit_group;" ::: "memory");
    };

    float acc[4][8][4];
#pragma unroll
    for (int i = 0; i < 4; i++)
#pragma unroll
        for (int j = 0; j < 8; j++)
#pragma unroll
            for (int q = 0; q < 4; q++) acc[i][j][q] = 0.0f;

    load_stage(0, 0);
    load_stage(1, 1);

    for (int kt = 0; kt < KI; kt++) {
        asm volatile("cp.async.wait_group 1;" ::: "memory");
        __syncthreads();
        int s = kt % NSTAGE;
        if (kt + 2 < KI) load_stage(kt + 2, (kt + 2) % NSTAGE);

        uint32_t sa = sb + s * STAGE;
        uint32_t sB = sa + SA_BYTES;
#pragma unroll
        for (int kk = 0; kk < 4; kk++) {
            uint32_t a[4][4], b[4][4];
#pragma unroll
            for (int i = 0; i < 4; i++) {
                int row = wm * 64 + i * 16 + (lane & 15);
                int ko = kk * 16 + ((lane >> 4) << 3);
                uint32_t ad = sa + row * ROWB + ko * 2;
                asm volatile("ldmatrix.sync.aligned.m8n8.x4.shared.b16 {%0,%1,%2,%3}, [%4];"
                             : "=r"(a[i][0]), "=r"(a[i][1]), "=r"(a[i][2]), "=r"(a[i][3])
                             : "r"(ad));
            }
#pragma unroll
            for (int j2 = 0; j2 < 4; j2++) {
                int nrow = wn * 64 + j2 * 16 + (lane & 7) + (((lane >> 4) & 1) << 3);
                int ko = kk * 16 + (((lane >> 3) & 1) << 3);
                uint32_t bd = sB + nrow * ROWB + ko * 2;
                asm volatile("ldmatrix.sync.aligned.m8n8.x4.shared.b16 {%0,%1,%2,%3}, [%4];"
                             : "=r"(b[j2][0]), "=r"(b[j2][1]), "=r"(b[j2][2]), "=r"(b[j2][3])
                             : "r"(bd));
            }
#pragma unroll
            for (int i = 0; i < 4; i++)
#pragma unroll
                for (int j2 = 0; j2 < 4; j2++) {
                    asm volatile(
                        "mma.sync.aligned.m16n8k16.row.col.f32.f16.f16.f32 "
                        "{%0,%1,%2,%3}, {%4,%5,%6,%7}, {%8,%9}, {%0,%1,%2,%3};"
                        : "+f"(acc[i][2*j2][0]), "+f"(acc[i][2*j2][1]),
                          "+f"(acc[i][2*j2][2]), "+f"(acc[i][2*j2][3])
                        : "r"(a[i][0]), "r"(a[i][1]), "r"(a[i][2]), "r"(a[i][3]),
                          "r"(b[j2][0]), "r"(b[j2][1]));
                    asm volatile(
                        "mma.sync.aligned.m16n8k16.row.col.f32.f16.f16.f32 "
                        "{%0,%1,%2,%3}, {%4,%5,%6,%7}, {%8,%9}, {%0,%1,%2,%3};"
                        : "+f"(acc[i][2*j2+1][0]), "+f"(acc[i][2*j2+1][1]),
                          "+f"(acc[i][2*j2+1][2]), "+f"(acc[i][2*j2+1][3])
                        : "r"(a[i][0]), "r"(a[i][1]), "r"(a[i][2]), "r"(a[i][3]),
                          "r"(b[j2][2]), "r"(b[j2][3]));
                }
        }
        __syncthreads();
    }
    asm volatile("cp.async.wait_group 0;" ::: "memory");

#pragma unroll
    for (int j = 0; j < 8; j++) {
        int ncol = n0 + wn * 64 + j * 8 + (lane & 3) * 2;
        float b0 = fcb[ncol], b1 = fcb[ncol + 1];
#pragma unroll
        for (int i = 0; i < 4; i++) {
            int mrow = m0 + wm * 64 + i * 16 + (lane >> 2);
            float2 v0 = {acc[i][j][0] + b0, acc[i][j][1] + b1};
            float2 v1 = {acc[i][j][2] + b0, acc[i][j][3] + b1};
            *(float2*)(C + (size_t)mrow * VOC + ncol) = v0;
            *(float2*)(C + (size_t)(mrow + 8) * VOC + ncol) = v1;
        }
    }
}

// ---------------------------------------------------------------------------
extern "C" void kernel_launch(void* const* d_in, const int* in_sizes, int n_in,
                              void* d_out, int out_size) {
    const int*   decX = (const int*)d_in[0];
    const float* enc  = (const float*)d_in[1];
    const float* h0   = (const float*)d_in[2];
    const float* c0   = (const float*)d_in[3];
    const float* embW = (const float*)d_in[4];
    const float* Wih  = (const float*)d_in[5];
    const float* Whh  = (const float*)d_in[6];
    const float* bih  = (const float*)d_in[7];
    const float* bhh  = (const float*)d_in[8];
    const float* attW = (const float*)d_in[9];
    const float* attb = (const float*)d_in[10];
    const float* fcW  = (const float*)d_in[11];
    const float* fcb  = (const float*)d_in[12];
    float* out = (float*)d_out;

    __half *p_Wihh, *p_attWh, *p_embh, *p_cath;
    float *p_bias;
    cudaGetSymbolAddress((void**)&p_Wihh,  g_Wihh);
    cudaGetSymbolAddress((void**)&p_attWh, g_attWh);
    cudaGetSymbolAddress((void**)&p_embh,  g_embh);
    cudaGetSymbolAddress((void**)&p_cath,  g_cath);
    cudaGetSymbolAddress((void**)&p_bias,  g_bias);

    cudaFuncSetAttribute(k_hgemm,  cudaFuncAttributeMaxDynamicSharedMemorySize, SM_TOTAL);
    cudaFuncSetAttribute(k_hgemm2, cudaFuncAttributeMaxDynamicSharedMemorySize, SM_TOTAL);
    cudaFuncSetAttribute(k_lstm_p, cudaFuncAttributeMaxDynamicSharedMemorySize, STEP_SMEM);
    cudaFuncSetAttribute(k_attn2,  cudaFuncAttributeMaxDynamicSharedMemorySize, ATN_SMEM);

    k_init<<<NB_INIT, 256>>>(fcW, Wih, attW, Whh, bih, bhh, h0, decX, embW, enc);
    k_hgemm2<<<dim3(M_BT / BM, G4 / BN), 256, SM_TOTAL>>>(p_embh, p_Wihh, p_bias,
                                                          EDIM, EDIM / BK, 0);
    k_lstm_p<<<LCTA, 256, STEP_SMEM>>>(c0, out);
    k_attn2<<<64, 256, ATN_SMEM>>>();
    k_hgemm2<<<dim3(M_BT / BM, HDIM / BN), 256, SM_TOTAL>>>(p_cath, p_attWh, attb,
                                                            2 * HDIM, 2 * HDIM / BK, 1);
    k_hgemm<<<dim3(M_BT / BM, VOC / BN), 256, SM_TOTAL>>>(fcb, out);
}

// round 15
// speedup vs baseline: 3.1549x; 1.1145x over previous
#include <cuda_runtime.h>
#include <cuda_fp16.h>
#include <math.h>
#include <stdint.h>

// Problem constants
#define BSZ   32
#define TD    64
#define TEC   128
#define EDIM  256
#define HDIM  512
#define G4    2048
#define VOC   32000
#define M_BT  2048

// Unified HMMA GEMM tiling: 128x128, 2-stage, 2 CTAs/SM
#define BM    128
#define BN    128
#define BK    64
#define KDIM  512
#define ROWB  144
#define SA_BYTES (BM * ROWB)
#define SB_BYTES (BN * ROWB)
#define STAGE    (SA_BYTES + SB_BYTES)     // 36864
#define SM_TOTAL (2 * STAGE)               // 73728

// Persistent LSTM kernel
#define LCTA  64
#define SAROW 1040
#define SMH   (32 * SAROW)
#define SMG   (SMH + 32 * SAROW)
#define STEP_SMEM (SMG + 2 * 32 * 33 * 4)

// HMMA attention kernel
#define AT_ENC 0
#define AT_H   (128 * SAROW)
#define AT_SC  (AT_H + 32 * SAROW)
#define AT_P   (AT_SC + 32 * 132 * 4)
#define ATN_SMEM (AT_P + 32 * 136 * 2)

// Init kernel grid sections
#define NB_FC   16000
#define NB_WIH  512
#define NB_ATT  512
#define NB_WHH  1024
#define NB_BIAS 8
#define NB_H0   64
#define NB_ENC  2048
#define NB_EMB  2048
#define NB_INIT (NB_FC + NB_WIH + NB_ATT + NB_WHH + NB_BIAS + NB_H0 + NB_ENC + NB_EMB)

// Scratch
__device__ float g_bias[G4];
__device__ float g_xihp[(size_t)TD * G4 * BSZ];
__device__ float g_c   [BSZ * HDIM];
__device__ unsigned g_bar;
__device__ __align__(16) __half g_hsh[(size_t)(TD + 1) * BSZ * HDIM];
__device__ __align__(16) __half g_ench[(size_t)BSZ * TEC * HDIM];
__device__ __align__(16) __half g_embh[M_BT * EDIM];
__device__ __align__(16) __half g_Wihh[(size_t)G4 * EDIM];
__device__ __align__(16) __half g_cath[(size_t)M_BT * 2 * HDIM];
__device__ __align__(16) __half g_attWh[(size_t)HDIM * 2 * HDIM];
__device__ __align__(16) __half g_Whp[(size_t)G4 * HDIM];
__device__ __align__(16) __half g_Ah[(size_t)M_BT * KDIM];
__device__ __align__(16) __half g_Bh[(size_t)VOC * KDIM];

__device__ __forceinline__ float sigf(float x) { return 1.0f / (1.0f + expf(-x)); }

__device__ __forceinline__ uint32_t smem_u32(const void* p) {
    uint32_t a;
    asm("{ .reg .u64 t; cvta.to.shared.u64 t, %1; cvt.u32.u64 %0, t; }" : "=r"(a) : "l"(p));
    return a;
}

__device__ __forceinline__ void cvt4(const float* src, __half* dst) {
    float4 x = *(const float4*)src;
    __half h[4] = {__float2half(x.x), __float2half(x.y),
                   __float2half(x.z), __float2half(x.w)};
    *(uint2*)dst = *(uint2*)h;
}

// ---------------------------------------------------------------------------
// ONE fused init kernel
__global__ void k_init(const float* __restrict__ fcW, const float* __restrict__ Wih,
                       const float* __restrict__ attW, const float* __restrict__ Whh,
                       const float* __restrict__ bih, const float* __restrict__ bhh,
                       const float* __restrict__ h0, const int* __restrict__ decX,
                       const float* __restrict__ embW, const float* __restrict__ enc) {
    int blk = blockIdx.x, tid = threadIdx.x;
    if (blk < NB_FC) {
        size_t i4 = (size_t)blk * 256 + tid;
        cvt4(fcW + i4 * 4, g_Bh + i4 * 4);
        return;
    }
    blk -= NB_FC;
    if (blk < NB_WIH) {
        size_t i4 = (size_t)blk * 256 + tid;
        cvt4(Wih + i4 * 4, g_Wihh + i4 * 4);
        return;
    }
    blk -= NB_WIH;
    if (blk < NB_ATT) {
        size_t i4 = (size_t)blk * 256 + tid;
        cvt4(attW + i4 * 4, g_attWh + i4 * 4);
        return;
    }
    blk -= NB_ATT;
    if (blk < NB_WHH) {
        size_t i4 = (size_t)blk * 256 + tid;
        size_t e = i4 * 4;
        int rp = (int)(e >> 9), k = (int)(e & 511);
        int u = rp >> 2, g = rp & 3;
        cvt4(Whh + (size_t)(g * HDIM + u) * HDIM + k, g_Whp + (size_t)rp * HDIM + k);
        return;
    }
    blk -= NB_WHH;
    if (blk < NB_BIAS) {
        int i = blk * 256 + tid;
        g_bias[i] = bih[i] + bhh[i];
        if (i == 0) g_bar = 0u;
        return;
    }
    blk -= NB_BIAS;
    if (blk < NB_H0) {
        int i = blk * 256 + tid;
        g_hsh[i] = __float2half(h0[i]);
        return;
    }
    blk -= NB_H0;
    if (blk < NB_ENC) {
        size_t i4 = (size_t)blk * 256 + tid;
        cvt4(enc + i4 * 4, g_ench + i4 * 4);
        return;
    }
    blk -= NB_ENC;
    {
        int m = blk, e = tid;
        int b = m & (BSZ - 1), t = m >> 5;
        int tok = decX[b * TD + t];
        g_embh[m * EDIM + e] = __float2half(embW[tok * EDIM + e]);
    }
}

// ---------------------------------------------------------------------------
// Unified fp16 HMMA GEMM: 128x128 tile, 2-stage, 2 CTAs/SM.
// mode 0: acc+bias -> permuted fp32 g_xihp       (xih)
// mode 1: tanh(acc+bias) -> fp16 g_Ah            (attn out)
// mode 2: acc+bias -> fp32 C (stride ldc)        (fc logits)
__global__ __launch_bounds__(256, 2)
void k_hgemm2(const __half* __restrict__ A, const __half* __restrict__ B,
              const float* __restrict__ bias, float* __restrict__ C,
              int K, int nI, int ldc, int mode) {
    extern __shared__ char smem[];
    uint32_t sb = smem_u32(smem);
    int tid = threadIdx.x;
    int wid = tid >> 5, lane = tid & 31;
    int wm = wid & 3, wn = wid >> 2;          // 4 m-tiles of 32, 2 n-tiles of 64
    int m0 = blockIdx.x * BM, n0 = blockIdx.y * BN;

    const __half* gA0 = A + (size_t)m0 * K;
    const __half* gB0 = B + (size_t)n0 * K;

    auto load_stage = [&](int kt, int s) {
        uint32_t sa = sb + s * STAGE;
        const __half* gA = gA0 + kt * BK;
#pragma unroll
        for (int r4 = 0; r4 < 4; r4++) {          // A: 128 rows x 8 segs
            int li = r4 * 256 + tid;
            int row = li >> 3, seg = li & 7;
            uint32_t dst = sa + row * ROWB + seg * 16;
            const void* src = gA + (size_t)row * K + seg * 8;
            asm volatile("cp.async.cg.shared.global [%0], [%1], 16;" :: "r"(dst), "l"(src));
        }
        uint32_t sbB = sa + SA_BYTES;
        const __half* gB = gB0 + kt * BK;
#pragma unroll
        for (int r4 = 0; r4 < 4; r4++) {          // B: 128 rows x 8 segs
            int li = r4 * 256 + tid;
            int row = li >> 3, seg = li & 7;
            uint32_t dst = sbB + row * ROWB + seg * 16;
            const void* src = gB + (size_t)row * K + seg * 8;
            asm volatile("cp.async.cg.shared.global [%0], [%1], 16;" :: "r"(dst), "l"(src));
        }
        asm volatile("cp.async.commit_group;" ::: "memory");
    };

    float acc[2][8][4];
#pragma unroll
    for (int i = 0; i < 2; i++)
#pragma unroll
        for (int j = 0; j < 8; j++)
#pragma unroll
            for (int q = 0; q < 4; q++) acc[i][j][q] = 0.0f;

    load_stage(0, 0);

    for (int kt = 0; kt < nI; kt++) {
        asm volatile("cp.async.wait_group 0;" ::: "memory");
        __syncthreads();
        if (kt + 1 < nI) load_stage(kt + 1, (kt + 1) & 1);

        uint32_t sa = sb + (kt & 1) * STAGE;
        uint32_t sB = sa + SA_BYTES;
#pragma unroll
        for (int kk = 0; kk < 4; kk++) {
            uint32_t a[2][4], b[4][4];
#pragma unroll
            for (int i = 0; i < 2; i++) {
                int row = wm * 32 + i * 16 + (lane & 15);
                int ko = kk * 16 + ((lane >> 4) << 3);
                uint32_t ad = sa + row * ROWB + ko * 2;
                asm volatile("ldmatrix.sync.aligned.m8n8.x4.shared.b16 {%0,%1,%2,%3}, [%4];"
                             : "=r"(a[i][0]), "=r"(a[i][1]), "=r"(a[i][2]), "=r"(a[i][3])
                             : "r"(ad));
            }
#pragma unroll
            for (int j2 = 0; j2 < 4; j2++) {
                int nrow = wn * 64 + j2 * 16 + (lane & 7) + (((lane >> 4) & 1) << 3);
                int ko = kk * 16 + (((lane >> 3) & 1) << 3);
                uint32_t bd = sB + nrow * ROWB + ko * 2;
                asm volatile("ldmatrix.sync.aligned.m8n8.x4.shared.b16 {%0,%1,%2,%3}, [%4];"
                             : "=r"(b[j2][0]), "=r"(b[j2][1]), "=r"(b[j2][2]), "=r"(b[j2][3])
                             : "r"(bd));
            }
#pragma unroll
            for (int i = 0; i < 2; i++)
#pragma unroll
                for (int j2 = 0; j2 < 4; j2++) {
                    asm volatile(
                        "mma.sync.aligned.m16n8k16.row.col.f32.f16.f16.f32 "
                        "{%0,%1,%2,%3}, {%4,%5,%6,%7}, {%8,%9}, {%0,%1,%2,%3};"
                        : "+f"(acc[i][2*j2][0]), "+f"(acc[i][2*j2][1]),
                          "+f"(acc[i][2*j2][2]), "+f"(acc[i][2*j2][3])
                        : "r"(a[i][0]), "r"(a[i][1]), "r"(a[i][2]), "r"(a[i][3]),
                          "r"(b[j2][0]), "r"(b[j2][1]));
                    asm volatile(
                        "mma.sync.aligned.m16n8k16.row.col.f32.f16.f16.f32 "
                        "{%0,%1,%2,%3}, {%4,%5,%6,%7}, {%8,%9}, {%0,%1,%2,%3};"
                        : "+f"(acc[i][2*j2+1][0]), "+f"(acc[i][2*j2+1][1]),
                          "+f"(acc[i][2*j2+1][2]), "+f"(acc[i][2*j2+1][3])
                        : "r"(a[i][0]), "r"(a[i][1]), "r"(a[i][2]), "r"(a[i][3]),
                          "r"(b[j2][2]), "r"(b[j2][3]));
                }
        }
        __syncthreads();
    }

#pragma unroll
    for (int j = 0; j < 8; j++) {
        int ncol = n0 + wn * 64 + j * 8 + (lane & 3) * 2;
        float b0 = bias[ncol], b1 = bias[ncol + 1];
#pragma unroll
        for (int i = 0; i < 2; i++) {
            int mr0 = m0 + wm * 32 + i * 16 + (lane >> 2);
#pragma unroll
            for (int h = 0; h < 2; h++) {
                int mrow = mr0 + h * 8;
                float v0 = acc[i][j][2*h + 0] + b0;
                float v1 = acc[i][j][2*h + 1] + b1;
                if (mode == 0) {
                    int tt = mrow >> 5, bb2 = mrow & 31;
                    int rp0 = ((ncol & 511) << 2) | (ncol >> 9);
                    int rp1 = (((ncol + 1) & 511) << 2) | ((ncol + 1) >> 9);
                    g_xihp[((size_t)tt * G4 + rp0) * 32 + bb2] = v0;
                    g_xihp[((size_t)tt * G4 + rp1) * 32 + bb2] = v1;
                } else if (mode == 1) {
                    __half2 hv = __floats2half2_rn(tanhf(v0), tanhf(v1));
                    *(__half2*)(g_Ah + (size_t)mrow * KDIM + ncol) = hv;
                } else {
                    float2 v = {v0, v1};
                    *(float2*)(C + (size_t)mrow * ldc + ncol) = v;
                }
            }
        }
    }
}

// ---------------------------------------------------------------------------
// Persistent fused LSTM (slot-shifted h history, relaxed-poll barrier)
__global__ __launch_bounds__(256, 1)
void k_lstm_p(const float* __restrict__ c0, float* __restrict__ out) {
    extern __shared__ char sm[];
    uint32_t sb = smem_u32(sm);
    int tid = threadIdx.x, w = tid >> 5, lane = tid & 31;
    int jt = blockIdx.x;

    const __half* Wp = g_Whp + (size_t)(jt * 32) * HDIM;
#pragma unroll
    for (int p = 0; p < 8; p++) {
        int idx = p * 256 + tid;
        int row = idx >> 6, seg = idx & 63;
        uint32_t dst = sb + row * SAROW + seg * 16;
        const void* src = Wp + row * HDIM + seg * 8;
        asm volatile("cp.async.cg.shared.global [%0], [%1], 16;" :: "r"(dst), "l"(src));
    }
    asm volatile("cp.async.commit_group;" ::: "memory");

    int b = tid & 31, ul = tid >> 5;
    int u = jt * 8 + ul;
    float creg = c0[b * HDIM + u];
    float hlast = 0.0f;

    float* gS0 = (float*)(sm + SMG);
    float* gS1 = gS0 + 32 * 33;
    int wg = w >> 2, wq = w & 3;
    int wm = wq >> 1, wn = wq & 1;

    for (int t = 0; t < TD; t++) {
        const float* xp = g_xihp + ((size_t)t * G4 + u * 4) * 32 + b;
        float x0 = xp[0], x1 = xp[32], x2 = xp[64], x3 = xp[96];

        const __half* hp = g_hsh + (size_t)t * BSZ * HDIM;
#pragma unroll
        for (int p = 0; p < 8; p++) {
            int idx = p * 256 + tid;
            int row = idx >> 6, seg = idx & 63;
            uint32_t dst = sb + SMH + row * SAROW + seg * 16;
            const void* src = hp + row * HDIM + seg * 8;
            asm volatile("cp.async.cg.shared.global [%0], [%1], 16;" :: "r"(dst), "l"(src));
        }
        asm volatile("cp.async.commit_group;" ::: "memory");
        asm volatile("cp.async.wait_group 0;" ::: "memory");
        __syncthreads();

        float acc[2][4] = {};
#pragma unroll
        for (int kk2 = 0; kk2 < 16; kk2++) {
            int kk = wg * 16 + kk2;
            uint32_t a[4], bb[4];
            {
                int row = wm * 16 + (lane & 15);
                int ko = kk * 16 + ((lane >> 4) << 3);
                uint32_t ad = sb + row * SAROW + ko * 2;
                asm volatile("ldmatrix.sync.aligned.m8n8.x4.shared.b16 {%0,%1,%2,%3}, [%4];"
                             : "=r"(a[0]), "=r"(a[1]), "=r"(a[2]), "=r"(a[3]) : "r"(ad));
            }
            {
                int nrow = wn * 16 + (lane & 7) + (((lane >> 4) & 1) << 3);
                int ko = kk * 16 + (((lane >> 3) & 1) << 3);
                uint32_t bd = sb + SMH + nrow * SAROW + ko * 2;
                asm volatile("ldmatrix.sync.aligned.m8n8.x4.shared.b16 {%0,%1,%2,%3}, [%4];"
                             : "=r"(bb[0]), "=r"(bb[1]), "=r"(bb[2]), "=r"(bb[3]) : "r"(bd));
            }
#pragma unroll
            for (int s = 0; s < 2; s++) {
                asm volatile(
                    "mma.sync.aligned.m16n8k16.row.col.f32.f16.f16.f32 "
                    "{%0,%1,%2,%3}, {%4,%5,%6,%7}, {%8,%9}, {%0,%1,%2,%3};"
                    : "+f"(acc[s][0]), "+f"(acc[s][1]), "+f"(acc[s][2]), "+f"(acc[s][3])
                    : "r"(a[0]), "r"(a[1]), "r"(a[2]), "r"(a[3]),
                      "r"(bb[2*s]), "r"(bb[2*s+1]));
            }
        }
        {
            float* gD = wg ? gS1 : gS0;
            int r0 = wm * 16 + (lane >> 2);
#pragma unroll
            for (int s = 0; s < 2; s++) {
                int c0i = wn * 16 + s * 8 + 2 * (lane & 3);
                gD[r0 * 33 + c0i]           = acc[s][0];
                gD[r0 * 33 + c0i + 1]       = acc[s][1];
                gD[(r0 + 8) * 33 + c0i]     = acc[s][2];
                gD[(r0 + 8) * 33 + c0i + 1] = acc[s][3];
            }
        }
        __syncthreads();

        {
            float gi = gS0[(4 * ul + 0) * 33 + b] + gS1[(4 * ul + 0) * 33 + b] + x0;
            float gf = gS0[(4 * ul + 1) * 33 + b] + gS1[(4 * ul + 1) * 33 + b] + x1;
            float gg = gS0[(4 * ul + 2) * 33 + b] + gS1[(4 * ul + 2) * 33 + b] + x2;
            float go = gS0[(4 * ul + 3) * 33 + b] + gS1[(4 * ul + 3) * 33 + b] + x3;
            float c = sigf(gf) * creg + sigf(gi) * tanhf(gg);
            creg = c;
            float hh = sigf(go) * tanhf(c);
            hlast = hh;
            g_hsh[((size_t)(t + 1) * BSZ + b) * HDIM + u] = __float2half(hh);
        }

        // Grid barrier: syncthreads + tid0 release-add + relaxed-poll + final acquire
        __syncthreads();
        if (tid == 0) {
            asm volatile("red.release.gpu.global.add.u32 [%0], %1;"
                         :: "l"(&g_bar), "r"(1u) : "memory");
            unsigned target = (unsigned)(t + 1) * LCTA;
            unsigned v;
            do {
                asm volatile("ld.relaxed.gpu.global.u32 %0, [%1];"
                             : "=r"(v) : "l"(&g_bar) : "memory");
            } while (v < target);
            asm volatile("ld.acquire.gpu.global.u32 %0, [%1];"
                         : "=r"(v) : "l"(&g_bar) : "memory");
        }
        __syncthreads();
    }

    g_c[b * HDIM + u] = creg;
    out[(size_t)M_BT * VOC + b * HDIM + u] = hlast;
    out[(size_t)M_BT * VOC + BSZ * HDIM + b * HDIM + u] = creg;
}

// ---------------------------------------------------------------------------
// HMMA attention (unchanged from R12)
__global__ __launch_bounds__(256, 1)
void k_attn2() {
    extern __shared__ char sm[];
    uint32_t sb = smem_u32(sm);
    int tid = threadIdx.x, wid = tid >> 5, lane = tid & 31;
    int bi = blockIdx.x;
    int b = bi >> 1, t0 = (bi & 1) * 32;

    const __half* encp = g_ench + (size_t)b * TEC * HDIM;
#pragma unroll
    for (int p = 0; p < 32; p++) {
        int idx = p * 256 + tid;
        int row = idx >> 6, seg = idx & 63;
        uint32_t dst = sb + AT_ENC + row * SAROW + seg * 16;
        const void* src = encp + (size_t)row * HDIM + seg * 8;
        asm volatile("cp.async.cg.shared.global [%0], [%1], 16;" :: "r"(dst), "l"(src));
    }
#pragma unroll
    for (int p = 0; p < 8; p++) {
        int idx = p * 256 + tid;
        int row = idx >> 6, seg = idx & 63;
        uint32_t dst = sb + AT_H + row * SAROW + seg * 16;
        const void* src = g_hsh + ((size_t)(t0 + row + 1) * BSZ + b) * HDIM + seg * 8;
        asm volatile("cp.async.cg.shared.global [%0], [%1], 16;" :: "r"(dst), "l"(src));
    }
    asm volatile("cp.async.commit_group;" ::: "memory");
    asm volatile("cp.async.wait_group 0;" ::: "memory");
    __syncthreads();

    int wm2 = wid >> 2, wn2 = wid & 3;

    float sacc[2][2][4] = {};
#pragma unroll
    for (int kk = 0; kk < 32; kk++) {
        uint32_t a[4];
        {
            int row = wm2 * 16 + (lane & 15);
            int ko = kk * 16 + ((lane >> 4) << 3);
            uint32_t ad = sb + AT_H + row * SAROW + ko * 2;
            asm volatile("ldmatrix.sync.aligned.m8n8.x4.shared.b16 {%0,%1,%2,%3}, [%4];"
                         : "=r"(a[0]), "=r"(a[1]), "=r"(a[2]), "=r"(a[3]) : "r"(ad));
        }
#pragma unroll
        for (int j2 = 0; j2 < 2; j2++) {
            uint32_t bb[4];
            int nrow = wn2 * 32 + j2 * 16 + (lane & 7) + (((lane >> 4) & 1) << 3);
            int ko = kk * 16 + (((lane >> 3) & 1) << 3);
            uint32_t bd = sb + AT_ENC + nrow * SAROW + ko * 2;
            asm volatile("ldmatrix.sync.aligned.m8n8.x4.shared.b16 {%0,%1,%2,%3}, [%4];"
                         : "=r"(bb[0]), "=r"(bb[1]), "=r"(bb[2]), "=r"(bb[3]) : "r"(bd));
#pragma unroll
            for (int s = 0; s < 2; s++) {
                asm volatile(
                    "mma.sync.aligned.m16n8k16.row.col.f32.f16.f16.f32 "
                    "{%0,%1,%2,%3}, {%4,%5,%6,%7}, {%8,%9}, {%0,%1,%2,%3};"
                    : "+f"(sacc[j2][s][0]), "+f"(sacc[j2][s][1]),
                      "+f"(sacc[j2][s][2]), "+f"(sacc[j2][s][3])
                    : "r"(a[0]), "r"(a[1]), "r"(a[2]), "r"(a[3]),
                      "r"(bb[2*s]), "r"(bb[2*s+1]));
            }
        }
    }
    float* sc = (float*)(sm + AT_SC);
    {
        int r0 = wm2 * 16 + (lane >> 2);
#pragma unroll
        for (int j2 = 0; j2 < 2; j2++)
#pragma unroll
            for (int nb = 0; nb < 2; nb++) {
                int c0i = wn2 * 32 + j2 * 16 + nb * 8 + 2 * (lane & 3);
                sc[r0 * 132 + c0i]           = sacc[j2][nb][0];
                sc[r0 * 132 + c0i + 1]       = sacc[j2][nb][1];
                sc[(r0 + 8) * 132 + c0i]     = sacc[j2][nb][2];
                sc[(r0 + 8) * 132 + c0i + 1] = sacc[j2][nb][3];
            }
    }
    __syncthreads();

    __half* Pp = (__half*)(sm + AT_P);
#pragma unroll
    for (int r = 0; r < 4; r++) {
        int row = wid * 4 + r;
        float sv[4], mx = -1e30f;
#pragma unroll
        for (int q = 0; q < 4; q++) { sv[q] = sc[row * 132 + lane + 32 * q]; mx = fmaxf(mx, sv[q]); }
#pragma unroll
        for (int off = 16; off; off >>= 1) mx = fmaxf(mx, __shfl_xor_sync(0xffffffffu, mx, off));
        float sum = 0.0f;
#pragma unroll
        for (int q = 0; q < 4; q++) { sv[q] = expf(sv[q] - mx); sum += sv[q]; }
#pragma unroll
        for (int off = 16; off; off >>= 1) sum += __shfl_xor_sync(0xffffffffu, sum, off);
        float inv = 1.0f / sum;
#pragma unroll
        for (int q = 0; q < 4; q++)
            Pp[row * 136 + lane + 32 * q] = __float2half(sv[q] * inv);
    }
    __syncthreads();

    float cacc[8][2][4];
#pragma unroll
    for (int j2 = 0; j2 < 8; j2++)
#pragma unroll
        for (int nb = 0; nb < 2; nb++)
#pragma unroll
            for (int q = 0; q < 4; q++) cacc[j2][nb][q] = 0.0f;

#pragma unroll
    for (int kk = 0; kk < 8; kk++) {
        uint32_t a[4];
        {
            int row = wm2 * 16 + (lane & 15);
            int ko = kk * 16 + ((lane >> 4) << 3);
            uint32_t ad = sb + AT_P + row * 272 + ko * 2;
            asm volatile("ldmatrix.sync.aligned.m8n8.x4.shared.b16 {%0,%1,%2,%3}, [%4];"
                         : "=r"(a[0]), "=r"(a[1]), "=r"(a[2]), "=r"(a[3]) : "r"(ad));
        }
#pragma unroll
        for (int j2 = 0; j2 < 8; j2++) {
            uint32_t bb[4];
            int j0 = wn2 * 128 + j2 * 16;
            int te = kk * 16 + (((lane >> 3) & 1) << 3) + (lane & 7);
            int jc = j0 + (((lane >> 4) & 1) << 3);
            uint32_t bd = sb + AT_ENC + te * SAROW + jc * 2;
            asm volatile("ldmatrix.sync.aligned.m8n8.x4.trans.shared.b16 {%0,%1,%2,%3}, [%4];"
                         : "=r"(bb[0]), "=r"(bb[1]), "=r"(bb[2]), "=r"(bb[3]) : "r"(bd));
#pragma unroll
            for (int s = 0; s < 2; s++) {
                asm volatile(
                    "mma.sync.aligned.m16n8k16.row.col.f32.f16.f16.f32 "
                    "{%0,%1,%2,%3}, {%4,%5,%6,%7}, {%8,%9}, {%0,%1,%2,%3};"
                    : "+f"(cacc[j2][s][0]), "+f"(cacc[j2][s][1]),
                      "+f"(cacc[j2][s][2]), "+f"(cacc[j2][s][3])
                    : "r"(a[0]), "r"(a[1]), "r"(a[2]), "r"(a[3]),
                      "r"(bb[2*s]), "r"(bb[2*s+1]));
            }
        }
    }

    {
        int r0 = wm2 * 16 + (lane >> 2);
#pragma unroll
        for (int j2 = 0; j2 < 8; j2++)
#pragma unroll
            for (int nb = 0; nb < 2; nb++) {
                int c0i = wn2 * 128 + j2 * 16 + nb * 8 + 2 * (lane & 3);
                int m = b * TD + t0 + r0;
                *(__half2*)(g_cath + (size_t)m * (2 * HDIM) + HDIM + c0i) =
                    __floats2half2_rn(cacc[j2][nb][0], cacc[j2][nb][1]);
                *(__half2*)(g_cath + (size_t)(m + 8) * (2 * HDIM) + HDIM + c0i) =
                    __floats2half2_rn(cacc[j2][nb][2], cacc[j2][nb][3]);
            }
    }
#pragma unroll
    for (int p = 0; p < 8; p++) {
        int idx = p * 256 + tid;
        int row = idx >> 6, seg = idx & 63;
        uint4 v = *(uint4*)(sm + AT_H + row * SAROW + seg * 16);
        int m = b * TD + t0 + row;
        *(uint4*)(g_cath + (size_t)m * (2 * HDIM) + seg * 8) = v;
    }
}

// ---------------------------------------------------------------------------
extern "C" void kernel_launch(void* const* d_in, const int* in_sizes, int n_in,
                              void* d_out, int out_size) {
    const int*   decX = (const int*)d_in[0];
    const float* enc  = (const float*)d_in[1];
    const float* h0   = (const float*)d_in[2];
    const float* c0   = (const float*)d_in[3];
    const float* embW = (const float*)d_in[4];
    const float* Wih  = (const float*)d_in[5];
    const float* Whh  = (const float*)d_in[6];
    const float* bih  = (const float*)d_in[7];
    const float* bhh  = (const float*)d_in[8];
    const float* attW = (const float*)d_in[9];
    const float* attb = (const float*)d_in[10];
    const float* fcW  = (const float*)d_in[11];
    const float* fcb  = (const float*)d_in[12];
    float* out = (float*)d_out;

    __half *p_Wihh, *p_attWh, *p_embh, *p_cath, *p_Ah, *p_Bh;
    float *p_bias;
    cudaGetSymbolAddress((void**)&p_Wihh,  g_Wihh);
    cudaGetSymbolAddress((void**)&p_attWh, g_attWh);
    cudaGetSymbolAddress((void**)&p_embh,  g_embh);
    cudaGetSymbolAddress((void**)&p_cath,  g_cath);
    cudaGetSymbolAddress((void**)&p_Ah,    g_Ah);
    cudaGetSymbolAddress((void**)&p_Bh,    g_Bh);
    cudaGetSymbolAddress((void**)&p_bias,  g_bias);

    cudaFuncSetAttribute(k_hgemm2, cudaFuncAttributeMaxDynamicSharedMemorySize, SM_TOTAL);
    cudaFuncSetAttribute(k_lstm_p, cudaFuncAttributeMaxDynamicSharedMemorySize, STEP_SMEM);
    cudaFuncSetAttribute(k_attn2,  cudaFuncAttributeMaxDynamicSharedMemorySize, ATN_SMEM);

    k_init<<<NB_INIT, 256>>>(fcW, Wih, attW, Whh, bih, bhh, h0, decX, embW, enc);
    // x_ih (+bias), permuted store
    k_hgemm2<<<dim3(M_BT / BM, G4 / BN), 256, SM_TOTAL>>>(
        p_embh, p_Wihh, p_bias, nullptr, EDIM, EDIM / BK, 0, 0);
    // Persistent fused HMMA LSTM
    k_lstm_p<<<LCTA, 256, STEP_SMEM>>>(c0, out);
    // Attention
    k_attn2<<<64, 256, ATN_SMEM>>>();
    // attn out = tanh(cat @ attW^T + attb)
    k_hgemm2<<<dim3(M_BT / BM, HDIM / BN), 256, SM_TOTAL>>>(
        p_cath, p_attWh, attb, nullptr, 2 * HDIM, 2 * HDIM / BK, 0, 1);
    // fc logits
    k_hgemm2<<<dim3(M_BT / BM, VOC / BN), 256, SM_TOTAL>>>(
        p_Ah, p_Bh, fcb, out, KDIM, KDIM / BK, VOC, 2);
}

// round 16
// speedup vs baseline: 3.1854x; 1.0097x over previous
#include <cuda_runtime.h>
#include <cuda_fp16.h>
#include <math.h>
#include <stdint.h>

// Problem constants
#define BSZ   32
#define TD    64
#define TEC   128
#define EDIM  256
#define HDIM  512
#define G4    2048
#define VOC   32000
#define M_BT  2048

// Unified HMMA GEMM tiling: 128x128, 2-stage, 2 CTAs/SM
#define BM    128
#define BN    128
#define BK    64
#define KDIM  512
#define ROWB  144
#define SA_BYTES (BM * ROWB)
#define SB_BYTES (BN * ROWB)
#define STAGE    (SA_BYTES + SB_BYTES)
#define SM_TOTAL (2 * STAGE)

// Persistent LSTM kernel: 64 worker CTAs + 84 converter CTAs
#define LCTA  64
#define TOTCTA 148
#define NCVT  (TOTCTA - LCTA)
#define SAROW 1040
#define SMH   (32 * SAROW)
#define SMG   (SMH + 32 * SAROW)
#define STEP_SMEM (SMG + 2 * 32 * 33 * 4)

// HMMA attention kernel
#define AT_ENC 0
#define AT_H   (128 * SAROW)
#define AT_SC  (AT_H + 32 * SAROW)
#define AT_P   (AT_SC + 32 * 132 * 4)
#define ATN_SMEM (AT_P + 32 * 136 * 2)

// Init kernel grid sections (LSTM-critical only; fc/att/enc conversions
// are hidden inside the LSTM launch on otherwise-idle SMs)
#define NB_WIH  512
#define NB_WHH  1024
#define NB_BIAS 8
#define NB_H0   64
#define NB_EMB  2048
#define NB_INIT (NB_WIH + NB_WHH + NB_BIAS + NB_H0 + NB_EMB)

// Scratch
__device__ float g_bias[G4];
__device__ float g_xihp[(size_t)TD * G4 * BSZ];
__device__ float g_c   [BSZ * HDIM];
__device__ unsigned g_bar;
__device__ __align__(16) __half g_hsh[(size_t)(TD + 1) * BSZ * HDIM];
__device__ __align__(16) __half g_ench[(size_t)BSZ * TEC * HDIM];
__device__ __align__(16) __half g_embh[M_BT * EDIM];
__device__ __align__(16) __half g_Wihh[(size_t)G4 * EDIM];
__device__ __align__(16) __half g_cath[(size_t)M_BT * 2 * HDIM];
__device__ __align__(16) __half g_attWh[(size_t)HDIM * 2 * HDIM];
__device__ __align__(16) __half g_Whp[(size_t)G4 * HDIM];
__device__ __align__(16) __half g_Ah[(size_t)M_BT * KDIM];
__device__ __align__(16) __half g_Bh[(size_t)VOC * KDIM];

__device__ __forceinline__ float sigf(float x) { return 1.0f / (1.0f + expf(-x)); }

__device__ __forceinline__ uint32_t smem_u32(const void* p) {
    uint32_t a;
    asm("{ .reg .u64 t; cvta.to.shared.u64 t, %1; cvt.u32.u64 %0, t; }" : "=r"(a) : "l"(p));
    return a;
}

__device__ __forceinline__ void cvt4(const float* src, __half* dst) {
    float4 x = *(const float4*)src;
    __half h[4] = {__float2half(x.x), __float2half(x.y),
                   __float2half(x.z), __float2half(x.w)};
    *(uint2*)dst = *(uint2*)h;
}

// ---------------------------------------------------------------------------
// Init kernel: only the sections the xih GEMM / LSTM need up front
__global__ void k_init(const float* __restrict__ Wih, const float* __restrict__ Whh,
                       const float* __restrict__ bih, const float* __restrict__ bhh,
                       const float* __restrict__ h0, const int* __restrict__ decX,
                       const float* __restrict__ embW) {
    int blk = blockIdx.x, tid = threadIdx.x;
    if (blk < NB_WIH) {
        size_t i4 = (size_t)blk * 256 + tid;
        cvt4(Wih + i4 * 4, g_Wihh + i4 * 4);
        return;
    }
    blk -= NB_WIH;
    if (blk < NB_WHH) {
        size_t i4 = (size_t)blk * 256 + tid;
        size_t e = i4 * 4;
        int rp = (int)(e >> 9), k = (int)(e & 511);
        int u = rp >> 2, g = rp & 3;
        cvt4(Whh + (size_t)(g * HDIM + u) * HDIM + k, g_Whp + (size_t)rp * HDIM + k);
        return;
    }
    blk -= NB_WHH;
    if (blk < NB_BIAS) {
        int i = blk * 256 + tid;
        g_bias[i] = bih[i] + bhh[i];
        if (i == 0) g_bar = 0u;
        return;
    }
    blk -= NB_BIAS;
    if (blk < NB_H0) {
        int i = blk * 256 + tid;
        g_hsh[i] = __float2half(h0[i]);
        return;
    }
    blk -= NB_H0;
    {
        int m = blk, e = tid;
        int b = m & (BSZ - 1), t = m >> 5;
        int tok = decX[b * TD + t];
        g_embh[m * EDIM + e] = __float2half(embW[tok * EDIM + e]);
    }
}

// ---------------------------------------------------------------------------
// Unified fp16 HMMA GEMM: 128x128 tile, 2-stage, 2 CTAs/SM.
// mode 0: acc+bias -> permuted fp32 g_xihp ; mode 1: tanh -> fp16 g_Ah ;
// mode 2: acc+bias -> fp32 C (stride ldc)
__global__ __launch_bounds__(256, 2)
void k_hgemm2(const __half* __restrict__ A, const __half* __restrict__ B,
              const float* __restrict__ bias, float* __restrict__ C,
              int K, int nI, int ldc, int mode) {
    extern __shared__ char smem[];
    uint32_t sb = smem_u32(smem);
    int tid = threadIdx.x;
    int wid = tid >> 5, lane = tid & 31;
    int wm = wid & 3, wn = wid >> 2;
    int m0 = blockIdx.x * BM, n0 = blockIdx.y * BN;

    const __half* gA0 = A + (size_t)m0 * K;
    const __half* gB0 = B + (size_t)n0 * K;

    auto load_stage = [&](int kt, int s) {
        uint32_t sa = sb + s * STAGE;
        const __half* gA = gA0 + kt * BK;
#pragma unroll
        for (int r4 = 0; r4 < 4; r4++) {
            int li = r4 * 256 + tid;
            int row = li >> 3, seg = li & 7;
            uint32_t dst = sa + row * ROWB + seg * 16;
            const void* src = gA + (size_t)row * K + seg * 8;
            asm volatile("cp.async.cg.shared.global [%0], [%1], 16;" :: "r"(dst), "l"(src));
        }
        uint32_t sbB = sa + SA_BYTES;
        const __half* gB = gB0 + kt * BK;
#pragma unroll
        for (int r4 = 0; r4 < 4; r4++) {
            int li = r4 * 256 + tid;
            int row = li >> 3, seg = li & 7;
            uint32_t dst = sbB + row * ROWB + seg * 16;
            const void* src = gB + (size_t)row * K + seg * 8;
            asm volatile("cp.async.cg.shared.global [%0], [%1], 16;" :: "r"(dst), "l"(src));
        }
        asm volatile("cp.async.commit_group;" ::: "memory");
    };

    float acc[2][8][4];
#pragma unroll
    for (int i = 0; i < 2; i++)
#pragma unroll
        for (int j = 0; j < 8; j++)
#pragma unroll
            for (int q = 0; q < 4; q++) acc[i][j][q] = 0.0f;

    load_stage(0, 0);

    for (int kt = 0; kt < nI; kt++) {
        asm volatile("cp.async.wait_group 0;" ::: "memory");
        __syncthreads();
        if (kt + 1 < nI) load_stage(kt + 1, (kt + 1) & 1);

        uint32_t sa = sb + (kt & 1) * STAGE;
        uint32_t sB = sa + SA_BYTES;
#pragma unroll
        for (int kk = 0; kk < 4; kk++) {
            uint32_t a[2][4], b[4][4];
#pragma unroll
            for (int i = 0; i < 2; i++) {
                int row = wm * 32 + i * 16 + (lane & 15);
                int ko = kk * 16 + ((lane >> 4) << 3);
                uint32_t ad = sa + row * ROWB + ko * 2;
                asm volatile("ldmatrix.sync.aligned.m8n8.x4.shared.b16 {%0,%1,%2,%3}, [%4];"
                             : "=r"(a[i][0]), "=r"(a[i][1]), "=r"(a[i][2]), "=r"(a[i][3])
                             : "r"(ad));
            }
#pragma unroll
            for (int j2 = 0; j2 < 4; j2++) {
                int nrow = wn * 64 + j2 * 16 + (lane & 7) + (((lane >> 4) & 1) << 3);
                int ko = kk * 16 + (((lane >> 3) & 1) << 3);
                uint32_t bd = sB + nrow * ROWB + ko * 2;
                asm volatile("ldmatrix.sync.aligned.m8n8.x4.shared.b16 {%0,%1,%2,%3}, [%4];"
                             : "=r"(b[j2][0]), "=r"(b[j2][1]), "=r"(b[j2][2]), "=r"(b[j2][3])
                             : "r"(bd));
            }
#pragma unroll
            for (int i = 0; i < 2; i++)
#pragma unroll
                for (int j2 = 0; j2 < 4; j2++) {
                    asm volatile(
                        "mma.sync.aligned.m16n8k16.row.col.f32.f16.f16.f32 "
                        "{%0,%1,%2,%3}, {%4,%5,%6,%7}, {%8,%9}, {%0,%1,%2,%3};"
                        : "+f"(acc[i][2*j2][0]), "+f"(acc[i][2*j2][1]),
                          "+f"(acc[i][2*j2][2]), "+f"(acc[i][2*j2][3])
                        : "r"(a[i][0]), "r"(a[i][1]), "r"(a[i][2]), "r"(a[i][3]),
                          "r"(b[j2][0]), "r"(b[j2][1]));
                    asm volatile(
                        "mma.sync.aligned.m16n8k16.row.col.f32.f16.f16.f32 "
                        "{%0,%1,%2,%3}, {%4,%5,%6,%7}, {%8,%9}, {%0,%1,%2,%3};"
                        : "+f"(acc[i][2*j2+1][0]), "+f"(acc[i][2*j2+1][1]),
                          "+f"(acc[i][2*j2+1][2]), "+f"(acc[i][2*j2+1][3])
                        : "r"(a[i][0]), "r"(a[i][1]), "r"(a[i][2]), "r"(a[i][3]),
                          "r"(b[j2][2]), "r"(b[j2][3]));
                }
        }
        __syncthreads();
    }

#pragma unroll
    for (int j = 0; j < 8; j++) {
        int ncol = n0 + wn * 64 + j * 8 + (lane & 3) * 2;
        float b0 = bias[ncol], b1 = bias[ncol + 1];
#pragma unroll
        for (int i = 0; i < 2; i++) {
            int mr0 = m0 + wm * 32 + i * 16 + (lane >> 2);
#pragma unroll
            for (int h = 0; h < 2; h++) {
                int mrow = mr0 + h * 8;
                float v0 = acc[i][j][2*h + 0] + b0;
                float v1 = acc[i][j][2*h + 1] + b1;
                if (mode == 0) {
                    int tt = mrow >> 5, bb2 = mrow & 31;
                    int rp0 = ((ncol & 511) << 2) | (ncol >> 9);
                    int rp1 = (((ncol + 1) & 511) << 2) | ((ncol + 1) >> 9);
                    g_xihp[((size_t)tt * G4 + rp0) * 32 + bb2] = v0;
                    g_xihp[((size_t)tt * G4 + rp1) * 32 + bb2] = v1;
                } else if (mode == 1) {
                    __half2 hv = __floats2half2_rn(tanhf(v0), tanhf(v1));
                    *(__half2*)(g_Ah + (size_t)mrow * KDIM + ncol) = hv;
                } else {
                    float2 v = {v0, v1};
                    *(float2*)(C + (size_t)mrow * ldc + ncol) = v;
                }
            }
        }
    }
}

// ---------------------------------------------------------------------------
// Persistent fused LSTM + free-rider converters.
// CTAs [0,64): LSTM (barrier counts 64 arrivals, unchanged).
// CTAs [64,148): grid-stride fp16 conversions of fcW / attW / enc — work that
// is only needed AFTER the LSTM, done on SMs that would otherwise idle.
__global__ __launch_bounds__(256, 1)
void k_lstm_p(const float* __restrict__ c0, float* __restrict__ out,
              const float* __restrict__ fcW, const float* __restrict__ attW,
              const float* __restrict__ enc) {
    int tid = threadIdx.x;
    if (blockIdx.x >= LCTA) {
        // Converter CTA
        size_t gtid = (size_t)(blockIdx.x - LCTA) * 256 + tid;
        const size_t NTH = (size_t)NCVT * 256;
        for (size_t i = gtid; i < (size_t)VOC * HDIM / 4; i += NTH)
            cvt4(fcW + i * 4, g_Bh + i * 4);
        for (size_t i = gtid; i < (size_t)HDIM * 2 * HDIM / 4; i += NTH)
            cvt4(attW + i * 4, g_attWh + i * 4);
        for (size_t i = gtid; i < (size_t)BSZ * TEC * HDIM / 4; i += NTH)
            cvt4(enc + i * 4, g_ench + i * 4);
        return;
    }

    extern __shared__ char sm[];
    uint32_t sb = smem_u32(sm);
    int w = tid >> 5, lane = tid & 31;
    int jt = blockIdx.x;

    const __half* Wp = g_Whp + (size_t)(jt * 32) * HDIM;
#pragma unroll
    for (int p = 0; p < 8; p++) {
        int idx = p * 256 + tid;
        int row = idx >> 6, seg = idx & 63;
        uint32_t dst = sb + row * SAROW + seg * 16;
        const void* src = Wp + row * HDIM + seg * 8;
        asm volatile("cp.async.cg.shared.global [%0], [%1], 16;" :: "r"(dst), "l"(src));
    }
    asm volatile("cp.async.commit_group;" ::: "memory");

    int b = tid & 31, ul = tid >> 5;
    int u = jt * 8 + ul;
    float creg = c0[b * HDIM + u];
    float hlast = 0.0f;

    float* gS0 = (float*)(sm + SMG);
    float* gS1 = gS0 + 32 * 33;
    int wg = w >> 2, wq = w & 3;
    int wm = wq >> 1, wn = wq & 1;

    for (int t = 0; t < TD; t++) {
        const float* xp = g_xihp + ((size_t)t * G4 + u * 4) * 32 + b;
        float x0 = xp[0], x1 = xp[32], x2 = xp[64], x3 = xp[96];

        const __half* hp = g_hsh + (size_t)t * BSZ * HDIM;
#pragma unroll
        for (int p = 0; p < 8; p++) {
            int idx = p * 256 + tid;
            int row = idx >> 6, seg = idx & 63;
            uint32_t dst = sb + SMH + row * SAROW + seg * 16;
            const void* src = hp + row * HDIM + seg * 8;
            asm volatile("cp.async.cg.shared.global [%0], [%1], 16;" :: "r"(dst), "l"(src));
        }
        asm volatile("cp.async.commit_group;" ::: "memory");
        asm volatile("cp.async.wait_group 0;" ::: "memory");
        __syncthreads();

        float acc[2][4] = {};
#pragma unroll
        for (int kk2 = 0; kk2 < 16; kk2++) {
            int kk = wg * 16 + kk2;
            uint32_t a[4], bb[4];
            {
                int row = wm * 16 + (lane & 15);
                int ko = kk * 16 + ((lane >> 4) << 3);
                uint32_t ad = sb + row * SAROW + ko * 2;
                asm volatile("ldmatrix.sync.aligned.m8n8.x4.shared.b16 {%0,%1,%2,%3}, [%4];"
                             : "=r"(a[0]), "=r"(a[1]), "=r"(a[2]), "=r"(a[3]) : "r"(ad));
            }
            {
                int nrow = wn * 16 + (lane & 7) + (((lane >> 4) & 1) << 3);
                int ko = kk * 16 + (((lane >> 3) & 1) << 3);
                uint32_t bd = sb + SMH + nrow * SAROW + ko * 2;
                asm volatile("ldmatrix.sync.aligned.m8n8.x4.shared.b16 {%0,%1,%2,%3}, [%4];"
                             : "=r"(bb[0]), "=r"(bb[1]), "=r"(bb[2]), "=r"(bb[3]) : "r"(bd));
            }
#pragma unroll
            for (int s = 0; s < 2; s++) {
                asm volatile(
                    "mma.sync.aligned.m16n8k16.row.col.f32.f16.f16.f32 "
                    "{%0,%1,%2,%3}, {%4,%5,%6,%7}, {%8,%9}, {%0,%1,%2,%3};"
                    : "+f"(acc[s][0]), "+f"(acc[s][1]), "+f"(acc[s][2]), "+f"(acc[s][3])
                    : "r"(a[0]), "r"(a[1]), "r"(a[2]), "r"(a[3]),
                      "r"(bb[2*s]), "r"(bb[2*s+1]));
            }
        }
        {
            float* gD = wg ? gS1 : gS0;
            int r0 = wm * 16 + (lane >> 2);
#pragma unroll
            for (int s = 0; s < 2; s++) {
                int c0i = wn * 16 + s * 8 + 2 * (lane & 3);
                gD[r0 * 33 + c0i]           = acc[s][0];
                gD[r0 * 33 + c0i + 1]       = acc[s][1];
                gD[(r0 + 8) * 33 + c0i]     = acc[s][2];
                gD[(r0 + 8) * 33 + c0i + 1] = acc[s][3];
            }
        }
        __syncthreads();

        {
            float gi = gS0[(4 * ul + 0) * 33 + b] + gS1[(4 * ul + 0) * 33 + b] + x0;
            float gf = gS0[(4 * ul + 1) * 33 + b] + gS1[(4 * ul + 1) * 33 + b] + x1;
            float gg = gS0[(4 * ul + 2) * 33 + b] + gS1[(4 * ul + 2) * 33 + b] + x2;
            float go = gS0[(4 * ul + 3) * 33 + b] + gS1[(4 * ul + 3) * 33 + b] + x3;
            float c = sigf(gf) * creg + sigf(gi) * tanhf(gg);
            creg = c;
            float hh = sigf(go) * tanhf(c);
            hlast = hh;
            g_hsh[((size_t)(t + 1) * BSZ + b) * HDIM + u] = __float2half(hh);
        }

        __syncthreads();
        if (tid == 0) {
            asm volatile("red.release.gpu.global.add.u32 [%0], %1;"
                         :: "l"(&g_bar), "r"(1u) : "memory");
            unsigned target = (unsigned)(t + 1) * LCTA;
            unsigned v;
            do {
                asm volatile("ld.relaxed.gpu.global.u32 %0, [%1];"
                             : "=r"(v) : "l"(&g_bar) : "memory");
            } while (v < target);
            asm volatile("ld.acquire.gpu.global.u32 %0, [%1];"
                         : "=r"(v) : "l"(&g_bar) : "memory");
        }
        __syncthreads();
    }

    g_c[b * HDIM + u] = creg;
    out[(size_t)M_BT * VOC + b * HDIM + u] = hlast;
    out[(size_t)M_BT * VOC + BSZ * HDIM + b * HDIM + u] = creg;
}

// ---------------------------------------------------------------------------
// HMMA attention (unchanged)
__global__ __launch_bounds__(256, 1)
void k_attn2() {
    extern __shared__ char sm[];
    uint32_t sb = smem_u32(sm);
    int tid = threadIdx.x, wid = tid >> 5, lane = tid & 31;
    int bi = blockIdx.x;
    int b = bi >> 1, t0 = (bi & 1) * 32;

    const __half* encp = g_ench + (size_t)b * TEC * HDIM;
#pragma unroll
    for (int p = 0; p < 32; p++) {
        int idx = p * 256 + tid;
        int row = idx >> 6, seg = idx & 63;
        uint32_t dst = sb + AT_ENC + row * SAROW + seg * 16;
        const void* src = encp + (size_t)row * HDIM + seg * 8;
        asm volatile("cp.async.cg.shared.global [%0], [%1], 16;" :: "r"(dst), "l"(src));
    }
#pragma unroll
    for (int p = 0; p < 8; p++) {
        int idx = p * 256 + tid;
        int row = idx >> 6, seg = idx & 63;
        uint32_t dst = sb + AT_H + row * SAROW + seg * 16;
        const void* src = g_hsh + ((size_t)(t0 + row + 1) * BSZ + b) * HDIM + seg * 8;
        asm volatile("cp.async.cg.shared.global [%0], [%1], 16;" :: "r"(dst), "l"(src));
    }
    asm volatile("cp.async.commit_group;" ::: "memory");
    asm volatile("cp.async.wait_group 0;" ::: "memory");
    __syncthreads();

    int wm2 = wid >> 2, wn2 = wid & 3;

    float sacc[2][2][4] = {};
#pragma unroll
    for (int kk = 0; kk < 32; kk++) {
        uint32_t a[4];
        {
            int row = wm2 * 16 + (lane & 15);
            int ko = kk * 16 + ((lane >> 4) << 3);
            uint32_t ad = sb + AT_H + row * SAROW + ko * 2;
            asm volatile("ldmatrix.sync.aligned.m8n8.x4.shared.b16 {%0,%1,%2,%3}, [%4];"
                         : "=r"(a[0]), "=r"(a[1]), "=r"(a[2]), "=r"(a[3]) : "r"(ad));
        }
#pragma unroll
        for (int j2 = 0; j2 < 2; j2++) {
            uint32_t bb[4];
            int nrow = wn2 * 32 + j2 * 16 + (lane & 7) + (((lane >> 4) & 1) << 3);
            int ko = kk * 16 + (((lane >> 3) & 1) << 3);
            uint32_t bd = sb + AT_ENC + nrow * SAROW + ko * 2;
            asm volatile("ldmatrix.sync.aligned.m8n8.x4.shared.b16 {%0,%1,%2,%3}, [%4];"
                         : "=r"(bb[0]), "=r"(bb[1]), "=r"(bb[2]), "=r"(bb[3]) : "r"(bd));
#pragma unroll
            for (int s = 0; s < 2; s++) {
                asm volatile(
                    "mma.sync.aligned.m16n8k16.row.col.f32.f16.f16.f32 "
                    "{%0,%1,%2,%3}, {%4,%5,%6,%7}, {%8,%9}, {%0,%1,%2,%3};"
                    : "+f"(sacc[j2][s][0]), "+f"(sacc[j2][s][1]),
                      "+f"(sacc[j2][s][2]), "+f"(sacc[j2][s][3])
                    : "r"(a[0]), "r"(a[1]), "r"(a[2]), "r"(a[3]),
                      "r"(bb[2*s]), "r"(bb[2*s+1]));
            }
        }
    }
    float* sc = (float*)(sm + AT_SC);
    {
        int r0 = wm2 * 16 + (lane >> 2);
#pragma unroll
        for (int j2 = 0; j2 < 2; j2++)
#pragma unroll
            for (int nb = 0; nb < 2; nb++) {
                int c0i = wn2 * 32 + j2 * 16 + nb * 8 + 2 * (lane & 3);
                sc[r0 * 132 + c0i]           = sacc[j2][nb][0];
                sc[r0 * 132 + c0i + 1]       = sacc[j2][nb][1];
                sc[(r0 + 8) * 132 + c0i]     = sacc[j2][nb][2];
                sc[(r0 + 8) * 132 + c0i + 1] = sacc[j2][nb][3];
            }
    }
    __syncthreads();

    __half* Pp = (__half*)(sm + AT_P);
#pragma unroll
    for (int r = 0; r < 4; r++) {
        int row = wid * 4 + r;
        float sv[4], mx = -1e30f;
#pragma unroll
        for (int q = 0; q < 4; q++) { sv[q] = sc[row * 132 + lane + 32 * q]; mx = fmaxf(mx, sv[q]); }
#pragma unroll
        for (int off = 16; off; off >>= 1) mx = fmaxf(mx, __shfl_xor_sync(0xffffffffu, mx, off));
        float sum = 0.0f;
#pragma unroll
        for (int q = 0; q < 4; q++) { sv[q] = expf(sv[q] - mx); sum += sv[q]; }
#pragma unroll
        for (int off = 16; off; off >>= 1) sum += __shfl_xor_sync(0xffffffffu, sum, off);
        float inv = 1.0f / sum;
#pragma unroll
        for (int q = 0; q < 4; q++)
            Pp[row * 136 + lane + 32 * q] = __float2half(sv[q] * inv);
    }
    __syncthreads();

    float cacc[8][2][4];
#pragma unroll
    for (int j2 = 0; j2 < 8; j2++)
#pragma unroll
        for (int nb = 0; nb < 2; nb++)
#pragma unroll
            for (int q = 0; q < 4; q++) cacc[j2][nb][q] = 0.0f;

#pragma unroll
    for (int kk = 0; kk < 8; kk++) {
        uint32_t a[4];
        {
            int row = wm2 * 16 + (lane & 15);
            int ko = kk * 16 + ((lane >> 4) << 3);
            uint32_t ad = sb + AT_P + row * 272 + ko * 2;
            asm volatile("ldmatrix.sync.aligned.m8n8.x4.shared.b16 {%0,%1,%2,%3}, [%4];"
                         : "=r"(a[0]), "=r"(a[1]), "=r"(a[2]), "=r"(a[3]) : "r"(ad));
        }
#pragma unroll
        for (int j2 = 0; j2 < 8; j2++) {
            uint32_t bb[4];
            int j0 = wn2 * 128 + j2 * 16;
            int te = kk * 16 + (((lane >> 3) & 1) << 3) + (lane & 7);
            int jc = j0 + (((lane >> 4) & 1) << 3);
            uint32_t bd = sb + AT_ENC + te * SAROW + jc * 2;
            asm volatile("ldmatrix.sync.aligned.m8n8.x4.trans.shared.b16 {%0,%1,%2,%3}, [%4];"
                         : "=r"(bb[0]), "=r"(bb[1]), "=r"(bb[2]), "=r"(bb[3]) : "r"(bd));
#pragma unroll
            for (int s = 0; s < 2; s++) {
                asm volatile(
                    "mma.sync.aligned.m16n8k16.row.col.f32.f16.f16.f32 "
                    "{%0,%1,%2,%3}, {%4,%5,%6,%7}, {%8,%9}, {%0,%1,%2,%3};"
                    : "+f"(cacc[j2][s][0]), "+f"(cacc[j2][s][1]),
                      "+f"(cacc[j2][s][2]), "+f"(cacc[j2][s][3])
                    : "r"(a[0]), "r"(a[1]), "r"(a[2]), "r"(a[3]),
                      "r"(bb[2*s]), "r"(bb[2*s+1]));
            }
        }
    }

    {
        int r0 = wm2 * 16 + (lane >> 2);
#pragma unroll
        for (int j2 = 0; j2 < 8; j2++)
#pragma unroll
            for (int nb = 0; nb < 2; nb++) {
                int c0i = wn2 * 128 + j2 * 16 + nb * 8 + 2 * (lane & 3);
                int m = b * TD + t0 + r0;
                *(__half2*)(g_cath + (size_t)m * (2 * HDIM) + HDIM + c0i) =
                    __floats2half2_rn(cacc[j2][nb][0], cacc[j2][nb][1]);
                *(__half2*)(g_cath + (size_t)(m + 8) * (2 * HDIM) + HDIM + c0i) =
                    __floats2half2_rn(cacc[j2][nb][2], cacc[j2][nb][3]);
            }
    }
#pragma unroll
    for (int p = 0; p < 8; p++) {
        int idx = p * 256 + tid;
        int row = idx >> 6, seg = idx & 63;
        uint4 v = *(uint4*)(sm + AT_H + row * SAROW + seg * 16);
        int m = b * TD + t0 + row;
        *(uint4*)(g_cath + (size_t)m * (2 * HDIM) + seg * 8) = v;
    }
}

// ---------------------------------------------------------------------------
extern "C" void kernel_launch(void* const* d_in, const int* in_sizes, int n_in,
                              void* d_out, int out_size) {
    const int*   decX = (const int*)d_in[0];
    const float* enc  = (const float*)d_in[1];
    const float* h0   = (const float*)d_in[2];
    const float* c0   = (const float*)d_in[3];
    const float* embW = (const float*)d_in[4];
    const float* Wih  = (const float*)d_in[5];
    const float* Whh  = (const float*)d_in[6];
    const float* bih  = (const float*)d_in[7];
    const float* bhh  = (const float*)d_in[8];
    const float* attW = (const float*)d_in[9];
    const float* attb = (const float*)d_in[10];
    const float* fcW  = (const float*)d_in[11];
    const float* fcb  = (const float*)d_in[12];
    float* out = (float*)d_out;

    __half *p_Wihh, *p_attWh, *p_embh, *p_cath, *p_Ah, *p_Bh;
    float *p_bias;
    cudaGetSymbolAddress((void**)&p_Wihh,  g_Wihh);
    cudaGetSymbolAddress((void**)&p_attWh, g_attWh);
    cudaGetSymbolAddress((void**)&p_embh,  g_embh);
    cudaGetSymbolAddress((void**)&p_cath,  g_cath);
    cudaGetSymbolAddress((void**)&p_Ah,    g_Ah);
    cudaGetSymbolAddress((void**)&p_Bh,    g_Bh);
    cudaGetSymbolAddress((void**)&p_bias,  g_bias);

    cudaFuncSetAttribute(k_hgemm2, cudaFuncAttributeMaxDynamicSharedMemorySize, SM_TOTAL);
    cudaFuncSetAttribute(k_lstm_p, cudaFuncAttributeMaxDynamicSharedMemorySize, STEP_SMEM);
    cudaFuncSetAttribute(k_attn2,  cudaFuncAttributeMaxDynamicSharedMemorySize, ATN_SMEM);

    // LSTM-critical init only
    k_init<<<NB_INIT, 256>>>(Wih, Whh, bih, bhh, h0, decX, embW);
    // x_ih (+bias), permuted store
    k_hgemm2<<<dim3(M_BT / BM, G4 / BN), 256, SM_TOTAL>>>(
        p_embh, p_Wihh, p_bias, nullptr, EDIM, EDIM / BK, 0, 0);
    // Persistent LSTM (64 CTAs) + hidden fcW/attW/enc conversions (84 CTAs)
    k_lstm_p<<<TOTCTA, 256, STEP_SMEM>>>(c0, out, fcW, attW, enc);
    // Attention
    k_attn2<<<64, 256, ATN_SMEM>>>();
    // attn out = tanh(cat @ attW^T + attb)
    k_hgemm2<<<dim3(M_BT / BM, HDIM / BN), 256, SM_TOTAL>>>(
        p_cath, p_attWh, attb, nullptr, 2 * HDIM, 2 * HDIM / BK, 0, 1);
    // fc logits
    k_hgemm2<<<dim3(M_BT / BM, VOC / BN), 256, SM_TOTAL>>>(
        p_Ah, p_Bh, fcb, out, KDIM, KDIM / BK, VOC, 2);
}